// round 1
// baseline (speedup 1.0000x reference)
#include <cuda_runtime.h>
#include <math.h>

// ---------------- static device scratch (no allocations allowed) ----------------
static __device__ float g_xn[4096*1024];
static __device__ float g_q [4096*1024];
static __device__ float g_k [4096*256];
static __device__ float g_v [4096*256];
static __device__ float g_y [4096*1024];
static __device__ float g_x2[4096*1024];
static __device__ float g_t1[4096*1024];
static __device__ float g_tk[16777216];   // 4096*4096
static __device__ float g_ac[16777216];   // 4096*4096
static __device__ float g_pa[4096*1024];
static __device__ int   g_sel[4];
static __device__ float g_coef[4];

// ---------------- RMSNorm over DIM=1024, one block per token ----------------
__global__ void rmsnorm_kernel(const float* __restrict__ x, float* __restrict__ o)
{
    int n = blockIdx.x;
    int tid = threadIdx.x;               // 256 threads
    const float4* xr = (const float4*)(x + (size_t)n * 1024);
    float4 v = xr[tid];
    float s = v.x*v.x + v.y*v.y + v.z*v.z + v.w*v.w;
#pragma unroll
    for (int off = 16; off > 0; off >>= 1) s += __shfl_xor_sync(0xffffffffu, s, off);
    __shared__ float red[8];
    if ((tid & 31) == 0) red[tid >> 5] = s;
    __syncthreads();
    float tot = 0.f;
#pragma unroll
    for (int i = 0; i < 8; i++) tot += red[i];
    float r = rsqrtf(tot * (1.f/1024.f) + 1e-6f);
    v.x *= r; v.y *= r; v.z *= r; v.w *= r;
    ((float4*)(o + (size_t)n * 1024))[tid] = v;
}

// ---------------- generic SGEMM: C = A(MxK) * W(NxK)^T (+ res) ----------------
// All shapes used are multiples of 128/8, so no bounds checks.
__global__ __launch_bounds__(256) void sgemm_kernel(
    const float* __restrict__ A, const float* __restrict__ W, float* __restrict__ C,
    int M, int Nn, int K,
    const float* __restrict__ res,
    const int* __restrict__ selp, size_t wstride)
{
    if (selp) W += (size_t)(*selp) * wstride;
    __shared__ __align__(16) float As[8][128];
    __shared__ __align__(16) float Bs[8][128];
    int tid = threadIdx.x;
    int tx = tid & 15, ty = tid >> 4;
    const float* Ab = A + (size_t)blockIdx.y * 128 * K;
    const float* Wb = W + (size_t)blockIdx.x * 128 * K;
    int lrow = tid >> 1;
    int lcol = (tid & 1) * 4;
    float acc[8][8];
#pragma unroll
    for (int i = 0; i < 8; i++)
#pragma unroll
        for (int j = 0; j < 8; j++) acc[i][j] = 0.f;

    for (int k0 = 0; k0 < K; k0 += 8) {
        float4 av = *(const float4*)(Ab + (size_t)lrow * K + k0 + lcol);
        float4 wv = *(const float4*)(Wb + (size_t)lrow * K + k0 + lcol);
        As[lcol+0][lrow] = av.x; As[lcol+1][lrow] = av.y;
        As[lcol+2][lrow] = av.z; As[lcol+3][lrow] = av.w;
        Bs[lcol+0][lrow] = wv.x; Bs[lcol+1][lrow] = wv.y;
        Bs[lcol+2][lrow] = wv.z; Bs[lcol+3][lrow] = wv.w;
        __syncthreads();
#pragma unroll
        for (int k = 0; k < 8; k++) {
            float a[8], b[8];
            *(float4*)(a)   = *(const float4*)&As[k][ty*8];
            *(float4*)(a+4) = *(const float4*)&As[k][ty*8+4];
            *(float4*)(b)   = *(const float4*)&Bs[k][tx*8];
            *(float4*)(b+4) = *(const float4*)&Bs[k][tx*8+4];
#pragma unroll
            for (int i = 0; i < 8; i++)
#pragma unroll
                for (int j = 0; j < 8; j++) acc[i][j] = fmaf(a[i], b[j], acc[i][j]);
        }
        __syncthreads();
    }
    size_t crow0 = (size_t)blockIdx.y * 128 + ty * 8;
    int ccol0 = blockIdx.x * 128 + tx * 8;
#pragma unroll
    for (int i = 0; i < 8; i++) {
        size_t base = (crow0 + i) * (size_t)Nn + ccol0;
#pragma unroll
        for (int j = 0; j < 8; j++) {
            float vv = acc[i][j];
            if (res) vv += res[base + j];
            C[base + j] = vv;
        }
    }
}

// ---------------- per-head RMSNorm * gain + RoPE, in place (q and k) ----------------
__global__ void qkprep_kernel(float* __restrict__ q, float* __restrict__ k,
                              const float* __restrict__ qg, const float* __restrict__ kg)
{
    int gt = blockIdx.x * blockDim.x + threadIdx.x;
    int w = gt >> 5;
    int lane = gt & 31;
    float* ptr; float gain; int t;
    if (w < 4096 * 16) {                     // q heads
        int n = w >> 4, h = w & 15;
        ptr = q + (size_t)n * 1024 + h * 64;
        gain = qg[h];
        t = n & 2047;
    } else {                                 // k heads
        int w2 = w - 4096 * 16;
        int n = w2 >> 2, h = w2 & 3;
        ptr = k + (size_t)n * 256 + h * 64;
        gain = kg[h];
        t = n & 2047;
    }
    float v1 = ptr[lane], v2 = ptr[lane + 32];
    float s = v1*v1 + v2*v2;
#pragma unroll
    for (int off = 16; off > 0; off >>= 1) s += __shfl_xor_sync(0xffffffffu, s, off);
    float r = rsqrtf(s * (1.f/64.f) + 1e-6f) * gain;
    v1 *= r; v2 *= r;
    float freq = powf(10000.f, -(float)(2 * lane) / 64.f);
    float ang = (float)t * freq;
    float sn, cs;
    sincosf(ang, &sn, &cs);
    ptr[lane]      = v1 * cs + v2 * sn;
    ptr[lane + 32] = v2 * cs - v1 * sn;
}

// ---------------- causal attention, streaming softmax ----------------
// grid (T/64, H, B), 64 threads; thread owns one query row (q,o in registers)
__global__ __launch_bounds__(64) void attn_kernel(
    const float* __restrict__ q, const float* __restrict__ k,
    const float* __restrict__ v, float* __restrict__ y)
{
    int qt = blockIdx.x, h = blockIdx.y, b = blockIdx.z;
    int kvh = h >> 2;                       // repeat factor 4
    int tid = threadIdx.x;
    int qr = qt * 64 + tid;
    const float4* qrow = (const float4*)(q + ((size_t)(b * 2048 + qr)) * 1024 + h * 64);
    float4 Q[16], O[16];
#pragma unroll
    for (int i = 0; i < 16; i++) { Q[i] = qrow[i]; O[i] = make_float4(0.f,0.f,0.f,0.f); }
    float m = -1e30f, l = 0.f;
    __shared__ __align__(16) float Ks[32][64];
    __shared__ __align__(16) float Vs[32][64];
    __shared__ float Ss[64][33];
    int ktend = qt * 64 + 63;
    for (int kt0 = 0; kt0 <= ktend; kt0 += 32) {
        __syncthreads();
#pragma unroll
        for (int r = 0; r < 8; r++) {
            int f = tid + 64 * r;
            int row = f >> 4;
            int c4 = (f & 15) << 2;
            size_t gi = ((size_t)(b * 2048 + kt0 + row)) * 256 + kvh * 64 + c4;
            *(float4*)&Ks[row][c4] = *(const float4*)(k + gi);
            *(float4*)&Vs[row][c4] = *(const float4*)(v + gi);
        }
        __syncthreads();
        float tmax = -1e30f;
        for (int j = 0; j < 32; j++) {
            float sv = -1e30f;
            if (kt0 + j <= qr) {
                const float4* kr = (const float4*)&Ks[j][0];
                float acc = 0.f;
#pragma unroll
                for (int i = 0; i < 16; i++) {
                    float4 kk = kr[i];
                    acc = fmaf(Q[i].x, kk.x, acc);
                    acc = fmaf(Q[i].y, kk.y, acc);
                    acc = fmaf(Q[i].z, kk.z, acc);
                    acc = fmaf(Q[i].w, kk.w, acc);
                }
                sv = acc * 0.125f;          // 1/sqrt(64)
            }
            Ss[tid][j] = sv;
            tmax = fmaxf(tmax, sv);
        }
        if (tmax > -1e29f) {
            float mnew = fmaxf(m, tmax);
            float corr = expf(m - mnew);
            m = mnew;
            l *= corr;
#pragma unroll
            for (int i = 0; i < 16; i++) {
                O[i].x *= corr; O[i].y *= corr; O[i].z *= corr; O[i].w *= corr;
            }
            for (int j = 0; j < 32; j++) {
                float p = expf(Ss[tid][j] - m);
                l += p;
                const float4* vr = (const float4*)&Vs[j][0];
#pragma unroll
                for (int i = 0; i < 16; i++) {
                    float4 vv = vr[i];
                    O[i].x = fmaf(p, vv.x, O[i].x);
                    O[i].y = fmaf(p, vv.y, O[i].y);
                    O[i].z = fmaf(p, vv.z, O[i].z);
                    O[i].w = fmaf(p, vv.w, O[i].w);
                }
            }
        }
    }
    float inv = 1.f / l;
    float4* yr = (float4*)(y + ((size_t)(b * 2048 + qr)) * 1024 + h * 64);
#pragma unroll
    for (int i = 0; i < 16; i++) {
        O[i].x *= inv; O[i].y *= inv; O[i].z *= inv; O[i].w *= inv;
        yr[i] = O[i];
    }
}

// ---------------- block-diagonal 64x64 GEMM with optional roll+transpose epilogue ----------------
// X:(N, nb*64). W block g = Wall[sel][g*64+c][d]. out[n, g*64+d] = sum_c X[n,g*64+c]*W[g,c,d]
// perm_out: write to out[n, d*nb + (g+sel%nb)%nb]  (fused jnp.roll + swapaxes)
// accum: O += coef*val  else O = coef*val
__global__ __launch_bounds__(256) void blockdiag_kernel(
    const float* __restrict__ X, const float* __restrict__ Wall, float* __restrict__ O,
    int nb, const int* __restrict__ selp,
    int perm_out, int accum, const float* __restrict__ coefp)
{
    int F = nb * 64;
    int sel = *selp;
    int g = blockIdx.x;
    int n0 = blockIdx.y * 64;
    const float* W = Wall + (size_t)sel * F * 64 + (size_t)g * 64 * 64;
    __shared__ __align__(16) float XsT[64][68];
    __shared__ __align__(16) float Ws[64][68];
    int tid = threadIdx.x;
#pragma unroll
    for (int r = 0; r < 4; r++) {
        int f = tid + 256 * r;
        int row = f >> 4;
        int c4 = (f & 15) << 2;
        float4 xv = *(const float4*)(X + (size_t)(n0 + row) * F + g * 64 + c4);
        XsT[c4+0][row] = xv.x; XsT[c4+1][row] = xv.y;
        XsT[c4+2][row] = xv.z; XsT[c4+3][row] = xv.w;
        float4 wv = *(const float4*)(W + row * 64 + c4);
        *(float4*)&Ws[row][c4] = wv;
    }
    __syncthreads();
    int tx = tid & 15, ty = tid >> 4;
    float acc[4][4];
#pragma unroll
    for (int i = 0; i < 4; i++)
#pragma unroll
        for (int j = 0; j < 4; j++) acc[i][j] = 0.f;
#pragma unroll
    for (int c = 0; c < 64; c++) {
        float a[4], b[4];
        *(float4*)a = *(const float4*)&XsT[c][ty*4];
        *(float4*)b = *(const float4*)&Ws[c][tx*4];
#pragma unroll
        for (int i = 0; i < 4; i++)
#pragma unroll
            for (int j = 0; j < 4; j++) acc[i][j] = fmaf(a[i], b[j], acc[i][j]);
    }
    float alpha = coefp ? *coefp : 1.f;
    int gout = g;
    if (perm_out) {
        gout = g + (sel % nb);
        if (gout >= nb) gout -= nb;
    }
#pragma unroll
    for (int i = 0; i < 4; i++) {
        size_t nrow = (size_t)(n0 + ty * 4 + i);
#pragma unroll
        for (int j = 0; j < 4; j++) {
            int d = tx * 4 + j;
            size_t idx = perm_out ? nrow * F + (size_t)d * nb + gout
                                  : nrow * F + (size_t)g * 64 + d;
            float vv = alpha * acc[i][j];
            if (accum) O[idx] += vv; else O[idx] = vv;
        }
    }
}

// ---------------- elementwise ----------------
__global__ void relu2_kernel(float* __restrict__ a, int n)
{
    int i = blockIdx.x * blockDim.x + threadIdx.x;
    if (i < n) { float v = a[i]; v = v > 0.f ? v : 0.f; a[i] = v * v; }
}

__global__ void add_kernel(const float* __restrict__ a, const float* __restrict__ b,
                           float* __restrict__ o, int n)
{
    int i = blockIdx.x * blockDim.x + threadIdx.x;
    if (i < n) o[i] = a[i] + b[i];
}

// ---------------- top-2 router + softmax coeffs ----------------
__global__ void router_kernel(const float* __restrict__ fcl, const float* __restrict__ pjl,
                              int* __restrict__ sel, float* __restrict__ coef)
{
    if (threadIdx.x == 0 && blockIdx.x == 0) {
#pragma unroll
        for (int s = 0; s < 2; s++) {
            const float* L = s ? pjl : fcl;
            int i1 = 0; float v1 = L[0];
            for (int i = 1; i < 8; i++) if (L[i] > v1) { v1 = L[i]; i1 = i; }
            int i2 = -1; float v2 = -1e30f;
            for (int i = 0; i < 8; i++) if (i != i1 && L[i] > v2) { v2 = L[i]; i2 = i; }
            float e = expf(v2 - v1);
            float z = 1.f + e;
            sel[s*2+0] = i1; sel[s*2+1] = i2;
            coef[s*2+0] = 1.f / z; coef[s*2+1] = e / z;
        }
    }
}

// ---------------- host orchestration ----------------
extern "C" void kernel_launch(void* const* d_in, const int* in_sizes, int n_in,
                              void* d_out, int out_size)
{
    (void)in_sizes; (void)n_in; (void)out_size;
    const float* x      = (const float*)d_in[0];
    const float* wq     = (const float*)d_in[1];
    const float* wk     = (const float*)d_in[2];
    const float* wv     = (const float*)d_in[3];
    const float* wo     = (const float*)d_in[4];
    const float* qg     = (const float*)d_in[5];
    const float* kg     = (const float*)d_in[6];
    const float* fc_s1  = (const float*)d_in[7];
    const float* fc_s2  = (const float*)d_in[8];
    const float* fc_mix = (const float*)d_in[9];
    const float* fc_lg  = (const float*)d_in[10];
    const float* pj_s1  = (const float*)d_in[11];
    const float* pj_s2  = (const float*)d_in[12];
    const float* pj_mix = (const float*)d_in[13];
    const float* pj_lg  = (const float*)d_in[14];

    float *xn, *q, *k, *v, *y, *x2, *t1, *tk, *ac, *pa, *coef;
    int* sel;
    cudaGetSymbolAddress((void**)&xn, g_xn);
    cudaGetSymbolAddress((void**)&q,  g_q);
    cudaGetSymbolAddress((void**)&k,  g_k);
    cudaGetSymbolAddress((void**)&v,  g_v);
    cudaGetSymbolAddress((void**)&y,  g_y);
    cudaGetSymbolAddress((void**)&x2, g_x2);
    cudaGetSymbolAddress((void**)&t1, g_t1);
    cudaGetSymbolAddress((void**)&tk, g_tk);
    cudaGetSymbolAddress((void**)&ac, g_ac);
    cudaGetSymbolAddress((void**)&pa, g_pa);
    cudaGetSymbolAddress((void**)&sel,  g_sel);
    cudaGetSymbolAddress((void**)&coef, g_coef);

    // x1 = rms_norm(x)
    rmsnorm_kernel<<<4096, 256>>>(x, xn);
    // q/k/v projections
    sgemm_kernel<<<dim3(8, 32), 256>>>(xn, wq, q, 4096, 1024, 1024, nullptr, nullptr, 0);
    sgemm_kernel<<<dim3(2, 32), 256>>>(xn, wk, k, 4096, 256, 1024, nullptr, nullptr, 0);
    sgemm_kernel<<<dim3(2, 32), 256>>>(xn, wv, v, 4096, 256, 1024, nullptr, nullptr, 0);
    // per-head rmsnorm * gain + rope (in place)
    qkprep_kernel<<<10240, 256>>>(q, k, qg, kg);
    // causal attention
    attn_kernel<<<dim3(32, 16, 2), 64>>>(q, k, v, y);
    // x2 = x + y @ wo^T
    sgemm_kernel<<<dim3(8, 32), 256>>>(y, wo, x2, 4096, 1024, 1024, x, nullptr, 0);
    // h = rms_norm(x2)
    rmsnorm_kernel<<<4096, 256>>>(x2, xn);
    // top-2 routing for both bank layers
    router_kernel<<<1, 32>>>(fc_lg, pj_lg, sel, coef);

    // fc bank: DIM -> HID, two experts accumulated into ac
    for (int r = 0; r < 2; r++) {
        blockdiag_kernel<<<dim3(16, 64), 256>>>(xn, fc_s1, t1, 16, sel + r, 1, 0, nullptr);
        sgemm_kernel<<<dim3(32, 32), 256>>>(t1, fc_mix, tk, 4096, 4096, 1024,
                                            nullptr, sel + r, (size_t)4096 * 1024);
        blockdiag_kernel<<<dim3(64, 64), 256>>>(tk, fc_s2, ac, 64, sel + r, 0, r, coef + r);
    }
    // h = relu(h)^2
    relu2_kernel<<<65536, 256>>>(ac, 16777216);
    // pj bank: HID -> DIM, two experts accumulated into pa
    for (int r = 0; r < 2; r++) {
        blockdiag_kernel<<<dim3(64, 64), 256>>>(ac, pj_s1, tk, 64, sel + 2 + r, 1, 0, nullptr);
        sgemm_kernel<<<dim3(8, 32), 256>>>(tk, pj_mix, t1, 4096, 1024, 4096,
                                           nullptr, sel + 2 + r, (size_t)1024 * 4096);
        blockdiag_kernel<<<dim3(16, 64), 256>>>(t1, pj_s2, pa, 16, sel + 2 + r, 0, r, coef + 2 + r);
    }
    // out = x2 + pj_out
    add_kernel<<<16384, 256>>>(x2, pa, (float*)d_out, 4194304);
}

// round 3
// speedup vs baseline: 1.7737x; 1.7737x over previous
#include <cuda_runtime.h>
#include <cuda_bf16.h>
#include <math.h>
#include <stdint.h>

// ---------------- static device scratch (no allocations allowed) ----------------
static __device__ float g_xn[4096*1024];
static __device__ float g_q [4096*1024];
static __device__ float g_k [4096*256];
static __device__ float g_v [4096*256];
static __device__ float g_y [4096*1024];
static __device__ float g_x2[4096*1024];
static __device__ float g_t1[4096*1024];
static __device__ float g_tk[16777216];   // 4096*4096
static __device__ float g_ac[16777216];   // 4096*4096
static __device__ float g_pa[4096*1024];
static __device__ int   g_sel[4];
static __device__ float g_coef[4];
// bf16 split buffers
static __device__ __nv_bfloat16 g_ah[16777216];
static __device__ __nv_bfloat16 g_al[16777216];
static __device__ __nv_bfloat16 g_wh[4194304];
static __device__ __nv_bfloat16 g_wl[4194304];

// ---------------- PTX helpers (mma.sync / ldmatrix / cp.async) ----------------
__device__ __forceinline__ uint32_t smem_u32(const void* p) {
    uint32_t a;
    asm("{ .reg .u64 t; cvta.to.shared.u64 t, %1; cvt.u32.u64 %0, t; }" : "=r"(a) : "l"(p));
    return a;
}
#define CP_ASYNC16(dst, src) \
    asm volatile("cp.async.cg.shared.global [%0], [%1], 16;" :: "r"(dst), "l"(src))
#define CP_COMMIT() asm volatile("cp.async.commit_group;" ::: "memory")
#define CP_WAIT2()  asm volatile("cp.async.wait_group 2;" ::: "memory")

#define LDSM_X4(r, addr) \
    asm volatile("ldmatrix.sync.aligned.m8n8.x4.shared.b16 {%0,%1,%2,%3}, [%4];" \
        : "=r"((r)[0]), "=r"((r)[1]), "=r"((r)[2]), "=r"((r)[3]) : "r"(addr))

#define MMA_BF16(d, a, b0, b1) \
    asm volatile("mma.sync.aligned.m16n8k16.row.col.f32.bf16.bf16.f32 " \
        "{%0,%1,%2,%3}, {%4,%5,%6,%7}, {%8,%9}, {%0,%1,%2,%3};" \
        : "+f"((d)[0]), "+f"((d)[1]), "+f"((d)[2]), "+f"((d)[3]) \
        : "r"((a)[0]), "r"((a)[1]), "r"((a)[2]), "r"((a)[3]), "r"(b0), "r"(b1))

// ---------------- fp32 -> (hi,lo) bf16 split ----------------
__global__ void split_kernel(const float* __restrict__ src, __nv_bfloat16* __restrict__ hi,
                             __nv_bfloat16* __restrict__ lo, int n,
                             const int* __restrict__ selp, size_t stride)
{
    if (selp) src += (size_t)(*selp) * stride;
    int i = (blockIdx.x * blockDim.x + threadIdx.x) * 8;
    if (i >= n) return;
    float4 a = *(const float4*)(src + i);
    float4 b = *(const float4*)(src + i + 4);
    float vv[8] = {a.x, a.y, a.z, a.w, b.x, b.y, b.z, b.w};
    uint16_t h[8], l[8];
#pragma unroll
    for (int j = 0; j < 8; j++) {
        __nv_bfloat16 hb = __float2bfloat16_rn(vv[j]);
        float r = vv[j] - __bfloat162float(hb);
        __nv_bfloat16 lb = __float2bfloat16_rn(r);
        h[j] = *(uint16_t*)&hb; l[j] = *(uint16_t*)&lb;
    }
    uint4 H, L;
    H.x = h[0] | ((uint32_t)h[1] << 16); H.y = h[2] | ((uint32_t)h[3] << 16);
    H.z = h[4] | ((uint32_t)h[5] << 16); H.w = h[6] | ((uint32_t)h[7] << 16);
    L.x = l[0] | ((uint32_t)l[1] << 16); L.y = l[2] | ((uint32_t)l[3] << 16);
    L.z = l[4] | ((uint32_t)l[5] << 16); L.w = l[6] | ((uint32_t)l[7] << 16);
    *(uint4*)(hi + i) = H;
    *(uint4*)(lo + i) = L;
}

// ---------------- HMMA bf16x3 GEMM: C = A(MxK) * W(NxK)^T (+ res) ----------------
// grid (N/128, M/128), 256 threads (8 warps, 4x2), 3-stage cp.async pipeline.
// smem tile: 128 rows x 32 bf16, row stride 40 bf16 (80B) -> conflict-free ldmatrix.
#define TSTRIDE 80                 // bytes per smem row
#define BUF_BYTES (128 * TSTRIDE)  // 10240
#define STAGE_BYTES (4 * BUF_BYTES)
#define GEMM_SMEM (3 * STAGE_BYTES)

__device__ __forceinline__ void gemm_load_stage(
    uint32_t smbase, int kt, int NT, int K, int tid,
    const __nv_bfloat16* s0, const __nv_bfloat16* s1,
    const __nv_bfloat16* s2, const __nv_bfloat16* s3)
{
    if (kt < NT) {
        uint32_t sb = smbase + (kt % 3) * STAGE_BYTES;
        int k0 = kt * 32;
        const __nv_bfloat16* srcs[4] = {s0, s1, s2, s3};
#pragma unroll
        for (int t = 0; t < 8; t++) {
            int c = tid + 256 * t;          // 0..2047
            int buf = c >> 9, cc = c & 511;
            int row = cc >> 2, kc = cc & 3;
            uint32_t dst = sb + buf * BUF_BYTES + row * TSTRIDE + kc * 16;
            const __nv_bfloat16* src = srcs[buf] + (size_t)row * K + k0 + kc * 8;
            CP_ASYNC16(dst, src);
        }
    }
    CP_COMMIT();
}

__global__ __launch_bounds__(256) void gemm_bf16x3(
    const __nv_bfloat16* __restrict__ Ah, const __nv_bfloat16* __restrict__ Al,
    const __nv_bfloat16* __restrict__ Wh, const __nv_bfloat16* __restrict__ Wl,
    float* __restrict__ C, const float* __restrict__ res, int N, int K)
{
    extern __shared__ char smem[];
    uint32_t smbase = smem_u32(smem);
    int tid = threadIdx.x, wid = tid >> 5, lane = tid & 31;
    int m0 = blockIdx.y * 128, n0 = blockIdx.x * 128;
    int wm = wid >> 1, wn = wid & 1;      // warp tile origin: (wm*32, wn*64)

    const __nv_bfloat16* s0 = Ah + (size_t)m0 * K;
    const __nv_bfloat16* s1 = Al + (size_t)m0 * K;
    const __nv_bfloat16* s2 = Wh + (size_t)n0 * K;
    const __nv_bfloat16* s3 = Wl + (size_t)n0 * K;

    float acc[2][8][4];
#pragma unroll
    for (int i = 0; i < 2; i++)
#pragma unroll
        for (int j = 0; j < 8; j++)
#pragma unroll
            for (int r = 0; r < 4; r++) acc[i][j][r] = 0.f;

    int NT = K >> 5;
    gemm_load_stage(smbase, 0, NT, K, tid, s0, s1, s2, s3);
    gemm_load_stage(smbase, 1, NT, K, tid, s0, s1, s2, s3);
    gemm_load_stage(smbase, 2, NT, K, tid, s0, s1, s2, s3);

    int lt = lane >> 3, lr = lane & 7;    // ldmatrix tile id / row-in-tile
    for (int kt = 0; kt < NT; kt++) {
        CP_WAIT2();
        __syncthreads();
        uint32_t sb = smbase + (kt % 3) * STAGE_BYTES;
#pragma unroll
        for (int kk = 0; kk < 2; kk++) {
            uint32_t a_hi[2][4], a_lo[2][4];
#pragma unroll
            for (int i = 0; i < 2; i++) {
                int row = wm * 32 + i * 16 + lr + (lt & 1) * 8;
                int kofs = kk * 16 + (lt >> 1) * 8;
                uint32_t addr = sb + row * TSTRIDE + kofs * 2;
                LDSM_X4(a_hi[i], addr);
                LDSM_X4(a_lo[i], addr + BUF_BYTES);
            }
            uint32_t b_hi[4][4], b_lo[4][4];
#pragma unroll
            for (int j = 0; j < 4; j++) {
                int row = wn * 64 + j * 16 + lr + (lt >> 1) * 8;
                int kofs = kk * 16 + (lt & 1) * 8;
                uint32_t addr = sb + 2 * BUF_BYTES + row * TSTRIDE + kofs * 2;
                LDSM_X4(b_hi[j], addr);
                LDSM_X4(b_lo[j], addr + BUF_BYTES);
            }
#pragma unroll
            for (int i = 0; i < 2; i++)
#pragma unroll
                for (int j = 0; j < 8; j++) {
                    uint32_t bh0 = b_hi[j >> 1][(j & 1) * 2], bh1 = b_hi[j >> 1][(j & 1) * 2 + 1];
                    uint32_t bl0 = b_lo[j >> 1][(j & 1) * 2], bl1 = b_lo[j >> 1][(j & 1) * 2 + 1];
                    MMA_BF16(acc[i][j], a_hi[i], bh0, bh1);
                    MMA_BF16(acc[i][j], a_hi[i], bl0, bl1);
                    MMA_BF16(acc[i][j], a_lo[i], bh0, bh1);
                }
        }
        __syncthreads();
        gemm_load_stage(smbase, kt + 3, NT, K, tid, s0, s1, s2, s3);
    }

    // epilogue: c[i][j] lane layout: row = i*16 + lane/4 (+8 for regs 2,3), col = j*8 + (lane&3)*2
    int rbase = m0 + wm * 32 + (lane >> 2);
    int cbase = n0 + wn * 64 + (lane & 3) * 2;
#pragma unroll
    for (int i = 0; i < 2; i++) {
#pragma unroll
        for (int half = 0; half < 2; half++) {
            size_t row = (size_t)(rbase + i * 16 + half * 8);
#pragma unroll
            for (int j = 0; j < 8; j++) {
                size_t idx = row * (size_t)N + cbase + j * 8;
                float v0 = acc[i][j][half * 2 + 0];
                float v1 = acc[i][j][half * 2 + 1];
                if (res) { v0 += res[idx]; v1 += res[idx + 1]; }
                *(float2*)(C + idx) = make_float2(v0, v1);
            }
        }
    }
}

// ---------------- RMSNorm over DIM=1024, one block per token ----------------
__global__ void rmsnorm_kernel(const float* __restrict__ x, float* __restrict__ o)
{
    int n = blockIdx.x;
    int tid = threadIdx.x;
    const float4* xr = (const float4*)(x + (size_t)n * 1024);
    float4 v = xr[tid];
    float s = v.x*v.x + v.y*v.y + v.z*v.z + v.w*v.w;
#pragma unroll
    for (int off = 16; off > 0; off >>= 1) s += __shfl_xor_sync(0xffffffffu, s, off);
    __shared__ float red[8];
    if ((tid & 31) == 0) red[tid >> 5] = s;
    __syncthreads();
    float tot = 0.f;
#pragma unroll
    for (int i = 0; i < 8; i++) tot += red[i];
    float r = rsqrtf(tot * (1.f/1024.f) + 1e-6f);
    v.x *= r; v.y *= r; v.z *= r; v.w *= r;
    ((float4*)(o + (size_t)n * 1024))[tid] = v;
}

// ---------------- per-head RMSNorm * gain + RoPE, in place (q and k) ----------------
__global__ void qkprep_kernel(float* __restrict__ q, float* __restrict__ k,
                              const float* __restrict__ qg, const float* __restrict__ kg)
{
    int gt = blockIdx.x * blockDim.x + threadIdx.x;
    int w = gt >> 5;
    int lane = gt & 31;
    float* ptr; float gain; int t;
    if (w < 4096 * 16) {
        int n = w >> 4, h = w & 15;
        ptr = q + (size_t)n * 1024 + h * 64;
        gain = qg[h];
        t = n & 2047;
    } else {
        int w2 = w - 4096 * 16;
        int n = w2 >> 2, h = w2 & 3;
        ptr = k + (size_t)n * 256 + h * 64;
        gain = kg[h];
        t = n & 2047;
    }
    float v1 = ptr[lane], v2 = ptr[lane + 32];
    float s = v1*v1 + v2*v2;
#pragma unroll
    for (int off = 16; off > 0; off >>= 1) s += __shfl_xor_sync(0xffffffffu, s, off);
    float r = rsqrtf(s * (1.f/64.f) + 1e-6f) * gain;
    v1 *= r; v2 *= r;
    float freq = powf(10000.f, -(float)(2 * lane) / 64.f);
    float ang = (float)t * freq;
    float sn, cs;
    sincosf(ang, &sn, &cs);
    ptr[lane]      = v1 * cs + v2 * sn;
    ptr[lane + 32] = v2 * cs - v1 * sn;
}

// ---------------- causal attention, streaming softmax ----------------
__global__ __launch_bounds__(64) void attn_kernel(
    const float* __restrict__ q, const float* __restrict__ k,
    const float* __restrict__ v, float* __restrict__ y)
{
    int qt = blockIdx.x, h = blockIdx.y, b = blockIdx.z;
    int kvh = h >> 2;
    int tid = threadIdx.x;
    int qr = qt * 64 + tid;
    const float4* qrow = (const float4*)(q + ((size_t)(b * 2048 + qr)) * 1024 + h * 64);
    float4 Q[16], O[16];
#pragma unroll
    for (int i = 0; i < 16; i++) { Q[i] = qrow[i]; O[i] = make_float4(0.f,0.f,0.f,0.f); }
    float m = -1e30f, l = 0.f;
    __shared__ __align__(16) float Ks[32][64];
    __shared__ __align__(16) float Vs[32][64];
    __shared__ float Ss[64][33];
    int ktend = qt * 64 + 63;
    for (int kt0 = 0; kt0 <= ktend; kt0 += 32) {
        __syncthreads();
#pragma unroll
        for (int r = 0; r < 8; r++) {
            int f = tid + 64 * r;
            int row = f >> 4;
            int c4 = (f & 15) << 2;
            size_t gi = ((size_t)(b * 2048 + kt0 + row)) * 256 + kvh * 64 + c4;
            *(float4*)&Ks[row][c4] = *(const float4*)(k + gi);
            *(float4*)&Vs[row][c4] = *(const float4*)(v + gi);
        }
        __syncthreads();
        float tmax = -1e30f;
        for (int j = 0; j < 32; j++) {
            float sv = -1e30f;
            if (kt0 + j <= qr) {
                const float4* kr = (const float4*)&Ks[j][0];
                float acc = 0.f;
#pragma unroll
                for (int i = 0; i < 16; i++) {
                    float4 kk = kr[i];
                    acc = fmaf(Q[i].x, kk.x, acc);
                    acc = fmaf(Q[i].y, kk.y, acc);
                    acc = fmaf(Q[i].z, kk.z, acc);
                    acc = fmaf(Q[i].w, kk.w, acc);
                }
                sv = acc * 0.125f;
            }
            Ss[tid][j] = sv;
            tmax = fmaxf(tmax, sv);
        }
        if (tmax > -1e29f) {
            float mnew = fmaxf(m, tmax);
            float corr = expf(m - mnew);
            m = mnew;
            l *= corr;
#pragma unroll
            for (int i = 0; i < 16; i++) {
                O[i].x *= corr; O[i].y *= corr; O[i].z *= corr; O[i].w *= corr;
            }
            for (int j = 0; j < 32; j++) {
                float p = expf(Ss[tid][j] - m);
                l += p;
                const float4* vr = (const float4*)&Vs[j][0];
#pragma unroll
                for (int i = 0; i < 16; i++) {
                    float4 vv = vr[i];
                    O[i].x = fmaf(p, vv.x, O[i].x);
                    O[i].y = fmaf(p, vv.y, O[i].y);
                    O[i].z = fmaf(p, vv.z, O[i].z);
                    O[i].w = fmaf(p, vv.w, O[i].w);
                }
            }
        }
    }
    float inv = 1.f / l;
    float4* yr = (float4*)(y + ((size_t)(b * 2048 + qr)) * 1024 + h * 64);
#pragma unroll
    for (int i = 0; i < 16; i++) {
        O[i].x *= inv; O[i].y *= inv; O[i].z *= inv; O[i].w *= inv;
        yr[i] = O[i];
    }
}

// ---------------- block-diagonal 64x64 GEMM (fused roll+transpose epilogue) ----------------
__global__ __launch_bounds__(256) void blockdiag_kernel(
    const float* __restrict__ X, const float* __restrict__ Wall, float* __restrict__ O,
    int nb, const int* __restrict__ selp,
    int perm_out, int accum, const float* __restrict__ coefp)
{
    int F = nb * 64;
    int sel = *selp;
    int g = blockIdx.x;
    int n0 = blockIdx.y * 64;
    const float* W = Wall + (size_t)sel * F * 64 + (size_t)g * 64 * 64;
    __shared__ __align__(16) float XsT[64][68];
    __shared__ __align__(16) float Ws[64][68];
    int tid = threadIdx.x;
#pragma unroll
    for (int r = 0; r < 4; r++) {
        int f = tid + 256 * r;
        int row = f >> 4;
        int c4 = (f & 15) << 2;
        float4 xv = *(const float4*)(X + (size_t)(n0 + row) * F + g * 64 + c4);
        XsT[c4+0][row] = xv.x; XsT[c4+1][row] = xv.y;
        XsT[c4+2][row] = xv.z; XsT[c4+3][row] = xv.w;
        float4 wv = *(const float4*)(W + row * 64 + c4);
        *(float4*)&Ws[row][c4] = wv;
    }
    __syncthreads();
    int tx = tid & 15, ty = tid >> 4;
    float acc[4][4];
#pragma unroll
    for (int i = 0; i < 4; i++)
#pragma unroll
        for (int j = 0; j < 4; j++) acc[i][j] = 0.f;
#pragma unroll
    for (int c = 0; c < 64; c++) {
        float a[4], bb[4];
        *(float4*)a = *(const float4*)&XsT[c][ty*4];
        *(float4*)bb = *(const float4*)&Ws[c][tx*4];
#pragma unroll
        for (int i = 0; i < 4; i++)
#pragma unroll
            for (int j = 0; j < 4; j++) acc[i][j] = fmaf(a[i], bb[j], acc[i][j]);
    }
    float alpha = coefp ? *coefp : 1.f;
    int gout = g;
    if (perm_out) {
        gout = g + (sel % nb);
        if (gout >= nb) gout -= nb;
    }
#pragma unroll
    for (int i = 0; i < 4; i++) {
        size_t nrow = (size_t)(n0 + ty * 4 + i);
#pragma unroll
        for (int j = 0; j < 4; j++) {
            int d = tx * 4 + j;
            size_t idx = perm_out ? nrow * F + (size_t)d * nb + gout
                                  : nrow * F + (size_t)g * 64 + d;
            float vv = alpha * acc[i][j];
            if (accum) O[idx] += vv; else O[idx] = vv;
        }
    }
}

// ---------------- elementwise ----------------
__global__ void relu2_kernel(float* __restrict__ a, int n)
{
    int i = blockIdx.x * blockDim.x + threadIdx.x;
    if (i < n) { float v = a[i]; v = v > 0.f ? v : 0.f; a[i] = v * v; }
}
__global__ void add_kernel(const float* __restrict__ a, const float* __restrict__ b,
                           float* __restrict__ o, int n)
{
    int i = blockIdx.x * blockDim.x + threadIdx.x;
    if (i < n) o[i] = a[i] + b[i];
}

// ---------------- top-2 router ----------------
__global__ void router_kernel(const float* __restrict__ fcl, const float* __restrict__ pjl,
                              int* __restrict__ sel, float* __restrict__ coef)
{
    if (threadIdx.x == 0 && blockIdx.x == 0) {
#pragma unroll
        for (int s = 0; s < 2; s++) {
            const float* L = s ? pjl : fcl;
            int i1 = 0; float v1 = L[0];
            for (int i = 1; i < 8; i++) if (L[i] > v1) { v1 = L[i]; i1 = i; }
            int i2 = -1; float v2 = -1e30f;
            for (int i = 0; i < 8; i++) if (i != i1 && L[i] > v2) { v2 = L[i]; i2 = i; }
            float e = expf(v2 - v1);
            float z = 1.f + e;
            sel[s*2+0] = i1; sel[s*2+1] = i2;
            coef[s*2+0] = 1.f / z; coef[s*2+1] = e / z;
        }
    }
}

// ---------------- host orchestration ----------------
extern "C" void kernel_launch(void* const* d_in, const int* in_sizes, int n_in,
                              void* d_out, int out_size)
{
    (void)in_sizes; (void)n_in; (void)out_size;
    const float* x      = (const float*)d_in[0];
    const float* wq     = (const float*)d_in[1];
    const float* wk     = (const float*)d_in[2];
    const float* wv     = (const float*)d_in[3];
    const float* wo     = (const float*)d_in[4];
    const float* qg     = (const float*)d_in[5];
    const float* kg     = (const float*)d_in[6];
    const float* fc_s1  = (const float*)d_in[7];
    const float* fc_s2  = (const float*)d_in[8];
    const float* fc_mix = (const float*)d_in[9];
    const float* fc_lg  = (const float*)d_in[10];
    const float* pj_s1  = (const float*)d_in[11];
    const float* pj_s2  = (const float*)d_in[12];
    const float* pj_mix = (const float*)d_in[13];
    const float* pj_lg  = (const float*)d_in[14];

    float *xn, *q, *k, *v, *y, *x2, *t1, *tk, *ac, *pa, *coef;
    int* sel;
    __nv_bfloat16 *ah, *al, *wh, *wl;
    cudaGetSymbolAddress((void**)&xn, g_xn);
    cudaGetSymbolAddress((void**)&q,  g_q);
    cudaGetSymbolAddress((void**)&k,  g_k);
    cudaGetSymbolAddress((void**)&v,  g_v);
    cudaGetSymbolAddress((void**)&y,  g_y);
    cudaGetSymbolAddress((void**)&x2, g_x2);
    cudaGetSymbolAddress((void**)&t1, g_t1);
    cudaGetSymbolAddress((void**)&tk, g_tk);
    cudaGetSymbolAddress((void**)&ac, g_ac);
    cudaGetSymbolAddress((void**)&pa, g_pa);
    cudaGetSymbolAddress((void**)&sel,  g_sel);
    cudaGetSymbolAddress((void**)&coef, g_coef);
    cudaGetSymbolAddress((void**)&ah, g_ah);
    cudaGetSymbolAddress((void**)&al, g_al);
    cudaGetSymbolAddress((void**)&wh, g_wh);
    cudaGetSymbolAddress((void**)&wl, g_wl);

    cudaFuncSetAttribute(gemm_bf16x3, cudaFuncAttributeMaxDynamicSharedMemorySize, GEMM_SMEM);

    // x1 = rms_norm(x); split to bf16
    rmsnorm_kernel<<<4096, 256>>>(x, xn);
    split_kernel<<<2048, 256>>>(xn, ah, al, 4194304, nullptr, 0);

    // q/k/v projections (tensor cores)
    split_kernel<<<512, 256>>>(wq, wh, wl, 1048576, nullptr, 0);
    gemm_bf16x3<<<dim3(8, 32), 256, GEMM_SMEM>>>(ah, al, wh, wl, q, nullptr, 1024, 1024);
    split_kernel<<<128, 256>>>(wk, wh, wl, 262144, nullptr, 0);
    gemm_bf16x3<<<dim3(2, 32), 256, GEMM_SMEM>>>(ah, al, wh, wl, k, nullptr, 256, 1024);
    split_kernel<<<128, 256>>>(wv, wh, wl, 262144, nullptr, 0);
    gemm_bf16x3<<<dim3(2, 32), 256, GEMM_SMEM>>>(ah, al, wh, wl, v, nullptr, 256, 1024);

    // per-head rmsnorm * gain + rope
    qkprep_kernel<<<10240, 256>>>(q, k, qg, kg);
    // causal attention
    attn_kernel<<<dim3(32, 16, 2), 64>>>(q, k, v, y);

    // x2 = x + y @ wo^T
    split_kernel<<<2048, 256>>>(y, ah, al, 4194304, nullptr, 0);
    split_kernel<<<512, 256>>>(wo, wh, wl, 1048576, nullptr, 0);
    gemm_bf16x3<<<dim3(8, 32), 256, GEMM_SMEM>>>(ah, al, wh, wl, x2, x, 1024, 1024);

    // h = rms_norm(x2)
    rmsnorm_kernel<<<4096, 256>>>(x2, xn);
    router_kernel<<<1, 32>>>(fc_lg, pj_lg, sel, coef);

    // fc bank: DIM -> HID, two experts accumulated into ac
    for (int r = 0; r < 2; r++) {
        blockdiag_kernel<<<dim3(16, 64), 256>>>(xn, fc_s1, t1, 16, sel + r, 1, 0, nullptr);
        split_kernel<<<2048, 256>>>(t1, ah, al, 4194304, nullptr, 0);
        split_kernel<<<2048, 256>>>(fc_mix, wh, wl, 4194304, sel + r, (size_t)4194304);
        gemm_bf16x3<<<dim3(32, 32), 256, GEMM_SMEM>>>(ah, al, wh, wl, tk, nullptr, 4096, 1024);
        blockdiag_kernel<<<dim3(64, 64), 256>>>(tk, fc_s2, ac, 64, sel + r, 0, r, coef + r);
    }
    // h = relu(h)^2
    relu2_kernel<<<65536, 256>>>(ac, 16777216);
    // pj bank: HID -> DIM, two experts accumulated into pa
    for (int r = 0; r < 2; r++) {
        blockdiag_kernel<<<dim3(64, 64), 256>>>(ac, pj_s1, tk, 64, sel + 2 + r, 1, 0, nullptr);
        split_kernel<<<8192, 256>>>(tk, ah, al, 16777216, nullptr, 0);
        split_kernel<<<2048, 256>>>(pj_mix, wh, wl, 4194304, sel + 2 + r, (size_t)4194304);
        gemm_bf16x3<<<dim3(8, 32), 256, GEMM_SMEM>>>(ah, al, wh, wl, t1, nullptr, 1024, 4096);
        blockdiag_kernel<<<dim3(16, 64), 256>>>(t1, pj_s2, pa, 16, sel + 2 + r, 0, r, coef + 2 + r);
    }
    // out = x2 + pj_out
    add_kernel<<<16384, 256>>>(x2, pa, (float*)d_out, 4194304);
}

// round 4
// speedup vs baseline: 2.1621x; 1.2189x over previous
#include <cuda_runtime.h>
#include <cuda_bf16.h>
#include <math.h>
#include <stdint.h>

// ---------------- static device scratch (no allocations allowed) ----------------
static __device__ float g_xn [4096*1024];
static __device__ float g_qkv[4096*1536];
static __device__ float g_x2 [4096*1024];
static __device__ float g_t1 [4096*1024];
static __device__ float g_tk [16777216];
static __device__ float g_ac [16777216];
static __device__ float g_pa [4096*1024];
static __device__ int   g_sel[4];
static __device__ float g_coef[4];
static __device__ __nv_bfloat16 g_ah[16777216];
static __device__ __nv_bfloat16 g_al[16777216];
static __device__ __nv_bfloat16 g_wh[4194304];
static __device__ __nv_bfloat16 g_wl[4194304];
static __device__ __nv_bfloat16 g_qh[4194304];
static __device__ __nv_bfloat16 g_ql[4194304];
static __device__ __nv_bfloat16 g_kh[1048576];
static __device__ __nv_bfloat16 g_kl[1048576];
static __device__ __nv_bfloat16 g_vh[1048576];
static __device__ __nv_bfloat16 g_vl[1048576];
static __device__ __nv_bfloat16 g_yh[4194304];
static __device__ __nv_bfloat16 g_yl[4194304];

// ---------------- PTX helpers ----------------
__device__ __forceinline__ uint32_t smem_u32(const void* p) {
    uint32_t a;
    asm("{ .reg .u64 t; cvta.to.shared.u64 t, %1; cvt.u32.u64 %0, t; }" : "=r"(a) : "l"(p));
    return a;
}
#define CP_ASYNC16(dst, src) \
    asm volatile("cp.async.cg.shared.global [%0], [%1], 16;" :: "r"(dst), "l"(src))
#define CP_COMMIT() asm volatile("cp.async.commit_group;" ::: "memory")
#define CP_WAIT2()  asm volatile("cp.async.wait_group 2;" ::: "memory")
#define CP_WAIT0()  asm volatile("cp.async.wait_group 0;" ::: "memory")

#define LDSM_X4(r, addr) \
    asm volatile("ldmatrix.sync.aligned.m8n8.x4.shared.b16 {%0,%1,%2,%3}, [%4];" \
        : "=r"((r)[0]), "=r"((r)[1]), "=r"((r)[2]), "=r"((r)[3]) : "r"(addr))
#define LDSM_X4_T(r, addr) \
    asm volatile("ldmatrix.sync.aligned.m8n8.x4.trans.shared.b16 {%0,%1,%2,%3}, [%4];" \
        : "=r"((r)[0]), "=r"((r)[1]), "=r"((r)[2]), "=r"((r)[3]) : "r"(addr))

#define MMA_BF16(d, a, b0, b1) \
    asm volatile("mma.sync.aligned.m16n8k16.row.col.f32.bf16.bf16.f32 " \
        "{%0,%1,%2,%3}, {%4,%5,%6,%7}, {%8,%9}, {%0,%1,%2,%3};" \
        : "+f"((d)[0]), "+f"((d)[1]), "+f"((d)[2]), "+f"((d)[3]) \
        : "r"((a)[0]), "r"((a)[1]), "r"((a)[2]), "r"((a)[3]), "r"(b0), "r"(b1))

__device__ __forceinline__ void split2(float v0, float v1, uint32_t& h, uint32_t& l) {
    __nv_bfloat16 h0 = __float2bfloat16_rn(v0), h1 = __float2bfloat16_rn(v1);
    float r0 = v0 - __bfloat162float(h0), r1 = v1 - __bfloat162float(h1);
    __nv_bfloat16 l0 = __float2bfloat16_rn(r0), l1 = __float2bfloat16_rn(r1);
    h = (uint32_t)*(uint16_t*)&h0 | ((uint32_t)*(uint16_t*)&h1 << 16);
    l = (uint32_t)*(uint16_t*)&l0 | ((uint32_t)*(uint16_t*)&l1 << 16);
}

// ---------------- fp32 -> (hi,lo) bf16 split (weights) ----------------
__global__ void split_kernel(const float* __restrict__ src, __nv_bfloat16* __restrict__ hi,
                             __nv_bfloat16* __restrict__ lo, int n,
                             const int* __restrict__ selp, size_t stride)
{
    if (selp) src += (size_t)(*selp) * stride;
    int i = (blockIdx.x * blockDim.x + threadIdx.x) * 8;
    if (i >= n) return;
    float4 a = *(const float4*)(src + i);
    float4 b = *(const float4*)(src + i + 4);
    uint32_t h0,l0,h1,l1,h2,l2,h3,l3;
    split2(a.x, a.y, h0, l0); split2(a.z, a.w, h1, l1);
    split2(b.x, b.y, h2, l2); split2(b.z, b.w, h3, l3);
    *(uint4*)(hi + i) = make_uint4(h0, h1, h2, h3);
    *(uint4*)(lo + i) = make_uint4(l0, l1, l2, l3);
}

// ---------------- HMMA bf16x3 GEMM: C = A(MxK)*W(NxK)^T (+res) ----------------
#define TSTRIDE 80
#define BUF_BYTES (128 * TSTRIDE)
#define STAGE_BYTES (4 * BUF_BYTES)
#define GEMM_SMEM (3 * STAGE_BYTES)

__device__ __forceinline__ void gemm_load_stage(
    uint32_t smbase, int kt, int NT, int K, int tid,
    const __nv_bfloat16* s0, const __nv_bfloat16* s1,
    const __nv_bfloat16* s2, const __nv_bfloat16* s3)
{
    if (kt < NT) {
        uint32_t sb = smbase + (kt % 3) * STAGE_BYTES;
        int k0 = kt * 32;
        const __nv_bfloat16* srcs[4] = {s0, s1, s2, s3};
#pragma unroll
        for (int t = 0; t < 8; t++) {
            int c = tid + 256 * t;
            int buf = c >> 9, cc = c & 511;
            int row = cc >> 2, kc = cc & 3;
            uint32_t dst = sb + buf * BUF_BYTES + row * TSTRIDE + kc * 16;
            const __nv_bfloat16* src = srcs[buf] + (size_t)row * K + k0 + kc * 8;
            CP_ASYNC16(dst, src);
        }
    }
    CP_COMMIT();
}

__global__ __launch_bounds__(256) void gemm_bf16x3(
    const __nv_bfloat16* __restrict__ Ah, const __nv_bfloat16* __restrict__ Al,
    const __nv_bfloat16* __restrict__ Wh, const __nv_bfloat16* __restrict__ Wl,
    float* __restrict__ C, const float* __restrict__ res, int N, int K)
{
    extern __shared__ char smem[];
    uint32_t smbase = smem_u32(smem);
    int tid = threadIdx.x, wid = tid >> 5, lane = tid & 31;
    int m0 = blockIdx.y * 128, n0 = blockIdx.x * 128;
    int wm = wid >> 1, wn = wid & 1;

    const __nv_bfloat16* s0 = Ah + (size_t)m0 * K;
    const __nv_bfloat16* s1 = Al + (size_t)m0 * K;
    const __nv_bfloat16* s2 = Wh + (size_t)n0 * K;
    const __nv_bfloat16* s3 = Wl + (size_t)n0 * K;

    float acc[2][8][4];
#pragma unroll
    for (int i = 0; i < 2; i++)
#pragma unroll
        for (int j = 0; j < 8; j++)
#pragma unroll
            for (int r = 0; r < 4; r++) acc[i][j][r] = 0.f;

    int NT = K >> 5;
    gemm_load_stage(smbase, 0, NT, K, tid, s0, s1, s2, s3);
    gemm_load_stage(smbase, 1, NT, K, tid, s0, s1, s2, s3);
    gemm_load_stage(smbase, 2, NT, K, tid, s0, s1, s2, s3);

    int lt = lane >> 3, lr = lane & 7;
    for (int kt = 0; kt < NT; kt++) {
        CP_WAIT2();
        __syncthreads();
        uint32_t sb = smbase + (kt % 3) * STAGE_BYTES;
#pragma unroll
        for (int kk = 0; kk < 2; kk++) {
            uint32_t a_hi[2][4], a_lo[2][4];
#pragma unroll
            for (int i = 0; i < 2; i++) {
                int row = wm * 32 + i * 16 + lr + (lt & 1) * 8;
                int kofs = kk * 16 + (lt >> 1) * 8;
                uint32_t addr = sb + row * TSTRIDE + kofs * 2;
                LDSM_X4(a_hi[i], addr);
                LDSM_X4(a_lo[i], addr + BUF_BYTES);
            }
            uint32_t b_hi[4][4], b_lo[4][4];
#pragma unroll
            for (int j = 0; j < 4; j++) {
                int row = wn * 64 + j * 16 + lr + (lt >> 1) * 8;
                int kofs = kk * 16 + (lt & 1) * 8;
                uint32_t addr = sb + 2 * BUF_BYTES + row * TSTRIDE + kofs * 2;
                LDSM_X4(b_hi[j], addr);
                LDSM_X4(b_lo[j], addr + BUF_BYTES);
            }
#pragma unroll
            for (int i = 0; i < 2; i++)
#pragma unroll
                for (int j = 0; j < 8; j++) {
                    uint32_t bh0 = b_hi[j >> 1][(j & 1) * 2], bh1 = b_hi[j >> 1][(j & 1) * 2 + 1];
                    uint32_t bl0 = b_lo[j >> 1][(j & 1) * 2], bl1 = b_lo[j >> 1][(j & 1) * 2 + 1];
                    MMA_BF16(acc[i][j], a_hi[i], bh0, bh1);
                    MMA_BF16(acc[i][j], a_hi[i], bl0, bl1);
                    MMA_BF16(acc[i][j], a_lo[i], bh0, bh1);
                }
        }
        __syncthreads();
        gemm_load_stage(smbase, kt + 3, NT, K, tid, s0, s1, s2, s3);
    }

    int rbase = m0 + wm * 32 + (lane >> 2);
    int cbase = n0 + wn * 64 + (lane & 3) * 2;
#pragma unroll
    for (int i = 0; i < 2; i++) {
#pragma unroll
        for (int half = 0; half < 2; half++) {
            size_t row = (size_t)(rbase + i * 16 + half * 8);
#pragma unroll
            for (int j = 0; j < 8; j++) {
                size_t idx = row * (size_t)N + cbase + j * 8;
                float v0 = acc[i][j][half * 2 + 0];
                float v1 = acc[i][j][half * 2 + 1];
                if (res) { v0 += res[idx]; v1 += res[idx + 1]; }
                *(float2*)(C + idx) = make_float2(v0, v1);
            }
        }
    }
}

// ---------------- RMSNorm (fp32 out) ----------------
__global__ void rmsnorm_kernel(const float* __restrict__ x, float* __restrict__ o)
{
    int n = blockIdx.x;
    int tid = threadIdx.x;
    const float4* xr = (const float4*)(x + (size_t)n * 1024);
    float4 v = xr[tid];
    float s = v.x*v.x + v.y*v.y + v.z*v.z + v.w*v.w;
#pragma unroll
    for (int off = 16; off > 0; off >>= 1) s += __shfl_xor_sync(0xffffffffu, s, off);
    __shared__ float red[8];
    if ((tid & 31) == 0) red[tid >> 5] = s;
    __syncthreads();
    float tot = 0.f;
#pragma unroll
    for (int i = 0; i < 8; i++) tot += red[i];
    float r = rsqrtf(tot * (1.f/1024.f) + 1e-6f);
    v.x *= r; v.y *= r; v.z *= r; v.w *= r;
    ((float4*)(o + (size_t)n * 1024))[tid] = v;
}

// ---------------- RMSNorm fused with bf16 hi/lo split output ----------------
__global__ void rmsnorm_split_kernel(const float* __restrict__ x,
                                     __nv_bfloat16* __restrict__ hi,
                                     __nv_bfloat16* __restrict__ lo)
{
    int n = blockIdx.x;
    int tid = threadIdx.x;
    const float4* xr = (const float4*)(x + (size_t)n * 1024);
    float4 v = xr[tid];
    float s = v.x*v.x + v.y*v.y + v.z*v.z + v.w*v.w;
#pragma unroll
    for (int off = 16; off > 0; off >>= 1) s += __shfl_xor_sync(0xffffffffu, s, off);
    __shared__ float red[8];
    if ((tid & 31) == 0) red[tid >> 5] = s;
    __syncthreads();
    float tot = 0.f;
#pragma unroll
    for (int i = 0; i < 8; i++) tot += red[i];
    float r = rsqrtf(tot * (1.f/1024.f) + 1e-6f);
    uint32_t h0,l0,h1,l1;
    split2(v.x*r, v.y*r, h0, l0);
    split2(v.z*r, v.w*r, h1, l1);
    size_t base = (size_t)n * 1024 + tid * 4;
    *(uint2*)(hi + base) = make_uint2(h0, h1);
    *(uint2*)(lo + base) = make_uint2(l0, l1);
}

// ---------------- qk prep (rms*gain + rope) + v prep; writes split head-major ----------------
// warps [0,65536): q; [65536,81920): k; [81920,98304): v
__global__ void qkvprep_kernel(const float* __restrict__ qkv,
                               __nv_bfloat16* __restrict__ qh, __nv_bfloat16* __restrict__ ql,
                               __nv_bfloat16* __restrict__ kh, __nv_bfloat16* __restrict__ kl,
                               __nv_bfloat16* __restrict__ vh, __nv_bfloat16* __restrict__ vl,
                               const float* __restrict__ qg, const float* __restrict__ kg)
{
    int gt = blockIdx.x * blockDim.x + threadIdx.x;
    int w = gt >> 5, lane = gt & 31;
    if (w < 81920) {
        const float* src; float gain; int t; __nv_bfloat16 *dh, *dl; size_t dbase;
        if (w < 65536) {
            int n = w >> 4, h = w & 15;
            src = qkv + (size_t)n * 1536 + h * 64;
            gain = qg[h]; t = n & 2047;
            dbase = ((size_t)((n >> 11) * 16 + h) * 2048 + t) * 64;
            dh = qh; dl = ql;
        } else {
            int w2 = w - 65536;
            int n = w2 >> 2, h = w2 & 3;
            src = qkv + (size_t)n * 1536 + 1024 + h * 64;
            gain = kg[h]; t = n & 2047;
            dbase = ((size_t)((n >> 11) * 4 + h) * 2048 + t) * 64;
            dh = kh; dl = kl;
        }
        float v1 = src[lane], v2 = src[lane + 32];
        float s = v1*v1 + v2*v2;
#pragma unroll
        for (int off = 16; off > 0; off >>= 1) s += __shfl_xor_sync(0xffffffffu, s, off);
        float r = rsqrtf(s * (1.f/64.f) + 1e-6f) * gain;
        v1 *= r; v2 *= r;
        float freq = powf(10000.f, -(float)(2 * lane) / 64.f);
        float ang = (float)t * freq;
        float sn, cs;
        sincosf(ang, &sn, &cs);
        float o1 = v1 * cs + v2 * sn;
        float o2 = v2 * cs - v1 * sn;
        __nv_bfloat16 hb1 = __float2bfloat16_rn(o1);
        __nv_bfloat16 lb1 = __float2bfloat16_rn(o1 - __bfloat162float(hb1));
        __nv_bfloat16 hb2 = __float2bfloat16_rn(o2);
        __nv_bfloat16 lb2 = __float2bfloat16_rn(o2 - __bfloat162float(hb2));
        dh[dbase + lane] = hb1; dl[dbase + lane] = lb1;
        dh[dbase + lane + 32] = hb2; dl[dbase + lane + 32] = lb2;
    } else {
        int w2 = w - 81920;
        int n = w2 >> 2, h = w2 & 3;
        const float* src = qkv + (size_t)n * 1536 + 1280 + h * 64;
        int t = n & 2047;
        size_t dbase = ((size_t)((n >> 11) * 4 + h) * 2048 + t) * 64;
        float v1 = src[lane], v2 = src[lane + 32];
        __nv_bfloat16 hb1 = __float2bfloat16_rn(v1);
        __nv_bfloat16 lb1 = __float2bfloat16_rn(v1 - __bfloat162float(hb1));
        __nv_bfloat16 hb2 = __float2bfloat16_rn(v2);
        __nv_bfloat16 lb2 = __float2bfloat16_rn(v2 - __bfloat162float(hb2));
        vh[dbase + lane] = hb1; vl[dbase + lane] = lb1;
        vh[dbase + lane + 32] = hb2; vl[dbase + lane + 32] = lb2;
    }
}

// ---------------- tensor-core flash attention (bf16x3, fp32 softmax) ----------------
#define AT_ROWB 144
#define AT_TILE (64 * AT_ROWB)            // 9216
#define AT_STAGE (4 * AT_TILE)            // 36864
#define ATTN_SMEM (2 * AT_TILE + 2 * AT_STAGE)  // 92160

__device__ __forceinline__ void attn_load_kv(
    uint32_t dstbase, int tid,
    const __nv_bfloat16* kh, const __nv_bfloat16* kl,
    const __nv_bfloat16* vh, const __nv_bfloat16* vl,
    size_t kvoff, int kt)
{
    const __nv_bfloat16* srcs[4] = {kh, kl, vh, vl};
#pragma unroll
    for (int t = 0; t < 16; t++) {
        int idx = tid + 128 * t;
        int buf = idx >> 9, cc = idx & 511, row = cc >> 3, ch = cc & 7;
        const __nv_bfloat16* src = srcs[buf] + kvoff + (size_t)(kt * 64 + row) * 64 + ch * 8;
        CP_ASYNC16(dstbase + buf * AT_TILE + row * AT_ROWB + ch * 16, src);
    }
}

__global__ __launch_bounds__(128) void attn_mma_kernel(
    const __nv_bfloat16* __restrict__ qh, const __nv_bfloat16* __restrict__ ql,
    const __nv_bfloat16* __restrict__ kh, const __nv_bfloat16* __restrict__ kl,
    const __nv_bfloat16* __restrict__ vh, const __nv_bfloat16* __restrict__ vl,
    __nv_bfloat16* __restrict__ yh, __nv_bfloat16* __restrict__ yl)
{
    extern __shared__ char smem[];
    uint32_t sb = smem_u32(smem);
    int qt = blockIdx.x, h = blockIdx.y, b = blockIdx.z;
    int tid = threadIdx.x, w = tid >> 5, lane = tid & 31;
    int lr = lane & 7, lt = lane >> 3;
    size_t qoff = ((size_t)(b * 16 + h) * 2048 + qt * 64) * 64;
    size_t kvoff = (size_t)(b * 4 + (h >> 2)) * 2048 * 64;

    // load Q (hi/lo)
#pragma unroll
    for (int t = 0; t < 8; t++) {
        int idx = tid + 128 * t;
        int buf = idx >> 9, cc = idx & 511, row = cc >> 3, ch = cc & 7;
        const __nv_bfloat16* src = (buf ? ql : qh) + qoff + row * 64 + ch * 8;
        CP_ASYNC16(sb + buf * AT_TILE + row * AT_ROWB + ch * 16, src);
    }
    CP_COMMIT();
    attn_load_kv(sb + 2 * AT_TILE, tid, kh, kl, vh, vl, kvoff, 0);
    CP_COMMIT();
    CP_WAIT0();
    __syncthreads();

    // Q fragments (held in registers for whole kernel)
    uint32_t qfh[4][4], qfl[4][4];
#pragma unroll
    for (int kk = 0; kk < 4; kk++) {
        uint32_t addr = sb + (w * 16 + lr + (lt & 1) * 8) * AT_ROWB + (kk * 16 + (lt >> 1) * 8) * 2;
        LDSM_X4(qfh[kk], addr);
        LDSM_X4(qfl[kk], addr + AT_TILE);
    }

    float O[8][4];
#pragma unroll
    for (int j = 0; j < 8; j++)
#pragma unroll
        for (int r = 0; r < 4; r++) O[j][r] = 0.f;
    float m0 = -1e30f, m1 = -1e30f, l0 = 0.f, l1 = 0.f;

    for (int kt = 0; kt <= qt; kt++) {
        if (kt < qt) {
            attn_load_kv(sb + 2 * AT_TILE + ((kt + 1) & 1) * AT_STAGE, tid, kh, kl, vh, vl, kvoff, kt + 1);
            CP_COMMIT();
        }
        uint32_t kb = sb + 2 * AT_TILE + (kt & 1) * AT_STAGE;
        // ---- S = Q K^T ----
        float c[8][4];
#pragma unroll
        for (int j = 0; j < 8; j++)
#pragma unroll
            for (int r = 0; r < 4; r++) c[j][r] = 0.f;
#pragma unroll
        for (int kk = 0; kk < 4; kk++) {
            uint32_t kbh[4][4], kbl[4][4];
#pragma unroll
            for (int j2 = 0; j2 < 4; j2++) {
                uint32_t addr = kb + (j2 * 16 + lr + (lt >> 1) * 8) * AT_ROWB + (kk * 16 + (lt & 1) * 8) * 2;
                LDSM_X4(kbh[j2], addr);
                LDSM_X4(kbl[j2], addr + AT_TILE);
            }
#pragma unroll
            for (int j = 0; j < 8; j++) {
                uint32_t bh0 = kbh[j >> 1][(j & 1) * 2], bh1 = kbh[j >> 1][(j & 1) * 2 + 1];
                uint32_t bl0 = kbl[j >> 1][(j & 1) * 2], bl1 = kbl[j >> 1][(j & 1) * 2 + 1];
                MMA_BF16(c[j], qfh[kk], bh0, bh1);
                MMA_BF16(c[j], qfh[kk], bl0, bl1);
                MMA_BF16(c[j], qfl[kk], bh0, bh1);
            }
        }
        // ---- mask (diagonal tile only) ----
        if (kt == qt) {
            int r0 = w * 16 + (lane >> 2), r1 = r0 + 8;
#pragma unroll
            for (int j = 0; j < 8; j++) {
                int col = j * 8 + (lane & 3) * 2;
                if (col     > r0) c[j][0] = -1e30f;
                if (col + 1 > r0) c[j][1] = -1e30f;
                if (col     > r1) c[j][2] = -1e30f;
                if (col + 1 > r1) c[j][3] = -1e30f;
            }
        }
        // ---- online softmax ----
        float mx0 = -1e30f, mx1 = -1e30f;
#pragma unroll
        for (int j = 0; j < 8; j++) {
            mx0 = fmaxf(mx0, fmaxf(c[j][0], c[j][1]));
            mx1 = fmaxf(mx1, fmaxf(c[j][2], c[j][3]));
        }
        mx0 *= 0.125f; mx1 *= 0.125f;
        mx0 = fmaxf(mx0, __shfl_xor_sync(0xffffffffu, mx0, 1));
        mx0 = fmaxf(mx0, __shfl_xor_sync(0xffffffffu, mx0, 2));
        mx1 = fmaxf(mx1, __shfl_xor_sync(0xffffffffu, mx1, 1));
        mx1 = fmaxf(mx1, __shfl_xor_sync(0xffffffffu, mx1, 2));
        float m0n = fmaxf(m0, mx0), m1n = fmaxf(m1, mx1);
        float cr0 = __expf(m0 - m0n), cr1 = __expf(m1 - m1n);
        float s0 = 0.f, s1 = 0.f;
#pragma unroll
        for (int j = 0; j < 8; j++) {
            c[j][0] = __expf(fmaf(c[j][0], 0.125f, -m0n)); s0 += c[j][0];
            c[j][1] = __expf(fmaf(c[j][1], 0.125f, -m0n)); s0 += c[j][1];
            c[j][2] = __expf(fmaf(c[j][2], 0.125f, -m1n)); s1 += c[j][2];
            c[j][3] = __expf(fmaf(c[j][3], 0.125f, -m1n)); s1 += c[j][3];
        }
        s0 += __shfl_xor_sync(0xffffffffu, s0, 1);
        s0 += __shfl_xor_sync(0xffffffffu, s0, 2);
        s1 += __shfl_xor_sync(0xffffffffu, s1, 1);
        s1 += __shfl_xor_sync(0xffffffffu, s1, 2);
        l0 = l0 * cr0 + s0; l1 = l1 * cr1 + s1;
        m0 = m0n; m1 = m1n;
#pragma unroll
        for (int j = 0; j < 8; j++) {
            O[j][0] *= cr0; O[j][1] *= cr0;
            O[j][2] *= cr1; O[j][3] *= cr1;
        }
        // ---- O += P V ----
#pragma unroll
        for (int kt2 = 0; kt2 < 4; kt2++) {
            uint32_t pah[4], pal[4];
            split2(c[2*kt2][0],   c[2*kt2][1],   pah[0], pal[0]);
            split2(c[2*kt2][2],   c[2*kt2][3],   pah[1], pal[1]);
            split2(c[2*kt2+1][0], c[2*kt2+1][1], pah[2], pal[2]);
            split2(c[2*kt2+1][2], c[2*kt2+1][3], pah[3], pal[3]);
#pragma unroll
            for (int jd = 0; jd < 4; jd++) {
                uint32_t vbh[4], vbl[4];
                uint32_t addr = kb + 2 * AT_TILE + (kt2 * 16 + (lt & 1) * 8 + lr) * AT_ROWB + (jd * 16 + (lt >> 1) * 8) * 2;
                LDSM_X4_T(vbh, addr);
                LDSM_X4_T(vbl, addr + AT_TILE);
#pragma unroll
                for (int js = 0; js < 2; js++) {
                    int j = jd * 2 + js;
                    MMA_BF16(O[j], pah, vbh[js*2], vbh[js*2+1]);
                    MMA_BF16(O[j], pah, vbl[js*2], vbl[js*2+1]);
                    MMA_BF16(O[j], pal, vbh[js*2], vbh[js*2+1]);
                }
            }
        }
        if (kt < qt) CP_WAIT0();
        __syncthreads();
    }
    // ---- epilogue: write y split bf16, token-major ----
    float i0 = 1.f / l0, i1 = 1.f / l1;
    size_t rA = (size_t)(b * 2048 + qt * 64 + w * 16 + (lane >> 2));
    size_t rB = rA + 8;
    int colb = h * 64 + (lane & 3) * 2;
#pragma unroll
    for (int j = 0; j < 8; j++) {
        uint32_t hh, ll;
        int col = colb + j * 8;
        split2(O[j][0] * i0, O[j][1] * i0, hh, ll);
        *(uint32_t*)(yh + rA * 1024 + col) = hh;
        *(uint32_t*)(yl + rA * 1024 + col) = ll;
        split2(O[j][2] * i1, O[j][3] * i1, hh, ll);
        *(uint32_t*)(yh + rB * 1024 + col) = hh;
        *(uint32_t*)(yl + rB * 1024 + col) = ll;
    }
}

// ---------------- block-diagonal 64x64 GEMM (roll+transpose, split-out, relu-in) ----------------
__global__ __launch_bounds__(256) void blockdiag_kernel(
    const float* __restrict__ X, const float* __restrict__ Wall, float* __restrict__ O,
    __nv_bfloat16* __restrict__ OH, __nv_bfloat16* __restrict__ OL,
    int nb, const int* __restrict__ selp,
    int perm_out, int accum, const float* __restrict__ coefp, int relu_in)
{
    int F = nb * 64;
    int sel = *selp;
    int g = blockIdx.x;
    int n0 = blockIdx.y * 64;
    const float* W = Wall + (size_t)sel * F * 64 + (size_t)g * 64 * 64;
    __shared__ __align__(16) float XsT[64][68];
    __shared__ __align__(16) float Ws[64][68];
    int tid = threadIdx.x;
#pragma unroll
    for (int r = 0; r < 4; r++) {
        int f = tid + 256 * r;
        int row = f >> 4;
        int c4 = (f & 15) << 2;
        float4 xv = *(const float4*)(X + (size_t)(n0 + row) * F + g * 64 + c4);
        if (relu_in) {
            xv.x = fmaxf(xv.x, 0.f); xv.x *= xv.x;
            xv.y = fmaxf(xv.y, 0.f); xv.y *= xv.y;
            xv.z = fmaxf(xv.z, 0.f); xv.z *= xv.z;
            xv.w = fmaxf(xv.w, 0.f); xv.w *= xv.w;
        }
        XsT[c4+0][row] = xv.x; XsT[c4+1][row] = xv.y;
        XsT[c4+2][row] = xv.z; XsT[c4+3][row] = xv.w;
        float4 wv = *(const float4*)(W + row * 64 + c4);
        *(float4*)&Ws[row][c4] = wv;
    }
    __syncthreads();
    int tx = tid & 15, ty = tid >> 4;
    float acc[4][4];
#pragma unroll
    for (int i = 0; i < 4; i++)
#pragma unroll
        for (int j = 0; j < 4; j++) acc[i][j] = 0.f;
#pragma unroll
    for (int c = 0; c < 64; c++) {
        float a[4], bb[4];
        *(float4*)a = *(const float4*)&XsT[c][ty*4];
        *(float4*)bb = *(const float4*)&Ws[c][tx*4];
#pragma unroll
        for (int i = 0; i < 4; i++)
#pragma unroll
            for (int j = 0; j < 4; j++) acc[i][j] = fmaf(a[i], bb[j], acc[i][j]);
    }
    float alpha = coefp ? *coefp : 1.f;
    int gout = g;
    if (perm_out) {
        gout = g + (sel % nb);
        if (gout >= nb) gout -= nb;
    }
#pragma unroll
    for (int i = 0; i < 4; i++) {
        size_t nrow = (size_t)(n0 + ty * 4 + i);
#pragma unroll
        for (int j = 0; j < 4; j++) {
            int d = tx * 4 + j;
            size_t idx = perm_out ? nrow * F + (size_t)d * nb + gout
                                  : nrow * F + (size_t)g * 64 + d;
            float vv = alpha * acc[i][j];
            if (OH) {
                __nv_bfloat16 hb = __float2bfloat16_rn(vv);
                __nv_bfloat16 lb = __float2bfloat16_rn(vv - __bfloat162float(hb));
                OH[idx] = hb; OL[idx] = lb;
            } else {
                if (accum) O[idx] += vv; else O[idx] = vv;
            }
        }
    }
}

// ---------------- elementwise add ----------------
__global__ void add_kernel(const float* __restrict__ a, const float* __restrict__ b,
                           float* __restrict__ o, int n)
{
    int i = blockIdx.x * blockDim.x + threadIdx.x;
    if (i < n) o[i] = a[i] + b[i];
}

// ---------------- top-2 router ----------------
__global__ void router_kernel(const float* __restrict__ fcl, const float* __restrict__ pjl,
                              int* __restrict__ sel, float* __restrict__ coef)
{
    if (threadIdx.x == 0 && blockIdx.x == 0) {
#pragma unroll
        for (int s = 0; s < 2; s++) {
            const float* L = s ? pjl : fcl;
            int i1 = 0; float v1 = L[0];
            for (int i = 1; i < 8; i++) if (L[i] > v1) { v1 = L[i]; i1 = i; }
            int i2 = -1; float v2 = -1e30f;
            for (int i = 0; i < 8; i++) if (i != i1 && L[i] > v2) { v2 = L[i]; i2 = i; }
            float e = expf(v2 - v1);
            float z = 1.f + e;
            sel[s*2+0] = i1; sel[s*2+1] = i2;
            coef[s*2+0] = 1.f / z; coef[s*2+1] = e / z;
        }
    }
}

// ---------------- host orchestration ----------------
extern "C" void kernel_launch(void* const* d_in, const int* in_sizes, int n_in,
                              void* d_out, int out_size)
{
    (void)in_sizes; (void)n_in; (void)out_size;
    const float* x      = (const float*)d_in[0];
    const float* wq     = (const float*)d_in[1];
    const float* wk     = (const float*)d_in[2];
    const float* wv     = (const float*)d_in[3];
    const float* wo     = (const float*)d_in[4];
    const float* qg     = (const float*)d_in[5];
    const float* kg     = (const float*)d_in[6];
    const float* fc_s1  = (const float*)d_in[7];
    const float* fc_s2  = (const float*)d_in[8];
    const float* fc_mix = (const float*)d_in[9];
    const float* fc_lg  = (const float*)d_in[10];
    const float* pj_s1  = (const float*)d_in[11];
    const float* pj_s2  = (const float*)d_in[12];
    const float* pj_mix = (const float*)d_in[13];
    const float* pj_lg  = (const float*)d_in[14];

    float *xn, *qkv, *x2, *t1, *tk, *ac, *pa, *coef;
    int* sel;
    __nv_bfloat16 *ah, *al, *wh, *wl, *qh, *ql, *kh, *kl, *vh, *vl, *yh, *yl;
    cudaGetSymbolAddress((void**)&xn,  g_xn);
    cudaGetSymbolAddress((void**)&qkv, g_qkv);
    cudaGetSymbolAddress((void**)&x2,  g_x2);
    cudaGetSymbolAddress((void**)&t1,  g_t1);
    cudaGetSymbolAddress((void**)&tk,  g_tk);
    cudaGetSymbolAddress((void**)&ac,  g_ac);
    cudaGetSymbolAddress((void**)&pa,  g_pa);
    cudaGetSymbolAddress((void**)&sel,  g_sel);
    cudaGetSymbolAddress((void**)&coef, g_coef);
    cudaGetSymbolAddress((void**)&ah, g_ah);
    cudaGetSymbolAddress((void**)&al, g_al);
    cudaGetSymbolAddress((void**)&wh, g_wh);
    cudaGetSymbolAddress((void**)&wl, g_wl);
    cudaGetSymbolAddress((void**)&qh, g_qh);
    cudaGetSymbolAddress((void**)&ql, g_ql);
    cudaGetSymbolAddress((void**)&kh, g_kh);
    cudaGetSymbolAddress((void**)&kl, g_kl);
    cudaGetSymbolAddress((void**)&vh, g_vh);
    cudaGetSymbolAddress((void**)&vl, g_vl);
    cudaGetSymbolAddress((void**)&yh, g_yh);
    cudaGetSymbolAddress((void**)&yl, g_yl);

    cudaFuncSetAttribute(gemm_bf16x3, cudaFuncAttributeMaxDynamicSharedMemorySize, GEMM_SMEM);
    cudaFuncSetAttribute(attn_mma_kernel, cudaFuncAttributeMaxDynamicSharedMemorySize, ATTN_SMEM);

    // x1 = rms_norm(x) -> split bf16 directly
    rmsnorm_split_kernel<<<4096, 256>>>(x, ah, al);

    // packed QKV weights split, one GEMM (N = 1536)
    split_kernel<<<512, 256>>>(wq, wh, wl, 1048576, nullptr, 0);
    split_kernel<<<128, 256>>>(wk, wh + 1048576, wl + 1048576, 262144, nullptr, 0);
    split_kernel<<<128, 256>>>(wv, wh + 1310720, wl + 1310720, 262144, nullptr, 0);
    gemm_bf16x3<<<dim3(12, 32), 256, GEMM_SMEM>>>(ah, al, wh, wl, qkv, nullptr, 1536, 1024);

    // per-head rmsnorm*gain + rope, v conversion; split head-major outputs
    qkvprep_kernel<<<12288, 256>>>(qkv, qh, ql, kh, kl, vh, vl, qg, kg);

    // tensor-core flash attention -> y split bf16 (token-major)
    attn_mma_kernel<<<dim3(32, 16, 2), 128, ATTN_SMEM>>>(qh, ql, kh, kl, vh, vl, yh, yl);

    // x2 = x + y @ wo^T
    split_kernel<<<512, 256>>>(wo, wh, wl, 1048576, nullptr, 0);
    gemm_bf16x3<<<dim3(8, 32), 256, GEMM_SMEM>>>(yh, yl, wh, wl, x2, x, 1024, 1024);

    // h = rms_norm(x2)
    rmsnorm_kernel<<<4096, 256>>>(x2, xn);
    router_kernel<<<1, 32>>>(fc_lg, pj_lg, sel, coef);

    // fc bank: DIM -> HID, two experts accumulated into ac
    for (int r = 0; r < 2; r++) {
        blockdiag_kernel<<<dim3(16, 64), 256>>>(xn, fc_s1, nullptr, ah, al, 16, sel + r, 1, 0, nullptr, 0);
        split_kernel<<<2048, 256>>>(fc_mix, wh, wl, 4194304, sel + r, (size_t)4194304);
        gemm_bf16x3<<<dim3(32, 32), 256, GEMM_SMEM>>>(ah, al, wh, wl, tk, nullptr, 4096, 1024);
        blockdiag_kernel<<<dim3(64, 64), 256>>>(tk, fc_s2, ac, nullptr, nullptr, 64, sel + r, 0, r, coef + r, 0);
    }
    // pj bank: HID -> DIM (relu^2 fused into load), two experts into pa
    for (int r = 0; r < 2; r++) {
        blockdiag_kernel<<<dim3(64, 64), 256>>>(ac, pj_s1, nullptr, ah, al, 64, sel + 2 + r, 1, 0, nullptr, 1);
        split_kernel<<<2048, 256>>>(pj_mix, wh, wl, 4194304, sel + 2 + r, (size_t)4194304);
        gemm_bf16x3<<<dim3(8, 32), 256, GEMM_SMEM>>>(ah, al, wh, wl, t1, nullptr, 1024, 4096);
        blockdiag_kernel<<<dim3(16, 64), 256>>>(t1, pj_s2, pa, nullptr, nullptr, 16, sel + 2 + r, 0, r, coef + 2 + r, 0);
    }
    // out = x2 + pj_out
    add_kernel<<<16384, 256>>>(x2, pa, (float*)d_out, 4194304);
}

// round 5
// speedup vs baseline: 2.8344x; 1.3110x over previous
#include <cuda_runtime.h>
#include <cuda_bf16.h>
#include <math.h>
#include <stdint.h>

// ---------------- static device scratch ----------------
static __device__ float g_xn [4096*1024];
static __device__ float g_qkv[4096*1536];
static __device__ float g_x2 [4096*1024];
static __device__ float g_t1a[4096*1024];
static __device__ float g_t1b[4096*1024];
static __device__ float g_tk0[16777216];
static __device__ float g_tk1[16777216];
static __device__ int   g_sel[4];
static __device__ float g_coef[4];
static __device__ __nv_bfloat16 g_ah[16777216];
static __device__ __nv_bfloat16 g_al[16777216];
static __device__ __nv_bfloat16 g_bh[16777216];
static __device__ __nv_bfloat16 g_bl[16777216];
static __device__ __nv_bfloat16 g_wh[4194304];
static __device__ __nv_bfloat16 g_wl[4194304];
static __device__ __nv_bfloat16 g_qh[4194304];
static __device__ __nv_bfloat16 g_ql[4194304];
static __device__ __nv_bfloat16 g_kh[1048576];
static __device__ __nv_bfloat16 g_kl[1048576];
static __device__ __nv_bfloat16 g_vh[1048576];
static __device__ __nv_bfloat16 g_vl[1048576];
static __device__ __nv_bfloat16 g_yh[4194304];
static __device__ __nv_bfloat16 g_yl[4194304];

// ---------------- PTX helpers ----------------
__device__ __forceinline__ uint32_t smem_u32(const void* p) {
    uint32_t a;
    asm("{ .reg .u64 t; cvta.to.shared.u64 t, %1; cvt.u32.u64 %0, t; }" : "=r"(a) : "l"(p));
    return a;
}
#define CP_ASYNC16(dst, src) \
    asm volatile("cp.async.cg.shared.global [%0], [%1], 16;" :: "r"(dst), "l"(src))
#define CP_COMMIT() asm volatile("cp.async.commit_group;" ::: "memory")
#define CP_WAIT2()  asm volatile("cp.async.wait_group 2;" ::: "memory")
#define CP_WAIT0()  asm volatile("cp.async.wait_group 0;" ::: "memory")

#define LDSM_X4(r, addr) \
    asm volatile("ldmatrix.sync.aligned.m8n8.x4.shared.b16 {%0,%1,%2,%3}, [%4];" \
        : "=r"((r)[0]), "=r"((r)[1]), "=r"((r)[2]), "=r"((r)[3]) : "r"(addr))
#define LDSM_X4_T(r, addr) \
    asm volatile("ldmatrix.sync.aligned.m8n8.x4.trans.shared.b16 {%0,%1,%2,%3}, [%4];" \
        : "=r"((r)[0]), "=r"((r)[1]), "=r"((r)[2]), "=r"((r)[3]) : "r"(addr))

#define MMA_BF16(d, a, b0, b1) \
    asm volatile("mma.sync.aligned.m16n8k16.row.col.f32.bf16.bf16.f32 " \
        "{%0,%1,%2,%3}, {%4,%5,%6,%7}, {%8,%9}, {%0,%1,%2,%3};" \
        : "+f"((d)[0]), "+f"((d)[1]), "+f"((d)[2]), "+f"((d)[3]) \
        : "r"((a)[0]), "r"((a)[1]), "r"((a)[2]), "r"((a)[3]), "r"(b0), "r"(b1))

__device__ __forceinline__ void split2(float v0, float v1, uint32_t& h, uint32_t& l) {
    __nv_bfloat16 h0 = __float2bfloat16_rn(v0), h1 = __float2bfloat16_rn(v1);
    float r0 = v0 - __bfloat162float(h0), r1 = v1 - __bfloat162float(h1);
    __nv_bfloat16 l0 = __float2bfloat16_rn(r0), l1 = __float2bfloat16_rn(r1);
    h = (uint32_t)*(uint16_t*)&h0 | ((uint32_t)*(uint16_t*)&h1 << 16);
    l = (uint32_t)*(uint16_t*)&l0 | ((uint32_t)*(uint16_t*)&l1 << 16);
}

// ---------------- plain fp32 -> (hi,lo) bf16 split ----------------
__global__ void split_kernel(const float* __restrict__ src, __nv_bfloat16* __restrict__ hi,
                             __nv_bfloat16* __restrict__ lo, int n)
{
    int i = (blockIdx.x * blockDim.x + threadIdx.x) * 8;
    if (i >= n) return;
    float4 a = *(const float4*)(src + i);
    float4 b = *(const float4*)(src + i + 4);
    uint32_t h0,l0,h1,l1,h2,l2,h3,l3;
    split2(a.x, a.y, h0, l0); split2(a.z, a.w, h1, l1);
    split2(b.x, b.y, h2, l2); split2(b.z, b.w, h3, l3);
    *(uint4*)(hi + i) = make_uint4(h0, h1, h2, h3);
    *(uint4*)(lo + i) = make_uint4(l0, l1, l2, l3);
}

// ---------------- permuting weight split: Wp[o,kpre] = W[o, d*nb + (g+s)%nb] ----------------
// kpre = g*64 + d. Moves the bank-roll permutation into the weight K-axis.
__global__ void split_perm_kernel(const float* __restrict__ Wall,
                                  __nv_bfloat16* __restrict__ hi, __nv_bfloat16* __restrict__ lo,
                                  int rowlen, int nb, int rpb,
                                  const int* __restrict__ selp, size_t stride)
{
    extern __shared__ float srow[];
    int sel = *selp;
    int s = sel & (nb - 1);
    const float* src = Wall + (size_t)sel * stride + (size_t)blockIdx.x * rpb * rowlen;
    int tid = threadIdx.x;
    int total = rpb * rowlen;
    for (int i = tid * 4; i < total; i += blockDim.x * 4) {
        float4 v = *(const float4*)(src + i);
        int p = i + (i >> 5);
        srow[p] = v.x; srow[p+1] = v.y; srow[p+2] = v.z; srow[p+3] = v.w;
    }
    __syncthreads();
    size_t obase = (size_t)blockIdx.x * rpb * rowlen;
    for (int idx = tid * 2; idx < total; idx += blockDim.x * 2) {
        int r = idx / rowlen, kpre = idx - r * rowlen;
        int g = kpre >> 6, d = kpre & 63;
        int gs = g + s; if (gs >= nb) gs -= nb;
        int a0 = r * rowlen + d * nb + gs;
        int a1 = a0 + nb;                 // (d+1)*nb + gs
        float v0 = srow[a0 + (a0 >> 5)];
        float v1 = srow[a1 + (a1 >> 5)];
        uint32_t h, l;
        split2(v0, v1, h, l);
        *(uint32_t*)(hi + obase + idx) = h;
        *(uint32_t*)(lo + obase + idx) = l;
    }
}

// ---------------- HMMA bf16x3 GEMM, 4-stage pipeline, 1 barrier/iter ----------------
#define TSTRIDE 80
#define BUF_BYTES (128 * TSTRIDE)
#define STAGE_BYTES (4 * BUF_BYTES)        // 40960
#define GEMM_SMEM (4 * STAGE_BYTES)        // 163840

__device__ __forceinline__ void gemm_load_stage(
    uint32_t smbase, int kt, int NT, int K, int tid,
    const __nv_bfloat16* s0, const __nv_bfloat16* s1,
    const __nv_bfloat16* s2, const __nv_bfloat16* s3)
{
    if (kt < NT) {
        uint32_t sb = smbase + (kt & 3) * STAGE_BYTES;
        int k0 = kt * 32;
        const __nv_bfloat16* srcs[4] = {s0, s1, s2, s3};
#pragma unroll
        for (int t = 0; t < 8; t++) {
            int c = tid + 256 * t;
            int buf = c >> 9, cc = c & 511;
            int row = cc >> 2, kc = cc & 3;
            uint32_t dst = sb + buf * BUF_BYTES + row * TSTRIDE + kc * 16;
            const __nv_bfloat16* src = srcs[buf] + (size_t)row * K + k0 + kc * 8;
            CP_ASYNC16(dst, src);
        }
    }
    CP_COMMIT();
}

__global__ __launch_bounds__(256) void gemm_bf16x3(
    const __nv_bfloat16* __restrict__ Ah, const __nv_bfloat16* __restrict__ Al,
    const __nv_bfloat16* __restrict__ Wh, const __nv_bfloat16* __restrict__ Wl,
    float* __restrict__ C, const float* __restrict__ res, int N, int K)
{
    extern __shared__ char smem[];
    uint32_t smbase = smem_u32(smem);
    int tid = threadIdx.x, wid = tid >> 5, lane = tid & 31;
    int m0 = blockIdx.y * 128, n0 = blockIdx.x * 128;
    int wm = wid >> 1, wn = wid & 1;

    const __nv_bfloat16* s0 = Ah + (size_t)m0 * K;
    const __nv_bfloat16* s1 = Al + (size_t)m0 * K;
    const __nv_bfloat16* s2 = Wh + (size_t)n0 * K;
    const __nv_bfloat16* s3 = Wl + (size_t)n0 * K;

    float acc[2][8][4];
#pragma unroll
    for (int i = 0; i < 2; i++)
#pragma unroll
        for (int j = 0; j < 8; j++)
#pragma unroll
            for (int r = 0; r < 4; r++) acc[i][j][r] = 0.f;

    int NT = K >> 5;
    gemm_load_stage(smbase, 0, NT, K, tid, s0, s1, s2, s3);
    gemm_load_stage(smbase, 1, NT, K, tid, s0, s1, s2, s3);
    gemm_load_stage(smbase, 2, NT, K, tid, s0, s1, s2, s3);

    int lt = lane >> 3, lr = lane & 7;
    for (int kt = 0; kt < NT; kt++) {
        CP_WAIT2();
        __syncthreads();
        gemm_load_stage(smbase, kt + 3, NT, K, tid, s0, s1, s2, s3);
        uint32_t sb = smbase + (kt & 3) * STAGE_BYTES;
#pragma unroll
        for (int kk = 0; kk < 2; kk++) {
            uint32_t a_hi[2][4], a_lo[2][4];
#pragma unroll
            for (int i = 0; i < 2; i++) {
                int row = wm * 32 + i * 16 + lr + (lt & 1) * 8;
                int kofs = kk * 16 + (lt >> 1) * 8;
                uint32_t addr = sb + row * TSTRIDE + kofs * 2;
                LDSM_X4(a_hi[i], addr);
                LDSM_X4(a_lo[i], addr + BUF_BYTES);
            }
            uint32_t b_hi[4][4], b_lo[4][4];
#pragma unroll
            for (int j = 0; j < 4; j++) {
                int row = wn * 64 + j * 16 + lr + (lt >> 1) * 8;
                int kofs = kk * 16 + (lt & 1) * 8;
                uint32_t addr = sb + 2 * BUF_BYTES + row * TSTRIDE + kofs * 2;
                LDSM_X4(b_hi[j], addr);
                LDSM_X4(b_lo[j], addr + BUF_BYTES);
            }
#pragma unroll
            for (int i = 0; i < 2; i++)
#pragma unroll
                for (int j = 0; j < 8; j++) {
                    uint32_t bh0 = b_hi[j >> 1][(j & 1) * 2], bh1 = b_hi[j >> 1][(j & 1) * 2 + 1];
                    uint32_t bl0 = b_lo[j >> 1][(j & 1) * 2], bl1 = b_lo[j >> 1][(j & 1) * 2 + 1];
                    MMA_BF16(acc[i][j], a_hi[i], bh0, bh1);
                    MMA_BF16(acc[i][j], a_hi[i], bl0, bl1);
                    MMA_BF16(acc[i][j], a_lo[i], bh0, bh1);
                }
        }
    }
    CP_WAIT0();

    int rbase = m0 + wm * 32 + (lane >> 2);
    int cbase = n0 + wn * 64 + (lane & 3) * 2;
#pragma unroll
    for (int i = 0; i < 2; i++) {
#pragma unroll
        for (int half = 0; half < 2; half++) {
            size_t row = (size_t)(rbase + i * 16 + half * 8);
#pragma unroll
            for (int j = 0; j < 8; j++) {
                size_t idx = row * (size_t)N + cbase + j * 8;
                float v0 = acc[i][j][half * 2 + 0];
                float v1 = acc[i][j][half * 2 + 1];
                if (res) { v0 += res[idx]; v1 += res[idx + 1]; }
                *(float2*)(C + idx) = make_float2(v0, v1);
            }
        }
    }
}

// ---------------- RMSNorm (fp32 out) ----------------
__global__ void rmsnorm_kernel(const float* __restrict__ x, float* __restrict__ o)
{
    int n = blockIdx.x;
    int tid = threadIdx.x;
    const float4* xr = (const float4*)(x + (size_t)n * 1024);
    float4 v = xr[tid];
    float s = v.x*v.x + v.y*v.y + v.z*v.z + v.w*v.w;
#pragma unroll
    for (int off = 16; off > 0; off >>= 1) s += __shfl_xor_sync(0xffffffffu, s, off);
    __shared__ float red[8];
    if ((tid & 31) == 0) red[tid >> 5] = s;
    __syncthreads();
    float tot = 0.f;
#pragma unroll
    for (int i = 0; i < 8; i++) tot += red[i];
    float r = rsqrtf(tot * (1.f/1024.f) + 1e-6f);
    v.x *= r; v.y *= r; v.z *= r; v.w *= r;
    ((float4*)(o + (size_t)n * 1024))[tid] = v;
}

// ---------------- RMSNorm with bf16 hi/lo split output ----------------
__global__ void rmsnorm_split_kernel(const float* __restrict__ x,
                                     __nv_bfloat16* __restrict__ hi,
                                     __nv_bfloat16* __restrict__ lo)
{
    int n = blockIdx.x;
    int tid = threadIdx.x;
    const float4* xr = (const float4*)(x + (size_t)n * 1024);
    float4 v = xr[tid];
    float s = v.x*v.x + v.y*v.y + v.z*v.z + v.w*v.w;
#pragma unroll
    for (int off = 16; off > 0; off >>= 1) s += __shfl_xor_sync(0xffffffffu, s, off);
    __shared__ float red[8];
    if ((tid & 31) == 0) red[tid >> 5] = s;
    __syncthreads();
    float tot = 0.f;
#pragma unroll
    for (int i = 0; i < 8; i++) tot += red[i];
    float r = rsqrtf(tot * (1.f/1024.f) + 1e-6f);
    uint32_t h0,l0,h1,l1;
    split2(v.x*r, v.y*r, h0, l0);
    split2(v.z*r, v.w*r, h1, l1);
    size_t base = (size_t)n * 1024 + tid * 4;
    *(uint2*)(hi + base) = make_uint2(h0, h1);
    *(uint2*)(lo + base) = make_uint2(l0, l1);
}

// ---------------- qkv prep (per-head rms*gain + rope; v passthrough) ----------------
__global__ void qkvprep_kernel(const float* __restrict__ qkv,
                               __nv_bfloat16* __restrict__ qh, __nv_bfloat16* __restrict__ ql,
                               __nv_bfloat16* __restrict__ kh, __nv_bfloat16* __restrict__ kl,
                               __nv_bfloat16* __restrict__ vh, __nv_bfloat16* __restrict__ vl,
                               const float* __restrict__ qg, const float* __restrict__ kg)
{
    int gt = blockIdx.x * blockDim.x + threadIdx.x;
    int w = gt >> 5, lane = gt & 31;
    if (w < 81920) {
        const float* src; float gain; int t; __nv_bfloat16 *dh, *dl; size_t dbase;
        if (w < 65536) {
            int n = w >> 4, h = w & 15;
            src = qkv + (size_t)n * 1536 + h * 64;
            gain = qg[h]; t = n & 2047;
            dbase = ((size_t)((n >> 11) * 16 + h) * 2048 + t) * 64;
            dh = qh; dl = ql;
        } else {
            int w2 = w - 65536;
            int n = w2 >> 2, h = w2 & 3;
            src = qkv + (size_t)n * 1536 + 1024 + h * 64;
            gain = kg[h]; t = n & 2047;
            dbase = ((size_t)((n >> 11) * 4 + h) * 2048 + t) * 64;
            dh = kh; dl = kl;
        }
        float v1 = src[lane], v2 = src[lane + 32];
        float s = v1*v1 + v2*v2;
#pragma unroll
        for (int off = 16; off > 0; off >>= 1) s += __shfl_xor_sync(0xffffffffu, s, off);
        float r = rsqrtf(s * (1.f/64.f) + 1e-6f) * gain;
        v1 *= r; v2 *= r;
        float freq = powf(10000.f, -(float)(2 * lane) / 64.f);
        float ang = (float)t * freq;
        float sn, cs;
        sincosf(ang, &sn, &cs);
        float o1 = v1 * cs + v2 * sn;
        float o2 = v2 * cs - v1 * sn;
        __nv_bfloat16 hb1 = __float2bfloat16_rn(o1);
        __nv_bfloat16 lb1 = __float2bfloat16_rn(o1 - __bfloat162float(hb1));
        __nv_bfloat16 hb2 = __float2bfloat16_rn(o2);
        __nv_bfloat16 lb2 = __float2bfloat16_rn(o2 - __bfloat162float(hb2));
        dh[dbase + lane] = hb1; dl[dbase + lane] = lb1;
        dh[dbase + lane + 32] = hb2; dl[dbase + lane + 32] = lb2;
    } else {
        int w2 = w - 81920;
        int n = w2 >> 2, h = w2 & 3;
        const float* src = qkv + (size_t)n * 1536 + 1280 + h * 64;
        int t = n & 2047;
        size_t dbase = ((size_t)((n >> 11) * 4 + h) * 2048 + t) * 64;
        float v1 = src[lane], v2 = src[lane + 32];
        __nv_bfloat16 hb1 = __float2bfloat16_rn(v1);
        __nv_bfloat16 lb1 = __float2bfloat16_rn(v1 - __bfloat162float(hb1));
        __nv_bfloat16 hb2 = __float2bfloat16_rn(v2);
        __nv_bfloat16 lb2 = __float2bfloat16_rn(v2 - __bfloat162float(hb2));
        vh[dbase + lane] = hb1; vl[dbase + lane] = lb1;
        vh[dbase + lane + 32] = hb2; vl[dbase + lane + 32] = lb2;
    }
}

// ---------------- tensor-core flash attention (bf16x3) ----------------
#define AT_ROWB 144
#define AT_TILE (64 * AT_ROWB)
#define AT_STAGE (4 * AT_TILE)
#define ATTN_SMEM (2 * AT_TILE + 2 * AT_STAGE)

__device__ __forceinline__ void attn_load_kv(
    uint32_t dstbase, int tid,
    const __nv_bfloat16* kh, const __nv_bfloat16* kl,
    const __nv_bfloat16* vh, const __nv_bfloat16* vl,
    size_t kvoff, int kt)
{
    const __nv_bfloat16* srcs[4] = {kh, kl, vh, vl};
#pragma unroll
    for (int t = 0; t < 16; t++) {
        int idx = tid + 128 * t;
        int buf = idx >> 9, cc = idx & 511, row = cc >> 3, ch = cc & 7;
        const __nv_bfloat16* src = srcs[buf] + kvoff + (size_t)(kt * 64 + row) * 64 + ch * 8;
        CP_ASYNC16(dstbase + buf * AT_TILE + row * AT_ROWB + ch * 16, src);
    }
}

__global__ __launch_bounds__(128) void attn_mma_kernel(
    const __nv_bfloat16* __restrict__ qh, const __nv_bfloat16* __restrict__ ql,
    const __nv_bfloat16* __restrict__ kh, const __nv_bfloat16* __restrict__ kl,
    const __nv_bfloat16* __restrict__ vh, const __nv_bfloat16* __restrict__ vl,
    __nv_bfloat16* __restrict__ yh, __nv_bfloat16* __restrict__ yl)
{
    extern __shared__ char smem[];
    uint32_t sb = smem_u32(smem);
    int qt = blockIdx.x, h = blockIdx.y, b = blockIdx.z;
    int tid = threadIdx.x, w = tid >> 5, lane = tid & 31;
    int lr = lane & 7, lt = lane >> 3;
    size_t qoff = ((size_t)(b * 16 + h) * 2048 + qt * 64) * 64;
    size_t kvoff = (size_t)(b * 4 + (h >> 2)) * 2048 * 64;

#pragma unroll
    for (int t = 0; t < 8; t++) {
        int idx = tid + 128 * t;
        int buf = idx >> 9, cc = idx & 511, row = cc >> 3, ch = cc & 7;
        const __nv_bfloat16* src = (buf ? ql : qh) + qoff + row * 64 + ch * 8;
        CP_ASYNC16(sb + buf * AT_TILE + row * AT_ROWB + ch * 16, src);
    }
    CP_COMMIT();
    attn_load_kv(sb + 2 * AT_TILE, tid, kh, kl, vh, vl, kvoff, 0);
    CP_COMMIT();
    CP_WAIT0();
    __syncthreads();

    uint32_t qfh[4][4], qfl[4][4];
#pragma unroll
    for (int kk = 0; kk < 4; kk++) {
        uint32_t addr = sb + (w * 16 + lr + (lt & 1) * 8) * AT_ROWB + (kk * 16 + (lt >> 1) * 8) * 2;
        LDSM_X4(qfh[kk], addr);
        LDSM_X4(qfl[kk], addr + AT_TILE);
    }

    float O[8][4];
#pragma unroll
    for (int j = 0; j < 8; j++)
#pragma unroll
        for (int r = 0; r < 4; r++) O[j][r] = 0.f;
    float m0 = -1e30f, m1 = -1e30f, l0 = 0.f, l1 = 0.f;

    for (int kt = 0; kt <= qt; kt++) {
        if (kt < qt) {
            attn_load_kv(sb + 2 * AT_TILE + ((kt + 1) & 1) * AT_STAGE, tid, kh, kl, vh, vl, kvoff, kt + 1);
            CP_COMMIT();
        }
        uint32_t kb = sb + 2 * AT_TILE + (kt & 1) * AT_STAGE;
        float c[8][4];
#pragma unroll
        for (int j = 0; j < 8; j++)
#pragma unroll
            for (int r = 0; r < 4; r++) c[j][r] = 0.f;
#pragma unroll
        for (int kk = 0; kk < 4; kk++) {
            uint32_t kbh[4][4], kbl[4][4];
#pragma unroll
            for (int j2 = 0; j2 < 4; j2++) {
                uint32_t addr = kb + (j2 * 16 + lr + (lt >> 1) * 8) * AT_ROWB + (kk * 16 + (lt & 1) * 8) * 2;
                LDSM_X4(kbh[j2], addr);
                LDSM_X4(kbl[j2], addr + AT_TILE);
            }
#pragma unroll
            for (int j = 0; j < 8; j++) {
                uint32_t bh0 = kbh[j >> 1][(j & 1) * 2], bh1 = kbh[j >> 1][(j & 1) * 2 + 1];
                uint32_t bl0 = kbl[j >> 1][(j & 1) * 2], bl1 = kbl[j >> 1][(j & 1) * 2 + 1];
                MMA_BF16(c[j], qfh[kk], bh0, bh1);
                MMA_BF16(c[j], qfh[kk], bl0, bl1);
                MMA_BF16(c[j], qfl[kk], bh0, bh1);
            }
        }
        if (kt == qt) {
            int r0 = w * 16 + (lane >> 2), r1 = r0 + 8;
#pragma unroll
            for (int j = 0; j < 8; j++) {
                int col = j * 8 + (lane & 3) * 2;
                if (col     > r0) c[j][0] = -1e30f;
                if (col + 1 > r0) c[j][1] = -1e30f;
                if (col     > r1) c[j][2] = -1e30f;
                if (col + 1 > r1) c[j][3] = -1e30f;
            }
        }
        float mx0 = -1e30f, mx1 = -1e30f;
#pragma unroll
        for (int j = 0; j < 8; j++) {
            mx0 = fmaxf(mx0, fmaxf(c[j][0], c[j][1]));
            mx1 = fmaxf(mx1, fmaxf(c[j][2], c[j][3]));
        }
        mx0 *= 0.125f; mx1 *= 0.125f;
        mx0 = fmaxf(mx0, __shfl_xor_sync(0xffffffffu, mx0, 1));
        mx0 = fmaxf(mx0, __shfl_xor_sync(0xffffffffu, mx0, 2));
        mx1 = fmaxf(mx1, __shfl_xor_sync(0xffffffffu, mx1, 1));
        mx1 = fmaxf(mx1, __shfl_xor_sync(0xffffffffu, mx1, 2));
        float m0n = fmaxf(m0, mx0), m1n = fmaxf(m1, mx1);
        float cr0 = __expf(m0 - m0n), cr1 = __expf(m1 - m1n);
        float s0 = 0.f, s1 = 0.f;
#pragma unroll
        for (int j = 0; j < 8; j++) {
            c[j][0] = __expf(fmaf(c[j][0], 0.125f, -m0n)); s0 += c[j][0];
            c[j][1] = __expf(fmaf(c[j][1], 0.125f, -m0n)); s0 += c[j][1];
            c[j][2] = __expf(fmaf(c[j][2], 0.125f, -m1n)); s1 += c[j][2];
            c[j][3] = __expf(fmaf(c[j][3], 0.125f, -m1n)); s1 += c[j][3];
        }
        s0 += __shfl_xor_sync(0xffffffffu, s0, 1);
        s0 += __shfl_xor_sync(0xffffffffu, s0, 2);
        s1 += __shfl_xor_sync(0xffffffffu, s1, 1);
        s1 += __shfl_xor_sync(0xffffffffu, s1, 2);
        l0 = l0 * cr0 + s0; l1 = l1 * cr1 + s1;
        m0 = m0n; m1 = m1n;
#pragma unroll
        for (int j = 0; j < 8; j++) {
            O[j][0] *= cr0; O[j][1] *= cr0;
            O[j][2] *= cr1; O[j][3] *= cr1;
        }
#pragma unroll
        for (int kt2 = 0; kt2 < 4; kt2++) {
            uint32_t pah[4], pal[4];
            split2(c[2*kt2][0],   c[2*kt2][1],   pah[0], pal[0]);
            split2(c[2*kt2][2],   c[2*kt2][3],   pah[1], pal[1]);
            split2(c[2*kt2+1][0], c[2*kt2+1][1], pah[2], pal[2]);
            split2(c[2*kt2+1][2], c[2*kt2+1][3], pah[3], pal[3]);
#pragma unroll
            for (int jd = 0; jd < 4; jd++) {
                uint32_t vbh[4], vbl[4];
                uint32_t addr = kb + 2 * AT_TILE + (kt2 * 16 + (lt & 1) * 8 + lr) * AT_ROWB + (jd * 16 + (lt >> 1) * 8) * 2;
                LDSM_X4_T(vbh, addr);
                LDSM_X4_T(vbl, addr + AT_TILE);
#pragma unroll
                for (int js = 0; js < 2; js++) {
                    int j = jd * 2 + js;
                    MMA_BF16(O[j], pah, vbh[js*2], vbh[js*2+1]);
                    MMA_BF16(O[j], pah, vbl[js*2], vbl[js*2+1]);
                    MMA_BF16(O[j], pal, vbh[js*2], vbh[js*2+1]);
                }
            }
        }
        if (kt < qt) CP_WAIT0();
        __syncthreads();
    }
    float i0 = 1.f / l0, i1 = 1.f / l1;
    size_t rA = (size_t)(b * 2048 + qt * 64 + w * 16 + (lane >> 2));
    size_t rB = rA + 8;
    int colb = h * 64 + (lane & 3) * 2;
#pragma unroll
    for (int j = 0; j < 8; j++) {
        uint32_t hh, ll;
        int col = colb + j * 8;
        split2(O[j][0] * i0, O[j][1] * i0, hh, ll);
        *(uint32_t*)(yh + rA * 1024 + col) = hh;
        *(uint32_t*)(yl + rA * 1024 + col) = ll;
        split2(O[j][2] * i1, O[j][3] * i1, hh, ll);
        *(uint32_t*)(yh + rB * 1024 + col) = hh;
        *(uint32_t*)(yl + rB * 1024 + col) = ll;
    }
}

// ---------------- shared tile helpers for dual blockdiag kernels ----------------
#define TP 68
__device__ __forceinline__ void load_tileT(float* dst, const float* src, size_t rstride, int tid) {
    // dst[c][row] = src[row*rstride + c], 64x64
#pragma unroll
    for (int r = 0; r < 4; r++) {
        int f = tid + 256 * r;
        int row = f >> 4, c4 = (f & 15) << 2;
        float4 v = *(const float4*)(src + (size_t)row * rstride + c4);
        dst[(c4+0)*TP + row] = v.x; dst[(c4+1)*TP + row] = v.y;
        dst[(c4+2)*TP + row] = v.z; dst[(c4+3)*TP + row] = v.w;
    }
}
__device__ __forceinline__ void load_tile(float* dst, const float* src, int tid) {
    // dst[c][d] = src[c*64 + d]
#pragma unroll
    for (int r = 0; r < 4; r++) {
        int f = tid + 256 * r;
        int row = f >> 4, c4 = (f & 15) << 2;
        *(float4*)&dst[row*TP + c4] = *(const float4*)(src + row * 64 + c4);
    }
}
__device__ __forceinline__ void mm64(const float* XT, const float* W, float acc[4][4], int tx, int ty) {
#pragma unroll
    for (int c = 0; c < 64; c++) {
        float a[4], bb[4];
        *(float4*)a  = *(const float4*)&XT[c*TP + ty*4];
        *(float4*)bb = *(const float4*)&W [c*TP + tx*4];
#pragma unroll
        for (int i = 0; i < 4; i++)
#pragma unroll
            for (int j = 0; j < 4; j++) acc[i][j] = fmaf(a[i], bb[j], acc[i][j]);
    }
}

// ---------------- fc_s1 dual: two expert blockdiags, split bf16 out (pre-perm layout) ----------------
__global__ __launch_bounds__(256) void fcs1_dual_kernel(
    const float* __restrict__ X, const float* __restrict__ Wall,
    __nv_bfloat16* __restrict__ AH, __nv_bfloat16* __restrict__ AL,
    __nv_bfloat16* __restrict__ BH, __nv_bfloat16* __restrict__ BL,
    const int* __restrict__ sel)
{
    extern __shared__ float sm[];
    float* XT = sm;            // 64*68
    float* W0 = sm + 4352;
    float* W1 = sm + 8704;
    int g = blockIdx.x, n0 = blockIdx.y * 64, tid = threadIdx.x;
    load_tileT(XT, X + (size_t)n0 * 1024 + g * 64, 1024, tid);
    load_tile(W0, Wall + (size_t)sel[0] * 65536 + g * 4096, tid);
    load_tile(W1, Wall + (size_t)sel[1] * 65536 + g * 4096, tid);
    __syncthreads();
    int tx = tid & 15, ty = tid >> 4;
    float a0[4][4] = {}, a1[4][4] = {};
    mm64(XT, W0, a0, tx, ty);
    mm64(XT, W1, a1, tx, ty);
#pragma unroll
    for (int i = 0; i < 4; i++) {
        size_t base = (size_t)(n0 + ty*4 + i) * 1024 + g * 64 + tx * 4;
        uint32_t h, l;
        split2(a0[i][0], a0[i][1], h, l);
        *(uint32_t*)(AH + base) = h; *(uint32_t*)(AL + base) = l;
        split2(a0[i][2], a0[i][3], h, l);
        *(uint32_t*)(AH + base + 2) = h; *(uint32_t*)(AL + base + 2) = l;
        split2(a1[i][0], a1[i][1], h, l);
        *(uint32_t*)(BH + base) = h; *(uint32_t*)(BL + base) = l;
        split2(a1[i][2], a1[i][3], h, l);
        *(uint32_t*)(BH + base + 2) = h; *(uint32_t*)(BL + base + 2) = l;
    }
}

// ---------------- mid dual: fc_s2 combine + relu^2 + pj_s1 dual, split bf16 out ----------------
__global__ __launch_bounds__(256) void mid_dual_kernel(
    const float* __restrict__ T0, const float* __restrict__ T1,
    const float* __restrict__ S2all, const float* __restrict__ P1all,
    __nv_bfloat16* __restrict__ AH, __nv_bfloat16* __restrict__ AL,
    __nv_bfloat16* __restrict__ BH, __nv_bfloat16* __restrict__ BL,
    const int* __restrict__ sel, const float* __restrict__ coef)
{
    extern __shared__ float sm[];
    float* A = sm;             // XsT0 then hT
    float* B = sm + 4352;      // XsT1
    float* C = sm + 8704;      // W0 then P0
    float* D = sm + 13056;     // W1 then P1
    int g = blockIdx.x, n0 = blockIdx.y * 64, tid = threadIdx.x;
    load_tileT(A, T0 + (size_t)n0 * 4096 + g * 64, 4096, tid);
    load_tileT(B, T1 + (size_t)n0 * 4096 + g * 64, 4096, tid);
    load_tile(C, S2all + (size_t)sel[0] * 262144 + g * 4096, tid);
    load_tile(D, S2all + (size_t)sel[1] * 262144 + g * 4096, tid);
    __syncthreads();
    int tx = tid & 15, ty = tid >> 4;
    float a0[4][4] = {}, a1[4][4] = {};
    mm64(A, C, a0, tx, ty);
    mm64(B, D, a1, tx, ty);
    float c0 = coef[0], c1 = coef[1];
    float h[4][4];
#pragma unroll
    for (int i = 0; i < 4; i++)
#pragma unroll
        for (int j = 0; j < 4; j++) {
            float v = c0 * a0[i][j] + c1 * a1[i][j];
            v = fmaxf(v, 0.f);
            h[i][j] = v * v;
        }
    __syncthreads();
    // store h transposed into A; load P0/P1
#pragma unroll
    for (int i = 0; i < 4; i++)
#pragma unroll
        for (int j = 0; j < 4; j++)
            A[(tx*4 + j)*TP + ty*4 + i] = h[i][j];
    load_tile(C, P1all + (size_t)sel[2] * 262144 + g * 4096, tid);
    load_tile(D, P1all + (size_t)sel[3] * 262144 + g * 4096, tid);
    __syncthreads();
    float o0[4][4] = {}, o1[4][4] = {};
    mm64(A, C, o0, tx, ty);
    mm64(A, D, o1, tx, ty);
#pragma unroll
    for (int i = 0; i < 4; i++) {
        size_t base = (size_t)(n0 + ty*4 + i) * 4096 + g * 64 + tx * 4;
        uint32_t hh, ll;
        split2(o0[i][0], o0[i][1], hh, ll);
        *(uint32_t*)(AH + base) = hh; *(uint32_t*)(AL + base) = ll;
        split2(o0[i][2], o0[i][3], hh, ll);
        *(uint32_t*)(AH + base + 2) = hh; *(uint32_t*)(AL + base + 2) = ll;
        split2(o1[i][0], o1[i][1], hh, ll);
        *(uint32_t*)(BH + base) = hh; *(uint32_t*)(BL + base) = ll;
        split2(o1[i][2], o1[i][3], hh, ll);
        *(uint32_t*)(BH + base + 2) = hh; *(uint32_t*)(BL + base + 2) = ll;
    }
}

// ---------------- final dual: pj_s2 combine + residual -> d_out ----------------
__global__ __launch_bounds__(256) void final_dual_kernel(
    const float* __restrict__ T0, const float* __restrict__ T1,
    const float* __restrict__ S2all, const float* __restrict__ x2,
    float* __restrict__ out, const int* __restrict__ sel, const float* __restrict__ coef)
{
    extern __shared__ float sm[];
    float* A = sm;
    float* B = sm + 4352;
    float* C = sm + 8704;
    float* D = sm + 13056;
    int g = blockIdx.x, n0 = blockIdx.y * 64, tid = threadIdx.x;
    load_tileT(A, T0 + (size_t)n0 * 1024 + g * 64, 1024, tid);
    load_tileT(B, T1 + (size_t)n0 * 1024 + g * 64, 1024, tid);
    load_tile(C, S2all + (size_t)sel[2] * 65536 + g * 4096, tid);
    load_tile(D, S2all + (size_t)sel[3] * 65536 + g * 4096, tid);
    __syncthreads();
    int tx = tid & 15, ty = tid >> 4;
    float a0[4][4] = {}, a1[4][4] = {};
    mm64(A, C, a0, tx, ty);
    mm64(B, D, a1, tx, ty);
    float c2 = coef[2], c3 = coef[3];
#pragma unroll
    for (int i = 0; i < 4; i++) {
        size_t base = (size_t)(n0 + ty*4 + i) * 1024 + g * 64 + tx * 4;
        float4 r = *(const float4*)(x2 + base);
        r.x += c2 * a0[i][0] + c3 * a1[i][0];
        r.y += c2 * a0[i][1] + c3 * a1[i][1];
        r.z += c2 * a0[i][2] + c3 * a1[i][2];
        r.w += c2 * a0[i][3] + c3 * a1[i][3];
        *(float4*)(out + base) = r;
    }
}

// ---------------- top-2 router ----------------
__global__ void router_kernel(const float* __restrict__ fcl, const float* __restrict__ pjl,
                              int* __restrict__ sel, float* __restrict__ coef)
{
    if (threadIdx.x == 0 && blockIdx.x == 0) {
#pragma unroll
        for (int s = 0; s < 2; s++) {
            const float* L = s ? pjl : fcl;
            int i1 = 0; float v1 = L[0];
            for (int i = 1; i < 8; i++) if (L[i] > v1) { v1 = L[i]; i1 = i; }
            int i2 = -1; float v2 = -1e30f;
            for (int i = 0; i < 8; i++) if (i != i1 && L[i] > v2) { v2 = L[i]; i2 = i; }
            float e = expf(v2 - v1);
            float z = 1.f + e;
            sel[s*2+0] = i1; sel[s*2+1] = i2;
            coef[s*2+0] = 1.f / z; coef[s*2+1] = e / z;
        }
    }
}

// ---------------- host orchestration ----------------
#define DUAL3_SMEM (13056 * 4)
#define DUAL4_SMEM (17408 * 4)
#define PERM_SMEM  34816

extern "C" void kernel_launch(void* const* d_in, const int* in_sizes, int n_in,
                              void* d_out, int out_size)
{
    (void)in_sizes; (void)n_in; (void)out_size;
    const float* x      = (const float*)d_in[0];
    const float* wq     = (const float*)d_in[1];
    const float* wk     = (const float*)d_in[2];
    const float* wv     = (const float*)d_in[3];
    const float* wo     = (const float*)d_in[4];
    const float* qg     = (const float*)d_in[5];
    const float* kg     = (const float*)d_in[6];
    const float* fc_s1  = (const float*)d_in[7];
    const float* fc_s2  = (const float*)d_in[8];
    const float* fc_mix = (const float*)d_in[9];
    const float* fc_lg  = (const float*)d_in[10];
    const float* pj_s1  = (const float*)d_in[11];
    const float* pj_s2  = (const float*)d_in[12];
    const float* pj_mix = (const float*)d_in[13];
    const float* pj_lg  = (const float*)d_in[14];

    float *xn, *qkv, *x2, *t1a, *t1b, *tk0, *tk1, *coef;
    int* sel;
    __nv_bfloat16 *ah, *al, *bh, *bl, *wh, *wl, *qh, *ql, *kh, *kl, *vh, *vl, *yh, *yl;
    cudaGetSymbolAddress((void**)&xn,  g_xn);
    cudaGetSymbolAddress((void**)&qkv, g_qkv);
    cudaGetSymbolAddress((void**)&x2,  g_x2);
    cudaGetSymbolAddress((void**)&t1a, g_t1a);
    cudaGetSymbolAddress((void**)&t1b, g_t1b);
    cudaGetSymbolAddress((void**)&tk0, g_tk0);
    cudaGetSymbolAddress((void**)&tk1, g_tk1);
    cudaGetSymbolAddress((void**)&sel,  g_sel);
    cudaGetSymbolAddress((void**)&coef, g_coef);
    cudaGetSymbolAddress((void**)&ah, g_ah);
    cudaGetSymbolAddress((void**)&al, g_al);
    cudaGetSymbolAddress((void**)&bh, g_bh);
    cudaGetSymbolAddress((void**)&bl, g_bl);
    cudaGetSymbolAddress((void**)&wh, g_wh);
    cudaGetSymbolAddress((void**)&wl, g_wl);
    cudaGetSymbolAddress((void**)&qh, g_qh);
    cudaGetSymbolAddress((void**)&ql, g_ql);
    cudaGetSymbolAddress((void**)&kh, g_kh);
    cudaGetSymbolAddress((void**)&kl, g_kl);
    cudaGetSymbolAddress((void**)&vh, g_vh);
    cudaGetSymbolAddress((void**)&vl, g_vl);
    cudaGetSymbolAddress((void**)&yh, g_yh);
    cudaGetSymbolAddress((void**)&yl, g_yl);

    cudaFuncSetAttribute(gemm_bf16x3, cudaFuncAttributeMaxDynamicSharedMemorySize, GEMM_SMEM);
    cudaFuncSetAttribute(attn_mma_kernel, cudaFuncAttributeMaxDynamicSharedMemorySize, ATTN_SMEM);
    cudaFuncSetAttribute(fcs1_dual_kernel, cudaFuncAttributeMaxDynamicSharedMemorySize, DUAL3_SMEM);
    cudaFuncSetAttribute(mid_dual_kernel, cudaFuncAttributeMaxDynamicSharedMemorySize, DUAL4_SMEM);
    cudaFuncSetAttribute(final_dual_kernel, cudaFuncAttributeMaxDynamicSharedMemorySize, DUAL4_SMEM);

    // x1 = rms_norm(x) -> split bf16
    rmsnorm_split_kernel<<<4096, 256>>>(x, ah, al);

    // packed QKV projection
    split_kernel<<<512, 256>>>(wq, wh, wl, 1048576);
    split_kernel<<<128, 256>>>(wk, wh + 1048576, wl + 1048576, 262144);
    split_kernel<<<128, 256>>>(wv, wh + 1310720, wl + 1310720, 262144);
    gemm_bf16x3<<<dim3(12, 32), 256, GEMM_SMEM>>>(ah, al, wh, wl, qkv, nullptr, 1536, 1024);
    qkvprep_kernel<<<12288, 256>>>(qkv, qh, ql, kh, kl, vh, vl, qg, kg);

    // attention
    attn_mma_kernel<<<dim3(32, 16, 2), 128, ATTN_SMEM>>>(qh, ql, kh, kl, vh, vl, yh, yl);

    // x2 = x + y @ wo^T
    split_kernel<<<512, 256>>>(wo, wh, wl, 1048576);
    gemm_bf16x3<<<dim3(8, 32), 256, GEMM_SMEM>>>(yh, yl, wh, wl, x2, x, 1024, 1024);

    // h = rms_norm(x2); routing
    rmsnorm_kernel<<<4096, 256>>>(x2, xn);
    router_kernel<<<1, 32>>>(fc_lg, pj_lg, sel, coef);

    // fc_s1 both experts -> ah/al, bh/bl (pre-perm layout)
    fcs1_dual_kernel<<<dim3(16, 64), 256, DUAL3_SMEM>>>(xn, fc_s1, ah, al, bh, bl, sel);
    // fc mix GEMMs (perm folded into weight split)
    split_perm_kernel<<<512, 256, PERM_SMEM>>>(fc_mix, wh, wl, 1024, 16, 8, sel + 0, 4194304);
    gemm_bf16x3<<<dim3(32, 32), 256, GEMM_SMEM>>>(ah, al, wh, wl, tk0, nullptr, 4096, 1024);
    split_perm_kernel<<<512, 256, PERM_SMEM>>>(fc_mix, wh, wl, 1024, 16, 8, sel + 1, 4194304);
    gemm_bf16x3<<<dim3(32, 32), 256, GEMM_SMEM>>>(bh, bl, wh, wl, tk1, nullptr, 4096, 1024);

    // fc_s2 combine + relu^2 + pj_s1 both experts
    mid_dual_kernel<<<dim3(64, 64), 256, DUAL4_SMEM>>>(tk0, tk1, fc_s2, pj_s1, ah, al, bh, bl, sel, coef);

    // pj mix GEMMs
    split_perm_kernel<<<512, 256, PERM_SMEM>>>(pj_mix, wh, wl, 4096, 64, 2, sel + 2, 4194304);
    gemm_bf16x3<<<dim3(8, 32), 256, GEMM_SMEM>>>(ah, al, wh, wl, t1a, nullptr, 1024, 4096);
    split_perm_kernel<<<512, 256, PERM_SMEM>>>(pj_mix, wh, wl, 4096, 64, 2, sel + 3, 4194304);
    gemm_bf16x3<<<dim3(8, 32), 256, GEMM_SMEM>>>(bh, bl, wh, wl, t1b, nullptr, 1024, 4096);

    // pj_s2 combine + residual -> out
    final_dual_kernel<<<dim3(16, 64), 256, DUAL4_SMEM>>>(t1a, t1b, pj_s2, x2, (float*)d_out, sel, coef);
}

// round 6
// speedup vs baseline: 4.8167x; 1.6994x over previous
#include <cuda_runtime.h>
#include <cuda_bf16.h>
#include <math.h>
#include <stdint.h>

// ---------------- static device scratch ----------------
static __device__ float g_qkv[4096*1536];
static __device__ float g_x2 [4096*1024];
static __device__ float g_wm0[8388608];    // WM2T scratch (fc, 2 experts x 4M)
static __device__ float g_wm1[8388608];    // WM2T scratch (pj, 2 experts x 4M)
static __device__ int   g_sel[4];
static __device__ float g_coef[4];
static __device__ __nv_bfloat16 g_ah[4194304];   // rms splits / fc gemm A
static __device__ __nv_bfloat16 g_al[4194304];
static __device__ __nv_bfloat16 g_gh[16777216];  // relu2 hidden hi
static __device__ __nv_bfloat16 g_gl[16777216];
static __device__ __nv_bfloat16 g_wh[4194304];   // qkv/wo weight splits
static __device__ __nv_bfloat16 g_wl[4194304];
static __device__ __nv_bfloat16 g_wfch[4194304]; // folded fc weight
static __device__ __nv_bfloat16 g_wfcl[4194304];
static __device__ __nv_bfloat16 g_wpjh[4194304]; // folded pj weight
static __device__ __nv_bfloat16 g_wpjl[4194304];
static __device__ __nv_bfloat16 g_qh[4194304];
static __device__ __nv_bfloat16 g_ql[4194304];
static __device__ __nv_bfloat16 g_kh[1048576];
static __device__ __nv_bfloat16 g_kl[1048576];
static __device__ __nv_bfloat16 g_vh[1048576];
static __device__ __nv_bfloat16 g_vl[1048576];
static __device__ __nv_bfloat16 g_yh[4194304];
static __device__ __nv_bfloat16 g_yl[4194304];

// ---------------- PTX helpers ----------------
__device__ __forceinline__ uint32_t smem_u32(const void* p) {
    uint32_t a;
    asm("{ .reg .u64 t; cvta.to.shared.u64 t, %1; cvt.u32.u64 %0, t; }" : "=r"(a) : "l"(p));
    return a;
}
#define CP_ASYNC16(dst, src) \
    asm volatile("cp.async.cg.shared.global [%0], [%1], 16;" :: "r"(dst), "l"(src))
#define CP_COMMIT() asm volatile("cp.async.commit_group;" ::: "memory")
#define CP_WAIT2()  asm volatile("cp.async.wait_group 2;" ::: "memory")
#define CP_WAIT0()  asm volatile("cp.async.wait_group 0;" ::: "memory")

#define LDSM_X4(r, addr) \
    asm volatile("ldmatrix.sync.aligned.m8n8.x4.shared.b16 {%0,%1,%2,%3}, [%4];" \
        : "=r"((r)[0]), "=r"((r)[1]), "=r"((r)[2]), "=r"((r)[3]) : "r"(addr))
#define LDSM_X4_T(r, addr) \
    asm volatile("ldmatrix.sync.aligned.m8n8.x4.trans.shared.b16 {%0,%1,%2,%3}, [%4];" \
        : "=r"((r)[0]), "=r"((r)[1]), "=r"((r)[2]), "=r"((r)[3]) : "r"(addr))

#define MMA_BF16(d, a, b0, b1) \
    asm volatile("mma.sync.aligned.m16n8k16.row.col.f32.bf16.bf16.f32 " \
        "{%0,%1,%2,%3}, {%4,%5,%6,%7}, {%8,%9}, {%0,%1,%2,%3};" \
        : "+f"((d)[0]), "+f"((d)[1]), "+f"((d)[2]), "+f"((d)[3]) \
        : "r"((a)[0]), "r"((a)[1]), "r"((a)[2]), "r"((a)[3]), "r"(b0), "r"(b1))

__device__ __forceinline__ void split2(float v0, float v1, uint32_t& h, uint32_t& l) {
    __nv_bfloat16 h0 = __float2bfloat16_rn(v0), h1 = __float2bfloat16_rn(v1);
    float r0 = v0 - __bfloat162float(h0), r1 = v1 - __bfloat162float(h1);
    __nv_bfloat16 l0 = __float2bfloat16_rn(r0), l1 = __float2bfloat16_rn(r1);
    h = (uint32_t)*(uint16_t*)&h0 | ((uint32_t)*(uint16_t*)&h1 << 16);
    l = (uint32_t)*(uint16_t*)&l0 | ((uint32_t)*(uint16_t*)&l1 << 16);
}

// ---------------- plain fp32 -> (hi,lo) bf16 split ----------------
__global__ void split_kernel(const float* __restrict__ src, __nv_bfloat16* __restrict__ hi,
                             __nv_bfloat16* __restrict__ lo, int n)
{
    int i = (blockIdx.x * blockDim.x + threadIdx.x) * 8;
    if (i >= n) return;
    float4 a = *(const float4*)(src + i);
    float4 b = *(const float4*)(src + i + 4);
    uint32_t h0,l0,h1,l1,h2,l2,h3,l3;
    split2(a.x, a.y, h0, l0); split2(a.z, a.w, h1, l1);
    split2(b.x, b.y, h2, l2); split2(b.z, b.w, h3, l3);
    *(uint4*)(hi + i) = make_uint4(h0, h1, h2, h3);
    *(uint4*)(lo + i) = make_uint4(l0, l1, l2, l3);
}

// ---------------- HMMA bf16x3 GEMM, 4-stage pipeline ----------------
// epilogue modes: 0 = fp32 C (+ optional res); 1 = relu(v)^2 -> split bf16 (OH/OL)
#define TSTRIDE 80
#define BUF_BYTES (128 * TSTRIDE)
#define STAGE_BYTES (4 * BUF_BYTES)
#define GEMM_SMEM (4 * STAGE_BYTES)

__device__ __forceinline__ void gemm_load_stage(
    uint32_t smbase, int kt, int NT, int K, int tid,
    const __nv_bfloat16* s0, const __nv_bfloat16* s1,
    const __nv_bfloat16* s2, const __nv_bfloat16* s3)
{
    if (kt < NT) {
        uint32_t sb = smbase + (kt & 3) * STAGE_BYTES;
        int k0 = kt * 32;
        const __nv_bfloat16* srcs[4] = {s0, s1, s2, s3};
#pragma unroll
        for (int t = 0; t < 8; t++) {
            int c = tid + 256 * t;
            int buf = c >> 9, cc = c & 511;
            int row = cc >> 2, kc = cc & 3;
            uint32_t dst = sb + buf * BUF_BYTES + row * TSTRIDE + kc * 16;
            const __nv_bfloat16* src = srcs[buf] + (size_t)row * K + k0 + kc * 8;
            CP_ASYNC16(dst, src);
        }
    }
    CP_COMMIT();
}

__global__ __launch_bounds__(256) void gemm_bf16x3(
    const __nv_bfloat16* __restrict__ Ah, const __nv_bfloat16* __restrict__ Al,
    const __nv_bfloat16* __restrict__ Wh, const __nv_bfloat16* __restrict__ Wl,
    float* __restrict__ C, const float* __restrict__ res, int N, int K,
    __nv_bfloat16* __restrict__ OH, __nv_bfloat16* __restrict__ OL)
{
    extern __shared__ char smem[];
    uint32_t smbase = smem_u32(smem);
    int tid = threadIdx.x, wid = tid >> 5, lane = tid & 31;
    int m0 = blockIdx.y * 128, n0 = blockIdx.x * 128;
    int wm = wid >> 1, wn = wid & 1;

    const __nv_bfloat16* s0 = Ah + (size_t)m0 * K;
    const __nv_bfloat16* s1 = Al + (size_t)m0 * K;
    const __nv_bfloat16* s2 = Wh + (size_t)n0 * K;
    const __nv_bfloat16* s3 = Wl + (size_t)n0 * K;

    float acc[2][8][4];
#pragma unroll
    for (int i = 0; i < 2; i++)
#pragma unroll
        for (int j = 0; j < 8; j++)
#pragma unroll
            for (int r = 0; r < 4; r++) acc[i][j][r] = 0.f;

    int NT = K >> 5;
    gemm_load_stage(smbase, 0, NT, K, tid, s0, s1, s2, s3);
    gemm_load_stage(smbase, 1, NT, K, tid, s0, s1, s2, s3);
    gemm_load_stage(smbase, 2, NT, K, tid, s0, s1, s2, s3);

    int lt = lane >> 3, lr = lane & 7;
    for (int kt = 0; kt < NT; kt++) {
        CP_WAIT2();
        __syncthreads();
        gemm_load_stage(smbase, kt + 3, NT, K, tid, s0, s1, s2, s3);
        uint32_t sb = smbase + (kt & 3) * STAGE_BYTES;
#pragma unroll
        for (int kk = 0; kk < 2; kk++) {
            uint32_t a_hi[2][4], a_lo[2][4];
#pragma unroll
            for (int i = 0; i < 2; i++) {
                int row = wm * 32 + i * 16 + lr + (lt & 1) * 8;
                int kofs = kk * 16 + (lt >> 1) * 8;
                uint32_t addr = sb + row * TSTRIDE + kofs * 2;
                LDSM_X4(a_hi[i], addr);
                LDSM_X4(a_lo[i], addr + BUF_BYTES);
            }
            uint32_t b_hi[4][4], b_lo[4][4];
#pragma unroll
            for (int j = 0; j < 4; j++) {
                int row = wn * 64 + j * 16 + lr + (lt >> 1) * 8;
                int kofs = kk * 16 + (lt & 1) * 8;
                uint32_t addr = sb + 2 * BUF_BYTES + row * TSTRIDE + kofs * 2;
                LDSM_X4(b_hi[j], addr);
                LDSM_X4(b_lo[j], addr + BUF_BYTES);
            }
#pragma unroll
            for (int i = 0; i < 2; i++)
#pragma unroll
                for (int j = 0; j < 8; j++) {
                    uint32_t bh0 = b_hi[j >> 1][(j & 1) * 2], bh1 = b_hi[j >> 1][(j & 1) * 2 + 1];
                    uint32_t bl0 = b_lo[j >> 1][(j & 1) * 2], bl1 = b_lo[j >> 1][(j & 1) * 2 + 1];
                    MMA_BF16(acc[i][j], a_hi[i], bh0, bh1);
                    MMA_BF16(acc[i][j], a_hi[i], bl0, bl1);
                    MMA_BF16(acc[i][j], a_lo[i], bh0, bh1);
                }
        }
    }
    CP_WAIT0();

    int rbase = m0 + wm * 32 + (lane >> 2);
    int cbase = n0 + wn * 64 + (lane & 3) * 2;
#pragma unroll
    for (int i = 0; i < 2; i++) {
#pragma unroll
        for (int half = 0; half < 2; half++) {
            size_t row = (size_t)(rbase + i * 16 + half * 8);
#pragma unroll
            for (int j = 0; j < 8; j++) {
                size_t idx = row * (size_t)N + cbase + j * 8;
                float v0 = acc[i][j][half * 2 + 0];
                float v1 = acc[i][j][half * 2 + 1];
                if (OH) {
                    v0 = fmaxf(v0, 0.f); v0 *= v0;
                    v1 = fmaxf(v1, 0.f); v1 *= v1;
                    uint32_t hh, ll;
                    split2(v0, v1, hh, ll);
                    *(uint32_t*)(OH + idx) = hh;
                    *(uint32_t*)(OL + idx) = ll;
                } else {
                    if (res) { v0 += res[idx]; v1 += res[idx + 1]; }
                    *(float2*)(C + idx) = make_float2(v0, v1);
                }
            }
        }
    }
}

// ---------------- RMSNorm with bf16 hi/lo split output ----------------
__global__ void rmsnorm_split_kernel(const float* __restrict__ x,
                                     __nv_bfloat16* __restrict__ hi,
                                     __nv_bfloat16* __restrict__ lo)
{
    int n = blockIdx.x;
    int tid = threadIdx.x;
    const float4* xr = (const float4*)(x + (size_t)n * 1024);
    float4 v = xr[tid];
    float s = v.x*v.x + v.y*v.y + v.z*v.z + v.w*v.w;
#pragma unroll
    for (int off = 16; off > 0; off >>= 1) s += __shfl_xor_sync(0xffffffffu, s, off);
    __shared__ float red[8];
    if ((tid & 31) == 0) red[tid >> 5] = s;
    __syncthreads();
    float tot = 0.f;
#pragma unroll
    for (int i = 0; i < 8; i++) tot += red[i];
    float r = rsqrtf(tot * (1.f/1024.f) + 1e-6f);
    uint32_t h0,l0,h1,l1;
    split2(v.x*r, v.y*r, h0, l0);
    split2(v.z*r, v.w*r, h1, l1);
    size_t base = (size_t)n * 1024 + tid * 4;
    *(uint2*)(hi + base) = make_uint2(h0, h1);
    *(uint2*)(lo + base) = make_uint2(l0, l1);
}

// ---------------- qkv prep (per-head rms*gain + rope; v passthrough) ----------------
__global__ void qkvprep_kernel(const float* __restrict__ qkv,
                               __nv_bfloat16* __restrict__ qh, __nv_bfloat16* __restrict__ ql,
                               __nv_bfloat16* __restrict__ kh, __nv_bfloat16* __restrict__ kl,
                               __nv_bfloat16* __restrict__ vh, __nv_bfloat16* __restrict__ vl,
                               const float* __restrict__ qg, const float* __restrict__ kg)
{
    int gt = blockIdx.x * blockDim.x + threadIdx.x;
    int w = gt >> 5, lane = gt & 31;
    if (w < 81920) {
        const float* src; float gain; int t; __nv_bfloat16 *dh, *dl; size_t dbase;
        if (w < 65536) {
            int n = w >> 4, h = w & 15;
            src = qkv + (size_t)n * 1536 + h * 64;
            gain = qg[h]; t = n & 2047;
            dbase = ((size_t)((n >> 11) * 16 + h) * 2048 + t) * 64;
            dh = qh; dl = ql;
        } else {
            int w2 = w - 65536;
            int n = w2 >> 2, h = w2 & 3;
            src = qkv + (size_t)n * 1536 + 1024 + h * 64;
            gain = kg[h]; t = n & 2047;
            dbase = ((size_t)((n >> 11) * 4 + h) * 2048 + t) * 64;
            dh = kh; dl = kl;
        }
        float v1 = src[lane], v2 = src[lane + 32];
        float s = v1*v1 + v2*v2;
#pragma unroll
        for (int off = 16; off > 0; off >>= 1) s += __shfl_xor_sync(0xffffffffu, s, off);
        float r = rsqrtf(s * (1.f/64.f) + 1e-6f) * gain;
        v1 *= r; v2 *= r;
        float freq = powf(10000.f, -(float)(2 * lane) / 64.f);
        float ang = (float)t * freq;
        float sn, cs;
        sincosf(ang, &sn, &cs);
        float o1 = v1 * cs + v2 * sn;
        float o2 = v2 * cs - v1 * sn;
        __nv_bfloat16 hb1 = __float2bfloat16_rn(o1);
        __nv_bfloat16 lb1 = __float2bfloat16_rn(o1 - __bfloat162float(hb1));
        __nv_bfloat16 hb2 = __float2bfloat16_rn(o2);
        __nv_bfloat16 lb2 = __float2bfloat16_rn(o2 - __bfloat162float(hb2));
        dh[dbase + lane] = hb1; dl[dbase + lane] = lb1;
        dh[dbase + lane + 32] = hb2; dl[dbase + lane + 32] = lb2;
    } else {
        int w2 = w - 81920;
        int n = w2 >> 2, h = w2 & 3;
        const float* src = qkv + (size_t)n * 1536 + 1280 + h * 64;
        int t = n & 2047;
        size_t dbase = ((size_t)((n >> 11) * 4 + h) * 2048 + t) * 64;
        float v1 = src[lane], v2 = src[lane + 32];
        __nv_bfloat16 hb1 = __float2bfloat16_rn(v1);
        __nv_bfloat16 lb1 = __float2bfloat16_rn(v1 - __bfloat162float(hb1));
        __nv_bfloat16 hb2 = __float2bfloat16_rn(v2);
        __nv_bfloat16 lb2 = __float2bfloat16_rn(v2 - __bfloat162float(hb2));
        vh[dbase + lane] = hb1; vl[dbase + lane] = lb1;
        vh[dbase + lane + 32] = hb2; vl[dbase + lane + 32] = lb2;
    }
}

// ---------------- tensor-core flash attention (bf16x3) ----------------
#define AT_ROWB 144
#define AT_TILE (64 * AT_ROWB)
#define AT_STAGE (4 * AT_TILE)
#define ATTN_SMEM (2 * AT_TILE + 2 * AT_STAGE)

__device__ __forceinline__ void attn_load_kv(
    uint32_t dstbase, int tid,
    const __nv_bfloat16* kh, const __nv_bfloat16* kl,
    const __nv_bfloat16* vh, const __nv_bfloat16* vl,
    size_t kvoff, int kt)
{
    const __nv_bfloat16* srcs[4] = {kh, kl, vh, vl};
#pragma unroll
    for (int t = 0; t < 16; t++) {
        int idx = tid + 128 * t;
        int buf = idx >> 9, cc = idx & 511, row = cc >> 3, ch = cc & 7;
        const __nv_bfloat16* src = srcs[buf] + kvoff + (size_t)(kt * 64 + row) * 64 + ch * 8;
        CP_ASYNC16(dstbase + buf * AT_TILE + row * AT_ROWB + ch * 16, src);
    }
}

__global__ __launch_bounds__(128) void attn_mma_kernel(
    const __nv_bfloat16* __restrict__ qh, const __nv_bfloat16* __restrict__ ql,
    const __nv_bfloat16* __restrict__ kh, const __nv_bfloat16* __restrict__ kl,
    const __nv_bfloat16* __restrict__ vh, const __nv_bfloat16* __restrict__ vl,
    __nv_bfloat16* __restrict__ yh, __nv_bfloat16* __restrict__ yl)
{
    extern __shared__ char smem[];
    uint32_t sb = smem_u32(smem);
    int qt = blockIdx.x, h = blockIdx.y, b = blockIdx.z;
    int tid = threadIdx.x, w = tid >> 5, lane = tid & 31;
    int lr = lane & 7, lt = lane >> 3;
    size_t qoff = ((size_t)(b * 16 + h) * 2048 + qt * 64) * 64;
    size_t kvoff = (size_t)(b * 4 + (h >> 2)) * 2048 * 64;

#pragma unroll
    for (int t = 0; t < 8; t++) {
        int idx = tid + 128 * t;
        int buf = idx >> 9, cc = idx & 511, row = cc >> 3, ch = cc & 7;
        const __nv_bfloat16* src = (buf ? ql : qh) + qoff + row * 64 + ch * 8;
        CP_ASYNC16(sb + buf * AT_TILE + row * AT_ROWB + ch * 16, src);
    }
    CP_COMMIT();
    attn_load_kv(sb + 2 * AT_TILE, tid, kh, kl, vh, vl, kvoff, 0);
    CP_COMMIT();
    CP_WAIT0();
    __syncthreads();

    uint32_t qfh[4][4], qfl[4][4];
#pragma unroll
    for (int kk = 0; kk < 4; kk++) {
        uint32_t addr = sb + (w * 16 + lr + (lt & 1) * 8) * AT_ROWB + (kk * 16 + (lt >> 1) * 8) * 2;
        LDSM_X4(qfh[kk], addr);
        LDSM_X4(qfl[kk], addr + AT_TILE);
    }

    float O[8][4];
#pragma unroll
    for (int j = 0; j < 8; j++)
#pragma unroll
        for (int r = 0; r < 4; r++) O[j][r] = 0.f;
    float m0 = -1e30f, m1 = -1e30f, l0 = 0.f, l1 = 0.f;

    for (int kt = 0; kt <= qt; kt++) {
        if (kt < qt) {
            attn_load_kv(sb + 2 * AT_TILE + ((kt + 1) & 1) * AT_STAGE, tid, kh, kl, vh, vl, kvoff, kt + 1);
            CP_COMMIT();
        }
        uint32_t kb = sb + 2 * AT_TILE + (kt & 1) * AT_STAGE;
        float c[8][4];
#pragma unroll
        for (int j = 0; j < 8; j++)
#pragma unroll
            for (int r = 0; r < 4; r++) c[j][r] = 0.f;
#pragma unroll
        for (int kk = 0; kk < 4; kk++) {
            uint32_t kbh[4][4], kbl[4][4];
#pragma unroll
            for (int j2 = 0; j2 < 4; j2++) {
                uint32_t addr = kb + (j2 * 16 + lr + (lt >> 1) * 8) * AT_ROWB + (kk * 16 + (lt & 1) * 8) * 2;
                LDSM_X4(kbh[j2], addr);
                LDSM_X4(kbl[j2], addr + AT_TILE);
            }
#pragma unroll
            for (int j = 0; j < 8; j++) {
                uint32_t bh0 = kbh[j >> 1][(j & 1) * 2], bh1 = kbh[j >> 1][(j & 1) * 2 + 1];
                uint32_t bl0 = kbl[j >> 1][(j & 1) * 2], bl1 = kbl[j >> 1][(j & 1) * 2 + 1];
                MMA_BF16(c[j], qfh[kk], bh0, bh1);
                MMA_BF16(c[j], qfh[kk], bl0, bl1);
                MMA_BF16(c[j], qfl[kk], bh0, bh1);
            }
        }
        if (kt == qt) {
            int r0 = w * 16 + (lane >> 2), r1 = r0 + 8;
#pragma unroll
            for (int j = 0; j < 8; j++) {
                int col = j * 8 + (lane & 3) * 2;
                if (col     > r0) c[j][0] = -1e30f;
                if (col + 1 > r0) c[j][1] = -1e30f;
                if (col     > r1) c[j][2] = -1e30f;
                if (col + 1 > r1) c[j][3] = -1e30f;
            }
        }
        float mx0 = -1e30f, mx1 = -1e30f;
#pragma unroll
        for (int j = 0; j < 8; j++) {
            mx0 = fmaxf(mx0, fmaxf(c[j][0], c[j][1]));
            mx1 = fmaxf(mx1, fmaxf(c[j][2], c[j][3]));
        }
        mx0 *= 0.125f; mx1 *= 0.125f;
        mx0 = fmaxf(mx0, __shfl_xor_sync(0xffffffffu, mx0, 1));
        mx0 = fmaxf(mx0, __shfl_xor_sync(0xffffffffu, mx0, 2));
        mx1 = fmaxf(mx1, __shfl_xor_sync(0xffffffffu, mx1, 1));
        mx1 = fmaxf(mx1, __shfl_xor_sync(0xffffffffu, mx1, 2));
        float m0n = fmaxf(m0, mx0), m1n = fmaxf(m1, mx1);
        float cr0 = __expf(m0 - m0n), cr1 = __expf(m1 - m1n);
        float s0 = 0.f, s1 = 0.f;
#pragma unroll
        for (int j = 0; j < 8; j++) {
            c[j][0] = __expf(fmaf(c[j][0], 0.125f, -m0n)); s0 += c[j][0];
            c[j][1] = __expf(fmaf(c[j][1], 0.125f, -m0n)); s0 += c[j][1];
            c[j][2] = __expf(fmaf(c[j][2], 0.125f, -m1n)); s1 += c[j][2];
            c[j][3] = __expf(fmaf(c[j][3], 0.125f, -m1n)); s1 += c[j][3];
        }
        s0 += __shfl_xor_sync(0xffffffffu, s0, 1);
        s0 += __shfl_xor_sync(0xffffffffu, s0, 2);
        s1 += __shfl_xor_sync(0xffffffffu, s1, 1);
        s1 += __shfl_xor_sync(0xffffffffu, s1, 2);
        l0 = l0 * cr0 + s0; l1 = l1 * cr1 + s1;
        m0 = m0n; m1 = m1n;
#pragma unroll
        for (int j = 0; j < 8; j++) {
            O[j][0] *= cr0; O[j][1] *= cr0;
            O[j][2] *= cr1; O[j][3] *= cr1;
        }
#pragma unroll
        for (int kt2 = 0; kt2 < 4; kt2++) {
            uint32_t pah[4], pal[4];
            split2(c[2*kt2][0],   c[2*kt2][1],   pah[0], pal[0]);
            split2(c[2*kt2][2],   c[2*kt2][3],   pah[1], pal[1]);
            split2(c[2*kt2+1][0], c[2*kt2+1][1], pah[2], pal[2]);
            split2(c[2*kt2+1][2], c[2*kt2+1][3], pah[3], pal[3]);
#pragma unroll
            for (int jd = 0; jd < 4; jd++) {
                uint32_t vbh[4], vbl[4];
                uint32_t addr = kb + 2 * AT_TILE + (kt2 * 16 + (lt & 1) * 8 + lr) * AT_ROWB + (jd * 16 + (lt >> 1) * 8) * 2;
                LDSM_X4_T(vbh, addr);
                LDSM_X4_T(vbl, addr + AT_TILE);
#pragma unroll
                for (int js = 0; js < 2; js++) {
                    int j = jd * 2 + js;
                    MMA_BF16(O[j], pah, vbh[js*2], vbh[js*2+1]);
                    MMA_BF16(O[j], pah, vbl[js*2], vbl[js*2+1]);
                    MMA_BF16(O[j], pal, vbh[js*2], vbh[js*2+1]);
                }
            }
        }
        if (kt < qt) CP_WAIT0();
        __syncthreads();
    }
    float i0 = 1.f / l0, i1 = 1.f / l1;
    size_t rA = (size_t)(b * 2048 + qt * 64 + w * 16 + (lane >> 2));
    size_t rB = rA + 8;
    int colb = h * 64 + (lane & 3) * 2;
#pragma unroll
    for (int j = 0; j < 8; j++) {
        uint32_t hh, ll;
        int col = colb + j * 8;
        split2(O[j][0] * i0, O[j][1] * i0, hh, ll);
        *(uint32_t*)(yh + rA * 1024 + col) = hh;
        *(uint32_t*)(yl + rA * 1024 + col) = ll;
        split2(O[j][2] * i1, O[j][3] * i1, hh, ll);
        *(uint32_t*)(yh + rB * 1024 + col) = hh;
        *(uint32_t*)(yl + rB * 1024 + col) = ll;
    }
}

// ---------------- tile helpers for folding kernels ----------------
#define TP 68
__device__ __forceinline__ void load_tile_s(float* dst, const float* src, size_t stride, int tid) {
    // dst[row][col] = src[row*stride + col], 64x64
#pragma unroll
    for (int r = 0; r < 4; r++) {
        int f = tid + 256 * r;
        int row = f >> 4, c4 = (f & 15) << 2;
        *(float4*)&dst[row*TP + c4] = *(const float4*)(src + (size_t)row * stride + c4);
    }
}
__device__ __forceinline__ void load_tileT_s(float* dst, const float* src, size_t stride, int tid) {
    // dst[col][row] = src[row*stride + col], 64x64
#pragma unroll
    for (int r = 0; r < 4; r++) {
        int f = tid + 256 * r;
        int row = f >> 4, c4 = (f & 15) << 2;
        float4 v = *(const float4*)(src + (size_t)row * stride + c4);
        dst[(c4+0)*TP + row] = v.x; dst[(c4+1)*TP + row] = v.y;
        dst[(c4+2)*TP + row] = v.z; dst[(c4+3)*TP + row] = v.w;
    }
}
__device__ __forceinline__ void mm64(const float* XT, const float* W, float acc[4][4], int tx, int ty) {
#pragma unroll
    for (int c = 0; c < 64; c++) {
        float a[4], bb[4];
        *(float4*)a  = *(const float4*)&XT[c*TP + ty*4];
        *(float4*)bb = *(const float4*)&W [c*TP + tx*4];
#pragma unroll
        for (int i = 0; i < 4; i++)
#pragma unroll
            for (int j = 0; j < 4; j++) acc[i][j] = fmaf(a[i], bb[j], acc[i][j]);
    }
}

// ---------------- P1: fold s2 into mix.  WM2T[j, G*64+D] = sum_C mix[G*64+C, j] * s2[G,C,D] ----------------
// grid: (in_f/64, n_out, 2 experts). out per expert offset r*in_f*out_f.
__global__ __launch_bounds__(256) void fold1_kernel(
    const float* __restrict__ Mix, const float* __restrict__ S2,
    float* __restrict__ WM2T, int in_f, int out_f,
    const int* __restrict__ selp)
{
    extern __shared__ float sm[];
    float* MT = sm;          // [C][j]
    float* S  = sm + 4352;   // [C][D]
    int jb = blockIdx.x, G = blockIdx.y, r = blockIdx.z;
    int sel = selp[r];
    int tid = threadIdx.x;
    load_tile_s(MT, Mix + (size_t)sel * out_f * in_f + (size_t)(G * 64) * in_f + jb * 64, in_f, tid);
    load_tile_s(S,  S2  + (size_t)sel * out_f * 64 + (size_t)G * 4096, 64, tid);
    __syncthreads();
    int tx = tid & 15, ty = tid >> 4;
    float acc[4][4] = {};
    mm64(MT, S, acc, tx, ty);       // acc[i=j][j'=D]
    float* outp = WM2T + (size_t)r * in_f * out_f;
#pragma unroll
    for (int i = 0; i < 4; i++) {
        size_t row = (size_t)(jb * 64 + ty * 4 + i);
        *(float4*)(outp + row * out_f + G * 64 + tx * 4) =
            make_float4(acc[i][0], acc[i][1], acc[i][2], acc[i][3]);
    }
}

// ---------------- P2: fold s1 + roll-perm, combine experts, split bf16 ----------------
// Wout[O, g*64+c] = sum_r coef_r * sum_d WM2T_r[d*n_in + (g+sel_r)%n_in, O] * s1_r[g,c,d]
// grid: (n_in, out_f/64)
__global__ __launch_bounds__(256) void fold2_kernel(
    const float* __restrict__ WM2T, const float* __restrict__ S1,
    __nv_bfloat16* __restrict__ WH, __nv_bfloat16* __restrict__ WL,
    int in_f, int out_f, int n_in,
    const int* __restrict__ selp, const float* __restrict__ coefp)
{
    extern __shared__ float sm[];
    float* G0 = sm;           // gathered [d][O] expert 0
    float* G1 = sm + 4352;
    float* T0 = sm + 8704;    // s1T [d][c] expert 0
    float* T1 = sm + 13056;
    int g = blockIdx.x, Ob = blockIdx.y, tid = threadIdx.x;
    int s0i = selp[0], s1i = selp[1];
    int gs0 = (g + s0i) % n_in, gs1 = (g + s1i) % n_in;
    const float* W0 = WM2T;
    const float* W1 = WM2T + (size_t)in_f * out_f;
#pragma unroll
    for (int r = 0; r < 4; r++) {
        int f = tid + 256 * r;
        int d = f >> 4, o4 = (f & 15) << 2;
        *(float4*)&G0[d*TP + o4] = *(const float4*)(W0 + (size_t)(d * n_in + gs0) * out_f + Ob * 64 + o4);
        *(float4*)&G1[d*TP + o4] = *(const float4*)(W1 + (size_t)(d * n_in + gs1) * out_f + Ob * 64 + o4);
    }
    load_tileT_s(T0, S1 + (size_t)s0i * in_f * 64 + (size_t)g * 4096, 64, tid);
    load_tileT_s(T1, S1 + (size_t)s1i * in_f * 64 + (size_t)g * 4096, 64, tid);
    __syncthreads();
    int tx = tid & 15, ty = tid >> 4;
    float a0[4][4] = {}, a1[4][4] = {};
    mm64(G0, T0, a0, tx, ty);       // acc[i=O][j=c]
    mm64(G1, T1, a1, tx, ty);
    float c0 = coefp[0], c1 = coefp[1];
#pragma unroll
    for (int i = 0; i < 4; i++) {
        size_t base = (size_t)(Ob * 64 + ty * 4 + i) * in_f + g * 64 + tx * 4;
        float v0 = c0 * a0[i][0] + c1 * a1[i][0];
        float v1 = c0 * a0[i][1] + c1 * a1[i][1];
        float v2 = c0 * a0[i][2] + c1 * a1[i][2];
        float v3 = c0 * a0[i][3] + c1 * a1[i][3];
        uint32_t hh, ll;
        split2(v0, v1, hh, ll);
        *(uint32_t*)(WH + base) = hh; *(uint32_t*)(WL + base) = ll;
        split2(v2, v3, hh, ll);
        *(uint32_t*)(WH + base + 2) = hh; *(uint32_t*)(WL + base + 2) = ll;
    }
}

// ---------------- top-2 router ----------------
__global__ void router_kernel(const float* __restrict__ fcl, const float* __restrict__ pjl,
                              int* __restrict__ sel, float* __restrict__ coef)
{
    if (threadIdx.x == 0 && blockIdx.x == 0) {
#pragma unroll
        for (int s = 0; s < 2; s++) {
            const float* L = s ? pjl : fcl;
            int i1 = 0; float v1 = L[0];
            for (int i = 1; i < 8; i++) if (L[i] > v1) { v1 = L[i]; i1 = i; }
            int i2 = -1; float v2 = -1e30f;
            for (int i = 0; i < 8; i++) if (i != i1 && L[i] > v2) { v2 = L[i]; i2 = i; }
            float e = expf(v2 - v1);
            float z = 1.f + e;
            sel[s*2+0] = i1; sel[s*2+1] = i2;
            coef[s*2+0] = 1.f / z; coef[s*2+1] = e / z;
        }
    }
}

// ---------------- host orchestration ----------------
#define FOLD1_SMEM (8704 * 4)
#define FOLD2_SMEM (17408 * 4)

extern "C" void kernel_launch(void* const* d_in, const int* in_sizes, int n_in_,
                              void* d_out, int out_size)
{
    (void)in_sizes; (void)n_in_; (void)out_size;
    const float* x      = (const float*)d_in[0];
    const float* wq     = (const float*)d_in[1];
    const float* wk     = (const float*)d_in[2];
    const float* wv     = (const float*)d_in[3];
    const float* wo     = (const float*)d_in[4];
    const float* qg     = (const float*)d_in[5];
    const float* kg     = (const float*)d_in[6];
    const float* fc_s1  = (const float*)d_in[7];
    const float* fc_s2  = (const float*)d_in[8];
    const float* fc_mix = (const float*)d_in[9];
    const float* fc_lg  = (const float*)d_in[10];
    const float* pj_s1  = (const float*)d_in[11];
    const float* pj_s2  = (const float*)d_in[12];
    const float* pj_mix = (const float*)d_in[13];
    const float* pj_lg  = (const float*)d_in[14];

    float *qkv, *x2, *wm0, *wm1, *coef;
    int* sel;
    __nv_bfloat16 *ah, *al, *gh, *gl, *wh, *wl, *wfch, *wfcl, *wpjh, *wpjl;
    __nv_bfloat16 *qh, *ql, *kh, *kl, *vh, *vl, *yh, *yl;
    cudaGetSymbolAddress((void**)&qkv, g_qkv);
    cudaGetSymbolAddress((void**)&x2,  g_x2);
    cudaGetSymbolAddress((void**)&wm0, g_wm0);
    cudaGetSymbolAddress((void**)&wm1, g_wm1);
    cudaGetSymbolAddress((void**)&sel,  g_sel);
    cudaGetSymbolAddress((void**)&coef, g_coef);
    cudaGetSymbolAddress((void**)&ah, g_ah);
    cudaGetSymbolAddress((void**)&al, g_al);
    cudaGetSymbolAddress((void**)&gh, g_gh);
    cudaGetSymbolAddress((void**)&gl, g_gl);
    cudaGetSymbolAddress((void**)&wh, g_wh);
    cudaGetSymbolAddress((void**)&wl, g_wl);
    cudaGetSymbolAddress((void**)&wfch, g_wfch);
    cudaGetSymbolAddress((void**)&wfcl, g_wfcl);
    cudaGetSymbolAddress((void**)&wpjh, g_wpjh);
    cudaGetSymbolAddress((void**)&wpjl, g_wpjl);
    cudaGetSymbolAddress((void**)&qh, g_qh);
    cudaGetSymbolAddress((void**)&ql, g_ql);
    cudaGetSymbolAddress((void**)&kh, g_kh);
    cudaGetSymbolAddress((void**)&kl, g_kl);
    cudaGetSymbolAddress((void**)&vh, g_vh);
    cudaGetSymbolAddress((void**)&vl, g_vl);
    cudaGetSymbolAddress((void**)&yh, g_yh);
    cudaGetSymbolAddress((void**)&yl, g_yl);

    cudaFuncSetAttribute(gemm_bf16x3, cudaFuncAttributeMaxDynamicSharedMemorySize, GEMM_SMEM);
    cudaFuncSetAttribute(attn_mma_kernel, cudaFuncAttributeMaxDynamicSharedMemorySize, ATTN_SMEM);
    cudaFuncSetAttribute(fold1_kernel, cudaFuncAttributeMaxDynamicSharedMemorySize, FOLD1_SMEM);
    cudaFuncSetAttribute(fold2_kernel, cudaFuncAttributeMaxDynamicSharedMemorySize, FOLD2_SMEM);

    // routing + weight folding (independent of activations)
    router_kernel<<<1, 32>>>(fc_lg, pj_lg, sel, coef);
    // fc: in_f=1024, out_f=4096, n_in=16, n_out=64
    fold1_kernel<<<dim3(16, 64, 2), 256, FOLD1_SMEM>>>(fc_mix, fc_s2, wm0, 1024, 4096, sel);
    fold2_kernel<<<dim3(16, 64), 256, FOLD2_SMEM>>>(wm0, fc_s1, wfch, wfcl, 1024, 4096, 16, sel, coef);
    // pj: in_f=4096, out_f=1024, n_in=64, n_out=16
    fold1_kernel<<<dim3(64, 16, 2), 256, FOLD1_SMEM>>>(pj_mix, pj_s2, wm1, 4096, 1024, sel + 2);
    fold2_kernel<<<dim3(64, 16), 256, FOLD2_SMEM>>>(wm1, pj_s1, wpjh, wpjl, 4096, 1024, 64, sel + 2, coef + 2);

    // x1 = rms_norm(x) -> split bf16
    rmsnorm_split_kernel<<<4096, 256>>>(x, ah, al);

    // packed QKV projection
    split_kernel<<<512, 256>>>(wq, wh, wl, 1048576);
    split_kernel<<<128, 256>>>(wk, wh + 1048576, wl + 1048576, 262144);
    split_kernel<<<128, 256>>>(wv, wh + 1310720, wl + 1310720, 262144);
    gemm_bf16x3<<<dim3(12, 32), 256, GEMM_SMEM>>>(ah, al, wh, wl, qkv, nullptr, 1536, 1024, nullptr, nullptr);
    qkvprep_kernel<<<12288, 256>>>(qkv, qh, ql, kh, kl, vh, vl, qg, kg);

    // attention
    attn_mma_kernel<<<dim3(32, 16, 2), 128, ATTN_SMEM>>>(qh, ql, kh, kl, vh, vl, yh, yl);

    // x2 = x + y @ wo^T
    split_kernel<<<512, 256>>>(wo, wh, wl, 1048576);
    gemm_bf16x3<<<dim3(8, 32), 256, GEMM_SMEM>>>(yh, yl, wh, wl, x2, x, 1024, 1024, nullptr, nullptr);

    // h = rms_norm(x2) -> split
    rmsnorm_split_kernel<<<4096, 256>>>(x2, ah, al);

    // fc bank (folded): h = relu(ah@Wfc^T)^2 -> split bf16
    gemm_bf16x3<<<dim3(32, 32), 256, GEMM_SMEM>>>(ah, al, wfch, wfcl, nullptr, nullptr, 4096, 1024, gh, gl);
    // pj bank (folded): out = x2 + h@Wpj^T
    gemm_bf16x3<<<dim3(8, 32), 256, GEMM_SMEM>>>(gh, gl, wpjh, wpjl, (float*)d_out, x2, 1024, 4096, nullptr, nullptr);
}

// round 7
// speedup vs baseline: 5.3268x; 1.1059x over previous
#include <cuda_runtime.h>
#include <cuda_bf16.h>
#include <math.h>
#include <stdint.h>

// ---------------- static device scratch ----------------
static __device__ float g_qkv[4096*1536];
static __device__ float g_x2 [4096*1024];
static __device__ float g_wm0[8388608];
static __device__ float g_wm1[8388608];
static __device__ int   g_sel[4];
static __device__ float g_coef[4];
static __device__ __nv_bfloat16 g_ah[4194304];
static __device__ __nv_bfloat16 g_al[4194304];
static __device__ __nv_bfloat16 g_gh[16777216];
static __device__ __nv_bfloat16 g_gl[16777216];
static __device__ __nv_bfloat16 g_wh[4194304];
static __device__ __nv_bfloat16 g_wl[4194304];
static __device__ __nv_bfloat16 g_wfch[4194304];
static __device__ __nv_bfloat16 g_wfcl[4194304];
static __device__ __nv_bfloat16 g_wpjh[4194304];
static __device__ __nv_bfloat16 g_wpjl[4194304];
static __device__ __nv_bfloat16 g_qh[4194304];
static __device__ __nv_bfloat16 g_ql[4194304];
static __device__ __nv_bfloat16 g_kh[1048576];
static __device__ __nv_bfloat16 g_kl[1048576];
static __device__ __nv_bfloat16 g_vh[1048576];
static __device__ __nv_bfloat16 g_vl[1048576];
static __device__ __nv_bfloat16 g_yh[4194304];
static __device__ __nv_bfloat16 g_yl[4194304];

// ---------------- PTX helpers ----------------
__device__ __forceinline__ uint32_t smem_u32(const void* p) {
    uint32_t a;
    asm("{ .reg .u64 t; cvta.to.shared.u64 t, %1; cvt.u32.u64 %0, t; }" : "=r"(a) : "l"(p));
    return a;
}
#define CP_ASYNC16(dst, src) \
    asm volatile("cp.async.cg.shared.global [%0], [%1], 16;" :: "r"(dst), "l"(src))
#define CP_COMMIT() asm volatile("cp.async.commit_group;" ::: "memory")
#define CP_WAIT1()  asm volatile("cp.async.wait_group 1;" ::: "memory")
#define CP_WAIT0()  asm volatile("cp.async.wait_group 0;" ::: "memory")

#define LDSM_X4(r, addr) \
    asm volatile("ldmatrix.sync.aligned.m8n8.x4.shared.b16 {%0,%1,%2,%3}, [%4];" \
        : "=r"((r)[0]), "=r"((r)[1]), "=r"((r)[2]), "=r"((r)[3]) : "r"(addr))
#define LDSM_X4_T(r, addr) \
    asm volatile("ldmatrix.sync.aligned.m8n8.x4.trans.shared.b16 {%0,%1,%2,%3}, [%4];" \
        : "=r"((r)[0]), "=r"((r)[1]), "=r"((r)[2]), "=r"((r)[3]) : "r"(addr))

#define MMA_BF16(d, a, b0, b1) \
    asm volatile("mma.sync.aligned.m16n8k16.row.col.f32.bf16.bf16.f32 " \
        "{%0,%1,%2,%3}, {%4,%5,%6,%7}, {%8,%9}, {%0,%1,%2,%3};" \
        : "+f"((d)[0]), "+f"((d)[1]), "+f"((d)[2]), "+f"((d)[3]) \
        : "r"((a)[0]), "r"((a)[1]), "r"((a)[2]), "r"((a)[3]), "r"(b0), "r"(b1))

__device__ __forceinline__ void split2(float v0, float v1, uint32_t& h, uint32_t& l) {
    __nv_bfloat16 h0 = __float2bfloat16_rn(v0), h1 = __float2bfloat16_rn(v1);
    float r0 = v0 - __bfloat162float(h0), r1 = v1 - __bfloat162float(h1);
    __nv_bfloat16 l0 = __float2bfloat16_rn(r0), l1 = __float2bfloat16_rn(r1);
    h = (uint32_t)*(uint16_t*)&h0 | ((uint32_t)*(uint16_t*)&h1 << 16);
    l = (uint32_t)*(uint16_t*)&l0 | ((uint32_t)*(uint16_t*)&l1 << 16);
}

// ---------------- plain fp32 -> (hi,lo) bf16 split ----------------
__global__ void split_kernel(const float* __restrict__ src, __nv_bfloat16* __restrict__ hi,
                             __nv_bfloat16* __restrict__ lo, int n)
{
    int i = (blockIdx.x * blockDim.x + threadIdx.x) * 8;
    if (i >= n) return;
    float4 a = *(const float4*)(src + i);
    float4 b = *(const float4*)(src + i + 4);
    uint32_t h0,l0,h1,l1,h2,l2,h3,l3;
    split2(a.x, a.y, h0, l0); split2(a.z, a.w, h1, l1);
    split2(b.x, b.y, h2, l2); split2(b.z, b.w, h3, l3);
    *(uint4*)(hi + i) = make_uint4(h0, h1, h2, h3);
    *(uint4*)(lo + i) = make_uint4(l0, l1, l2, l3);
}

// ---------------- HMMA bf16x3 GEMM: packed hi|lo rows, 3-stage, 2 CTAs/SM ----------------
// smem row: [hi 64B | lo 64B | pad 16B] = 144B. Region 0 = A (128 rows), region 1 = W.
#define TST 144
#define REG_BYTES (128 * TST)          // 18432
#define STG (2 * REG_BYTES)            // 36864
#define GEMM_SMEM (3 * STG)            // 110592

__device__ __forceinline__ void gemm_load_stage(
    uint32_t smbase, int kt, int NT, int K, int tid,
    const __nv_bfloat16* s0, const __nv_bfloat16* s1,
    const __nv_bfloat16* s2, const __nv_bfloat16* s3)
{
    if (kt < NT) {
        uint32_t sb = smbase + (kt % 3) * STG;
        int k0 = kt * 32;
#pragma unroll
        for (int t = 0; t < 8; t++) {
            int idx = tid + 256 * t;            // 0..2047
            int region = idx >> 10;
            int cc = idx & 1023;
            int row = cc >> 3, ch = cc & 7;
            uint32_t dst = sb + region * REG_BYTES + row * TST
                         + ((ch < 4) ? ch * 16 : 64 + (ch - 4) * 16);
            const __nv_bfloat16* base = region ? ((ch < 4) ? s2 : s3)
                                               : ((ch < 4) ? s0 : s1);
            CP_ASYNC16(dst, base + (size_t)row * K + k0 + (ch & 3) * 8);
        }
    }
    CP_COMMIT();
}

__global__ __launch_bounds__(256, 2) void gemm_bf16x3(
    const __nv_bfloat16* __restrict__ Ah, const __nv_bfloat16* __restrict__ Al,
    const __nv_bfloat16* __restrict__ Wh, const __nv_bfloat16* __restrict__ Wl,
    float* __restrict__ C, const float* __restrict__ res, int N, int K,
    __nv_bfloat16* __restrict__ OH, __nv_bfloat16* __restrict__ OL)
{
    extern __shared__ char smem[];
    uint32_t smbase = smem_u32(smem);
    int tid = threadIdx.x, wid = tid >> 5, lane = tid & 31;
    int m0 = blockIdx.y * 128, n0 = blockIdx.x * 128;
    int wm = wid >> 1, wn = wid & 1;

    const __nv_bfloat16* s0 = Ah + (size_t)m0 * K;
    const __nv_bfloat16* s1 = Al + (size_t)m0 * K;
    const __nv_bfloat16* s2 = Wh + (size_t)n0 * K;
    const __nv_bfloat16* s3 = Wl + (size_t)n0 * K;

    float acc[2][8][4];
#pragma unroll
    for (int i = 0; i < 2; i++)
#pragma unroll
        for (int j = 0; j < 8; j++)
#pragma unroll
            for (int r = 0; r < 4; r++) acc[i][j][r] = 0.f;

    int NT = K >> 5;
    gemm_load_stage(smbase, 0, NT, K, tid, s0, s1, s2, s3);
    gemm_load_stage(smbase, 1, NT, K, tid, s0, s1, s2, s3);

    int lt = lane >> 3, lr = lane & 7;
    for (int kt = 0; kt < NT; kt++) {
        CP_WAIT1();
        __syncthreads();
        gemm_load_stage(smbase, kt + 2, NT, K, tid, s0, s1, s2, s3);
        uint32_t sb = smbase + (kt % 3) * STG;
        uint32_t sbW = sb + REG_BYTES;
#pragma unroll
        for (int kk = 0; kk < 2; kk++) {
            uint32_t a_hi[2][4], a_lo[2][4];
#pragma unroll
            for (int i = 0; i < 2; i++) {
                int row = wm * 32 + i * 16 + lr + (lt & 1) * 8;
                int kofs = kk * 16 + (lt >> 1) * 8;
                uint32_t addr = sb + row * TST + kofs * 2;
                LDSM_X4(a_hi[i], addr);
                LDSM_X4(a_lo[i], addr + 64);
            }
            uint32_t b_hi[4][4], b_lo[4][4];
#pragma unroll
            for (int j = 0; j < 4; j++) {
                int row = wn * 64 + j * 16 + lr + (lt >> 1) * 8;
                int kofs = kk * 16 + (lt & 1) * 8;
                uint32_t addr = sbW + row * TST + kofs * 2;
                LDSM_X4(b_hi[j], addr);
                LDSM_X4(b_lo[j], addr + 64);
            }
#pragma unroll
            for (int i = 0; i < 2; i++)
#pragma unroll
                for (int j = 0; j < 8; j++) {
                    uint32_t bh0 = b_hi[j >> 1][(j & 1) * 2], bh1 = b_hi[j >> 1][(j & 1) * 2 + 1];
                    uint32_t bl0 = b_lo[j >> 1][(j & 1) * 2], bl1 = b_lo[j >> 1][(j & 1) * 2 + 1];
                    MMA_BF16(acc[i][j], a_hi[i], bh0, bh1);
                    MMA_BF16(acc[i][j], a_hi[i], bl0, bl1);
                    MMA_BF16(acc[i][j], a_lo[i], bh0, bh1);
                }
        }
    }
    CP_WAIT0();

    int rbase = m0 + wm * 32 + (lane >> 2);
    int cbase = n0 + wn * 64 + (lane & 3) * 2;
#pragma unroll
    for (int i = 0; i < 2; i++) {
#pragma unroll
        for (int half = 0; half < 2; half++) {
            size_t row = (size_t)(rbase + i * 16 + half * 8);
#pragma unroll
            for (int j = 0; j < 8; j++) {
                size_t idx = row * (size_t)N + cbase + j * 8;
                float v0 = acc[i][j][half * 2 + 0];
                float v1 = acc[i][j][half * 2 + 1];
                if (OH) {
                    v0 = fmaxf(v0, 0.f); v0 *= v0;
                    v1 = fmaxf(v1, 0.f); v1 *= v1;
                    uint32_t hh, ll;
                    split2(v0, v1, hh, ll);
                    *(uint32_t*)(OH + idx) = hh;
                    *(uint32_t*)(OL + idx) = ll;
                } else {
                    if (res) { v0 += res[idx]; v1 += res[idx + 1]; }
                    *(float2*)(C + idx) = make_float2(v0, v1);
                }
            }
        }
    }
}

// ---------------- RMSNorm with bf16 hi/lo split output ----------------
__global__ void rmsnorm_split_kernel(const float* __restrict__ x,
                                     __nv_bfloat16* __restrict__ hi,
                                     __nv_bfloat16* __restrict__ lo)
{
    int n = blockIdx.x;
    int tid = threadIdx.x;
    const float4* xr = (const float4*)(x + (size_t)n * 1024);
    float4 v = xr[tid];
    float s = v.x*v.x + v.y*v.y + v.z*v.z + v.w*v.w;
#pragma unroll
    for (int off = 16; off > 0; off >>= 1) s += __shfl_xor_sync(0xffffffffu, s, off);
    __shared__ float red[8];
    if ((tid & 31) == 0) red[tid >> 5] = s;
    __syncthreads();
    float tot = 0.f;
#pragma unroll
    for (int i = 0; i < 8; i++) tot += red[i];
    float r = rsqrtf(tot * (1.f/1024.f) + 1e-6f);
    uint32_t h0,l0,h1,l1;
    split2(v.x*r, v.y*r, h0, l0);
    split2(v.z*r, v.w*r, h1, l1);
    size_t base = (size_t)n * 1024 + tid * 4;
    *(uint2*)(hi + base) = make_uint2(h0, h1);
    *(uint2*)(lo + base) = make_uint2(l0, l1);
}

// ---------------- qkv prep ----------------
__global__ void qkvprep_kernel(const float* __restrict__ qkv,
                               __nv_bfloat16* __restrict__ qh, __nv_bfloat16* __restrict__ ql,
                               __nv_bfloat16* __restrict__ kh, __nv_bfloat16* __restrict__ kl,
                               __nv_bfloat16* __restrict__ vh, __nv_bfloat16* __restrict__ vl,
                               const float* __restrict__ qg, const float* __restrict__ kg)
{
    int gt = blockIdx.x * blockDim.x + threadIdx.x;
    int w = gt >> 5, lane = gt & 31;
    if (w < 81920) {
        const float* src; float gain; int t; __nv_bfloat16 *dh, *dl; size_t dbase;
        if (w < 65536) {
            int n = w >> 4, h = w & 15;
            src = qkv + (size_t)n * 1536 + h * 64;
            gain = qg[h]; t = n & 2047;
            dbase = ((size_t)((n >> 11) * 16 + h) * 2048 + t) * 64;
            dh = qh; dl = ql;
        } else {
            int w2 = w - 65536;
            int n = w2 >> 2, h = w2 & 3;
            src = qkv + (size_t)n * 1536 + 1024 + h * 64;
            gain = kg[h]; t = n & 2047;
            dbase = ((size_t)((n >> 11) * 4 + h) * 2048 + t) * 64;
            dh = kh; dl = kl;
        }
        float v1 = src[lane], v2 = src[lane + 32];
        float s = v1*v1 + v2*v2;
#pragma unroll
        for (int off = 16; off > 0; off >>= 1) s += __shfl_xor_sync(0xffffffffu, s, off);
        float r = rsqrtf(s * (1.f/64.f) + 1e-6f) * gain;
        v1 *= r; v2 *= r;
        float freq = exp2f(-0.41524101186092029f * (float)lane);
        float ang = (float)t * freq;
        float sn, cs;
        sincosf(ang, &sn, &cs);
        float o1 = v1 * cs + v2 * sn;
        float o2 = v2 * cs - v1 * sn;
        __nv_bfloat16 hb1 = __float2bfloat16_rn(o1);
        __nv_bfloat16 lb1 = __float2bfloat16_rn(o1 - __bfloat162float(hb1));
        __nv_bfloat16 hb2 = __float2bfloat16_rn(o2);
        __nv_bfloat16 lb2 = __float2bfloat16_rn(o2 - __bfloat162float(hb2));
        dh[dbase + lane] = hb1; dl[dbase + lane] = lb1;
        dh[dbase + lane + 32] = hb2; dl[dbase + lane + 32] = lb2;
    } else {
        int w2 = w - 81920;
        int n = w2 >> 2, h = w2 & 3;
        const float* src = qkv + (size_t)n * 1536 + 1280 + h * 64;
        int t = n & 2047;
        size_t dbase = ((size_t)((n >> 11) * 4 + h) * 2048 + t) * 64;
        float v1 = src[lane], v2 = src[lane + 32];
        __nv_bfloat16 hb1 = __float2bfloat16_rn(v1);
        __nv_bfloat16 lb1 = __float2bfloat16_rn(v1 - __bfloat162float(hb1));
        __nv_bfloat16 hb2 = __float2bfloat16_rn(v2);
        __nv_bfloat16 lb2 = __float2bfloat16_rn(v2 - __bfloat162float(hb2));
        vh[dbase + lane] = hb1; vl[dbase + lane] = lb1;
        vh[dbase + lane + 32] = hb2; vl[dbase + lane + 32] = lb2;
    }
}

// ---------------- tensor-core flash attention (bf16x3) ----------------
#define AT_ROWB 144
#define AT_TILE (64 * AT_ROWB)
#define AT_STAGE (4 * AT_TILE)
#define ATTN_SMEM (2 * AT_TILE + 2 * AT_STAGE)

__device__ __forceinline__ void attn_load_kv(
    uint32_t dstbase, int tid,
    const __nv_bfloat16* kh, const __nv_bfloat16* kl,
    const __nv_bfloat16* vh, const __nv_bfloat16* vl,
    size_t kvoff, int kt)
{
    const __nv_bfloat16* srcs[4] = {kh, kl, vh, vl};
#pragma unroll
    for (int t = 0; t < 16; t++) {
        int idx = tid + 128 * t;
        int buf = idx >> 9, cc = idx & 511, row = cc >> 3, ch = cc & 7;
        const __nv_bfloat16* src = srcs[buf] + kvoff + (size_t)(kt * 64 + row) * 64 + ch * 8;
        CP_ASYNC16(dstbase + buf * AT_TILE + row * AT_ROWB + ch * 16, src);
    }
}

__global__ __launch_bounds__(128) void attn_mma_kernel(
    const __nv_bfloat16* __restrict__ qh, const __nv_bfloat16* __restrict__ ql,
    const __nv_bfloat16* __restrict__ kh, const __nv_bfloat16* __restrict__ kl,
    const __nv_bfloat16* __restrict__ vh, const __nv_bfloat16* __restrict__ vl,
    __nv_bfloat16* __restrict__ yh, __nv_bfloat16* __restrict__ yl)
{
    extern __shared__ char smem[];
    uint32_t sb = smem_u32(smem);
    int qt = gridDim.x - 1 - blockIdx.x;     // heavy tiles first
    int h = blockIdx.y, b = blockIdx.z;
    int tid = threadIdx.x, w = tid >> 5, lane = tid & 31;
    int lr = lane & 7, lt = lane >> 3;
    size_t qoff = ((size_t)(b * 16 + h) * 2048 + qt * 64) * 64;
    size_t kvoff = (size_t)(b * 4 + (h >> 2)) * 2048 * 64;

#pragma unroll
    for (int t = 0; t < 8; t++) {
        int idx = tid + 128 * t;
        int buf = idx >> 9, cc = idx & 511, row = cc >> 3, ch = cc & 7;
        const __nv_bfloat16* src = (buf ? ql : qh) + qoff + row * 64 + ch * 8;
        CP_ASYNC16(sb + buf * AT_TILE + row * AT_ROWB + ch * 16, src);
    }
    CP_COMMIT();
    attn_load_kv(sb + 2 * AT_TILE, tid, kh, kl, vh, vl, kvoff, 0);
    CP_COMMIT();
    CP_WAIT0();
    __syncthreads();

    uint32_t qfh[4][4], qfl[4][4];
#pragma unroll
    for (int kk = 0; kk < 4; kk++) {
        uint32_t addr = sb + (w * 16 + lr + (lt & 1) * 8) * AT_ROWB + (kk * 16 + (lt >> 1) * 8) * 2;
        LDSM_X4(qfh[kk], addr);
        LDSM_X4(qfl[kk], addr + AT_TILE);
    }

    float O[8][4];
#pragma unroll
    for (int j = 0; j < 8; j++)
#pragma unroll
        for (int r = 0; r < 4; r++) O[j][r] = 0.f;
    float m0 = -1e30f, m1 = -1e30f, l0 = 0.f, l1 = 0.f;

    for (int kt = 0; kt <= qt; kt++) {
        if (kt < qt) {
            attn_load_kv(sb + 2 * AT_TILE + ((kt + 1) & 1) * AT_STAGE, tid, kh, kl, vh, vl, kvoff, kt + 1);
            CP_COMMIT();
        }
        uint32_t kb = sb + 2 * AT_TILE + (kt & 1) * AT_STAGE;
        float c[8][4];
#pragma unroll
        for (int j = 0; j < 8; j++)
#pragma unroll
            for (int r = 0; r < 4; r++) c[j][r] = 0.f;
#pragma unroll
        for (int kk = 0; kk < 4; kk++) {
            uint32_t kbh[4][4], kbl[4][4];
#pragma unroll
            for (int j2 = 0; j2 < 4; j2++) {
                uint32_t addr = kb + (j2 * 16 + lr + (lt >> 1) * 8) * AT_ROWB + (kk * 16 + (lt & 1) * 8) * 2;
                LDSM_X4(kbh[j2], addr);
                LDSM_X4(kbl[j2], addr + AT_TILE);
            }
#pragma unroll
            for (int j = 0; j < 8; j++) {
                uint32_t bh0 = kbh[j >> 1][(j & 1) * 2], bh1 = kbh[j >> 1][(j & 1) * 2 + 1];
                uint32_t bl0 = kbl[j >> 1][(j & 1) * 2], bl1 = kbl[j >> 1][(j & 1) * 2 + 1];
                MMA_BF16(c[j], qfh[kk], bh0, bh1);
                MMA_BF16(c[j], qfh[kk], bl0, bl1);
                MMA_BF16(c[j], qfl[kk], bh0, bh1);
            }
        }
        if (kt == qt) {
            int r0 = w * 16 + (lane >> 2), r1 = r0 + 8;
#pragma unroll
            for (int j = 0; j < 8; j++) {
                int col = j * 8 + (lane & 3) * 2;
                if (col     > r0) c[j][0] = -1e30f;
                if (col + 1 > r0) c[j][1] = -1e30f;
                if (col     > r1) c[j][2] = -1e30f;
                if (col + 1 > r1) c[j][3] = -1e30f;
            }
        }
        float mx0 = -1e30f, mx1 = -1e30f;
#pragma unroll
        for (int j = 0; j < 8; j++) {
            mx0 = fmaxf(mx0, fmaxf(c[j][0], c[j][1]));
            mx1 = fmaxf(mx1, fmaxf(c[j][2], c[j][3]));
        }
        mx0 *= 0.125f; mx1 *= 0.125f;
        mx0 = fmaxf(mx0, __shfl_xor_sync(0xffffffffu, mx0, 1));
        mx0 = fmaxf(mx0, __shfl_xor_sync(0xffffffffu, mx0, 2));
        mx1 = fmaxf(mx1, __shfl_xor_sync(0xffffffffu, mx1, 1));
        mx1 = fmaxf(mx1, __shfl_xor_sync(0xffffffffu, mx1, 2));
        float m0n = fmaxf(m0, mx0), m1n = fmaxf(m1, mx1);
        float cr0 = __expf(m0 - m0n), cr1 = __expf(m1 - m1n);
        float s0 = 0.f, s1 = 0.f;
#pragma unroll
        for (int j = 0; j < 8; j++) {
            c[j][0] = __expf(fmaf(c[j][0], 0.125f, -m0n)); s0 += c[j][0];
            c[j][1] = __expf(fmaf(c[j][1], 0.125f, -m0n)); s0 += c[j][1];
            c[j][2] = __expf(fmaf(c[j][2], 0.125f, -m1n)); s1 += c[j][2];
            c[j][3] = __expf(fmaf(c[j][3], 0.125f, -m1n)); s1 += c[j][3];
        }
        s0 += __shfl_xor_sync(0xffffffffu, s0, 1);
        s0 += __shfl_xor_sync(0xffffffffu, s0, 2);
        s1 += __shfl_xor_sync(0xffffffffu, s1, 1);
        s1 += __shfl_xor_sync(0xffffffffu, s1, 2);
        l0 = l0 * cr0 + s0; l1 = l1 * cr1 + s1;
        m0 = m0n; m1 = m1n;
#pragma unroll
        for (int j = 0; j < 8; j++) {
            O[j][0] *= cr0; O[j][1] *= cr0;
            O[j][2] *= cr1; O[j][3] *= cr1;
        }
#pragma unroll
        for (int kt2 = 0; kt2 < 4; kt2++) {
            uint32_t pah[4], pal[4];
            split2(c[2*kt2][0],   c[2*kt2][1],   pah[0], pal[0]);
            split2(c[2*kt2][2],   c[2*kt2][3],   pah[1], pal[1]);
            split2(c[2*kt2+1][0], c[2*kt2+1][1], pah[2], pal[2]);
            split2(c[2*kt2+1][2], c[2*kt2+1][3], pah[3], pal[3]);
#pragma unroll
            for (int jd = 0; jd < 4; jd++) {
                uint32_t vbh[4], vbl[4];
                uint32_t addr = kb + 2 * AT_TILE + (kt2 * 16 + (lt & 1) * 8 + lr) * AT_ROWB + (jd * 16 + (lt >> 1) * 8) * 2;
                LDSM_X4_T(vbh, addr);
                LDSM_X4_T(vbl, addr + AT_TILE);
#pragma unroll
                for (int js = 0; js < 2; js++) {
                    int j = jd * 2 + js;
                    MMA_BF16(O[j], pah, vbh[js*2], vbh[js*2+1]);
                    MMA_BF16(O[j], pah, vbl[js*2], vbl[js*2+1]);
                    MMA_BF16(O[j], pal, vbh[js*2], vbh[js*2+1]);
                }
            }
        }
        if (kt < qt) CP_WAIT0();
        __syncthreads();
    }
    float i0 = 1.f / l0, i1 = 1.f / l1;
    size_t rA = (size_t)(b * 2048 + qt * 64 + w * 16 + (lane >> 2));
    size_t rB = rA + 8;
    int colb = h * 64 + (lane & 3) * 2;
#pragma unroll
    for (int j = 0; j < 8; j++) {
        uint32_t hh, ll;
        int col = colb + j * 8;
        split2(O[j][0] * i0, O[j][1] * i0, hh, ll);
        *(uint32_t*)(yh + rA * 1024 + col) = hh;
        *(uint32_t*)(yl + rA * 1024 + col) = ll;
        split2(O[j][2] * i1, O[j][3] * i1, hh, ll);
        *(uint32_t*)(yh + rB * 1024 + col) = hh;
        *(uint32_t*)(yl + rB * 1024 + col) = ll;
    }
}

// ---------------- tile helpers for folding kernels ----------------
#define TP 68
__device__ __forceinline__ void load_tile_s(float* dst, const float* src, size_t stride, int tid) {
#pragma unroll
    for (int r = 0; r < 4; r++) {
        int f = tid + 256 * r;
        int row = f >> 4, c4 = (f & 15) << 2;
        *(float4*)&dst[row*TP + c4] = *(const float4*)(src + (size_t)row * stride + c4);
    }
}
__device__ __forceinline__ void load_tileT_s(float* dst, const float* src, size_t stride, int tid) {
#pragma unroll
    for (int r = 0; r < 4; r++) {
        int f = tid + 256 * r;
        int row = f >> 4, c4 = (f & 15) << 2;
        float4 v = *(const float4*)(src + (size_t)row * stride + c4);
        dst[(c4+0)*TP + row] = v.x; dst[(c4+1)*TP + row] = v.y;
        dst[(c4+2)*TP + row] = v.z; dst[(c4+3)*TP + row] = v.w;
    }
}
__device__ __forceinline__ void mm64(const float* XT, const float* W, float acc[4][4], int tx, int ty) {
#pragma unroll
    for (int c = 0; c < 64; c++) {
        float a[4], bb[4];
        *(float4*)a  = *(const float4*)&XT[c*TP + ty*4];
        *(float4*)bb = *(const float4*)&W [c*TP + tx*4];
#pragma unroll
        for (int i = 0; i < 4; i++)
#pragma unroll
            for (int j = 0; j < 4; j++) acc[i][j] = fmaf(a[i], bb[j], acc[i][j]);
    }
}

// ---------------- P1: fold s2 into mix ----------------
__global__ __launch_bounds__(256) void fold1_kernel(
    const float* __restrict__ Mix, const float* __restrict__ S2,
    float* __restrict__ WM2T, int in_f, int out_f,
    const int* __restrict__ selp)
{
    extern __shared__ float sm[];
    float* MT = sm;
    float* S  = sm + 4352;
    int jb = blockIdx.x, G = blockIdx.y, r = blockIdx.z;
    int sel = selp[r];
    int tid = threadIdx.x;
    load_tile_s(MT, Mix + (size_t)sel * out_f * in_f + (size_t)(G * 64) * in_f + jb * 64, in_f, tid);
    load_tile_s(S,  S2  + (size_t)sel * out_f * 64 + (size_t)G * 4096, 64, tid);
    __syncthreads();
    int tx = tid & 15, ty = tid >> 4;
    float acc[4][4] = {};
    mm64(MT, S, acc, tx, ty);
    float* outp = WM2T + (size_t)r * in_f * out_f;
#pragma unroll
    for (int i = 0; i < 4; i++) {
        size_t row = (size_t)(jb * 64 + ty * 4 + i);
        *(float4*)(outp + row * out_f + G * 64 + tx * 4) =
            make_float4(acc[i][0], acc[i][1], acc[i][2], acc[i][3]);
    }
}

// ---------------- P2: fold s1 + roll-perm, combine experts, split bf16 ----------------
__global__ __launch_bounds__(256) void fold2_kernel(
    const float* __restrict__ WM2T, const float* __restrict__ S1,
    __nv_bfloat16* __restrict__ WH, __nv_bfloat16* __restrict__ WL,
    int in_f, int out_f, int n_in,
    const int* __restrict__ selp, const float* __restrict__ coefp)
{
    extern __shared__ float sm[];
    float* G0 = sm;
    float* G1 = sm + 4352;
    float* T0 = sm + 8704;
    float* T1 = sm + 13056;
    int g = blockIdx.x, Ob = blockIdx.y, tid = threadIdx.x;
    int s0i = selp[0], s1i = selp[1];
    int gs0 = (g + s0i) % n_in, gs1 = (g + s1i) % n_in;
    const float* W0 = WM2T;
    const float* W1 = WM2T + (size_t)in_f * out_f;
#pragma unroll
    for (int r = 0; r < 4; r++) {
        int f = tid + 256 * r;
        int d = f >> 4, o4 = (f & 15) << 2;
        *(float4*)&G0[d*TP + o4] = *(const float4*)(W0 + (size_t)(d * n_in + gs0) * out_f + Ob * 64 + o4);
        *(float4*)&G1[d*TP + o4] = *(const float4*)(W1 + (size_t)(d * n_in + gs1) * out_f + Ob * 64 + o4);
    }
    load_tileT_s(T0, S1 + (size_t)s0i * in_f * 64 + (size_t)g * 4096, 64, tid);
    load_tileT_s(T1, S1 + (size_t)s1i * in_f * 64 + (size_t)g * 4096, 64, tid);
    __syncthreads();
    int tx = tid & 15, ty = tid >> 4;
    float a0[4][4] = {}, a1[4][4] = {};
    mm64(G0, T0, a0, tx, ty);
    mm64(G1, T1, a1, tx, ty);
    float c0 = coefp[0], c1 = coefp[1];
#pragma unroll
    for (int i = 0; i < 4; i++) {
        size_t base = (size_t)(Ob * 64 + ty * 4 + i) * in_f + g * 64 + tx * 4;
        float v0 = c0 * a0[i][0] + c1 * a1[i][0];
        float v1 = c0 * a0[i][1] + c1 * a1[i][1];
        float v2 = c0 * a0[i][2] + c1 * a1[i][2];
        float v3 = c0 * a0[i][3] + c1 * a1[i][3];
        uint32_t hh, ll;
        split2(v0, v1, hh, ll);
        *(uint32_t*)(WH + base) = hh; *(uint32_t*)(WL + base) = ll;
        split2(v2, v3, hh, ll);
        *(uint32_t*)(WH + base + 2) = hh; *(uint32_t*)(WL + base + 2) = ll;
    }
}

// ---------------- top-2 router ----------------
__global__ void router_kernel(const float* __restrict__ fcl, const float* __restrict__ pjl,
                              int* __restrict__ sel, float* __restrict__ coef)
{
    if (threadIdx.x == 0 && blockIdx.x == 0) {
#pragma unroll
        for (int s = 0; s < 2; s++) {
            const float* L = s ? pjl : fcl;
            int i1 = 0; float v1 = L[0];
            for (int i = 1; i < 8; i++) if (L[i] > v1) { v1 = L[i]; i1 = i; }
            int i2 = -1; float v2 = -1e30f;
            for (int i = 0; i < 8; i++) if (i != i1 && L[i] > v2) { v2 = L[i]; i2 = i; }
            float e = expf(v2 - v1);
            float z = 1.f + e;
            sel[s*2+0] = i1; sel[s*2+1] = i2;
            coef[s*2+0] = 1.f / z; coef[s*2+1] = e / z;
        }
    }
}

// ---------------- host orchestration ----------------
#define FOLD1_SMEM (8704 * 4)
#define FOLD2_SMEM (17408 * 4)

extern "C" void kernel_launch(void* const* d_in, const int* in_sizes, int n_in_,
                              void* d_out, int out_size)
{
    (void)in_sizes; (void)n_in_; (void)out_size;
    const float* x      = (const float*)d_in[0];
    const float* wq     = (const float*)d_in[1];
    const float* wk     = (const float*)d_in[2];
    const float* wv     = (const float*)d_in[3];
    const float* wo     = (const float*)d_in[4];
    const float* qg     = (const float*)d_in[5];
    const float* kg     = (const float*)d_in[6];
    const float* fc_s1  = (const float*)d_in[7];
    const float* fc_s2  = (const float*)d_in[8];
    const float* fc_mix = (const float*)d_in[9];
    const float* fc_lg  = (const float*)d_in[10];
    const float* pj_s1  = (const float*)d_in[11];
    const float* pj_s2  = (const float*)d_in[12];
    const float* pj_mix = (const float*)d_in[13];
    const float* pj_lg  = (const float*)d_in[14];

    float *qkv, *x2, *wm0, *wm1, *coef;
    int* sel;
    __nv_bfloat16 *ah, *al, *gh, *gl, *wh, *wl, *wfch, *wfcl, *wpjh, *wpjl;
    __nv_bfloat16 *qh, *ql, *kh, *kl, *vh, *vl, *yh, *yl;
    cudaGetSymbolAddress((void**)&qkv, g_qkv);
    cudaGetSymbolAddress((void**)&x2,  g_x2);
    cudaGetSymbolAddress((void**)&wm0, g_wm0);
    cudaGetSymbolAddress((void**)&wm1, g_wm1);
    cudaGetSymbolAddress((void**)&sel,  g_sel);
    cudaGetSymbolAddress((void**)&coef, g_coef);
    cudaGetSymbolAddress((void**)&ah, g_ah);
    cudaGetSymbolAddress((void**)&al, g_al);
    cudaGetSymbolAddress((void**)&gh, g_gh);
    cudaGetSymbolAddress((void**)&gl, g_gl);
    cudaGetSymbolAddress((void**)&wh, g_wh);
    cudaGetSymbolAddress((void**)&wl, g_wl);
    cudaGetSymbolAddress((void**)&wfch, g_wfch);
    cudaGetSymbolAddress((void**)&wfcl, g_wfcl);
    cudaGetSymbolAddress((void**)&wpjh, g_wpjh);
    cudaGetSymbolAddress((void**)&wpjl, g_wpjl);
    cudaGetSymbolAddress((void**)&qh, g_qh);
    cudaGetSymbolAddress((void**)&ql, g_ql);
    cudaGetSymbolAddress((void**)&kh, g_kh);
    cudaGetSymbolAddress((void**)&kl, g_kl);
    cudaGetSymbolAddress((void**)&vh, g_vh);
    cudaGetSymbolAddress((void**)&vl, g_vl);
    cudaGetSymbolAddress((void**)&yh, g_yh);
    cudaGetSymbolAddress((void**)&yl, g_yl);

    cudaFuncSetAttribute(gemm_bf16x3, cudaFuncAttributeMaxDynamicSharedMemorySize, GEMM_SMEM);
    cudaFuncSetAttribute(attn_mma_kernel, cudaFuncAttributeMaxDynamicSharedMemorySize, ATTN_SMEM);
    cudaFuncSetAttribute(fold1_kernel, cudaFuncAttributeMaxDynamicSharedMemorySize, FOLD1_SMEM);
    cudaFuncSetAttribute(fold2_kernel, cudaFuncAttributeMaxDynamicSharedMemorySize, FOLD2_SMEM);

    // routing + weight folding (independent of activations)
    router_kernel<<<1, 32>>>(fc_lg, pj_lg, sel, coef);
    fold1_kernel<<<dim3(16, 64, 2), 256, FOLD1_SMEM>>>(fc_mix, fc_s2, wm0, 1024, 4096, sel);
    fold2_kernel<<<dim3(16, 64), 256, FOLD2_SMEM>>>(wm0, fc_s1, wfch, wfcl, 1024, 4096, 16, sel, coef);
    fold1_kernel<<<dim3(64, 16, 2), 256, FOLD1_SMEM>>>(pj_mix, pj_s2, wm1, 4096, 1024, sel + 2);
    fold2_kernel<<<dim3(64, 16), 256, FOLD2_SMEM>>>(wm1, pj_s1, wpjh, wpjl, 4096, 1024, 64, sel + 2, coef + 2);

    // x1 = rms_norm(x) -> split bf16
    rmsnorm_split_kernel<<<4096, 256>>>(x, ah, al);

    // packed QKV projection
    split_kernel<<<512, 256>>>(wq, wh, wl, 1048576);
    split_kernel<<<128, 256>>>(wk, wh + 1048576, wl + 1048576, 262144);
    split_kernel<<<128, 256>>>(wv, wh + 1310720, wl + 1310720, 262144);
    gemm_bf16x3<<<dim3(12, 32), 256, GEMM_SMEM>>>(ah, al, wh, wl, qkv, nullptr, 1536, 1024, nullptr, nullptr);
    qkvprep_kernel<<<12288, 256>>>(qkv, qh, ql, kh, kl, vh, vl, qg, kg);

    // attention
    attn_mma_kernel<<<dim3(32, 16, 2), 128, ATTN_SMEM>>>(qh, ql, kh, kl, vh, vl, yh, yl);

    // x2 = x + y @ wo^T
    split_kernel<<<512, 256>>>(wo, wh, wl, 1048576);
    gemm_bf16x3<<<dim3(8, 32), 256, GEMM_SMEM>>>(yh, yl, wh, wl, x2, x, 1024, 1024, nullptr, nullptr);

    // h = rms_norm(x2) -> split
    rmsnorm_split_kernel<<<4096, 256>>>(x2, ah, al);

    // fc bank (folded): h = relu(ah@Wfc^T)^2 -> split bf16
    gemm_bf16x3<<<dim3(32, 32), 256, GEMM_SMEM>>>(ah, al, wfch, wfcl, nullptr, nullptr, 4096, 1024, gh, gl);
    // pj bank (folded): out = x2 + h@Wpj^T
    gemm_bf16x3<<<dim3(8, 32), 256, GEMM_SMEM>>>(gh, gl, wpjh, wpjl, (float*)d_out, x2, 1024, 4096, nullptr, nullptr);
}

// round 8
// speedup vs baseline: 6.7652x; 1.2700x over previous
#include <cuda_runtime.h>
#include <cuda_bf16.h>
#include <cuda_fp16.h>
#include <math.h>
#include <stdint.h>

// ---------------- static device scratch ----------------
static __device__ float g_x2 [4096*1024];
static __device__ float g_wm0[8388608];
static __device__ float g_wm1[8388608];
static __device__ int   g_sel[4];
static __device__ float g_coef[4];
static __device__ __half g_ah[4194304];
static __device__ __half g_al[4194304];
static __device__ __half g_gh[16777216];
static __device__ __half g_gl[16777216];
static __device__ __half g_wh[4194304];      // qkv/wo weight hi
static __device__ __half g_wfch[4194304];    // folded fc weight hi
static __device__ __half g_wpjh[4194304];    // folded pj weight hi
static __device__ __half g_yh[4194304];
static __device__ __half g_yl[4194304];
static __device__ __nv_bfloat16 g_qh[4194304];
static __device__ __nv_bfloat16 g_ql[4194304];
static __device__ __nv_bfloat16 g_kh[1048576];
static __device__ __nv_bfloat16 g_kl[1048576];
static __device__ __nv_bfloat16 g_vh[1048576];
static __device__ __nv_bfloat16 g_vl[1048576];

// ---------------- PTX helpers ----------------
__device__ __forceinline__ uint32_t smem_u32(const void* p) {
    uint32_t a;
    asm("{ .reg .u64 t; cvta.to.shared.u64 t, %1; cvt.u32.u64 %0, t; }" : "=r"(a) : "l"(p));
    return a;
}
#define CP_ASYNC16(dst, src) \
    asm volatile("cp.async.cg.shared.global [%0], [%1], 16;" :: "r"(dst), "l"(src))
#define CP_COMMIT() asm volatile("cp.async.commit_group;" ::: "memory")
#define CP_WAIT1()  asm volatile("cp.async.wait_group 1;" ::: "memory")
#define CP_WAIT0()  asm volatile("cp.async.wait_group 0;" ::: "memory")

#define LDSM_X4(r, addr) \
    asm volatile("ldmatrix.sync.aligned.m8n8.x4.shared.b16 {%0,%1,%2,%3}, [%4];" \
        : "=r"((r)[0]), "=r"((r)[1]), "=r"((r)[2]), "=r"((r)[3]) : "r"(addr))
#define LDSM_X4_T(r, addr) \
    asm volatile("ldmatrix.sync.aligned.m8n8.x4.trans.shared.b16 {%0,%1,%2,%3}, [%4];" \
        : "=r"((r)[0]), "=r"((r)[1]), "=r"((r)[2]), "=r"((r)[3]) : "r"(addr))

#define MMA_BF16(d, a, b0, b1) \
    asm volatile("mma.sync.aligned.m16n8k16.row.col.f32.bf16.bf16.f32 " \
        "{%0,%1,%2,%3}, {%4,%5,%6,%7}, {%8,%9}, {%0,%1,%2,%3};" \
        : "+f"((d)[0]), "+f"((d)[1]), "+f"((d)[2]), "+f"((d)[3]) \
        : "r"((a)[0]), "r"((a)[1]), "r"((a)[2]), "r"((a)[3]), "r"(b0), "r"(b1))
#define MMA_FP16(d, a, b0, b1) \
    asm volatile("mma.sync.aligned.m16n8k16.row.col.f32.f16.f16.f32 " \
        "{%0,%1,%2,%3}, {%4,%5,%6,%7}, {%8,%9}, {%0,%1,%2,%3};" \
        : "+f"((d)[0]), "+f"((d)[1]), "+f"((d)[2]), "+f"((d)[3]) \
        : "r"((a)[0]), "r"((a)[1]), "r"((a)[2]), "r"((a)[3]), "r"(b0), "r"(b1))

// bf16 hi/lo split (attention internals)
__device__ __forceinline__ void split2(float v0, float v1, uint32_t& h, uint32_t& l) {
    __nv_bfloat16 h0 = __float2bfloat16_rn(v0), h1 = __float2bfloat16_rn(v1);
    float r0 = v0 - __bfloat162float(h0), r1 = v1 - __bfloat162float(h1);
    __nv_bfloat16 l0 = __float2bfloat16_rn(r0), l1 = __float2bfloat16_rn(r1);
    h = (uint32_t)*(uint16_t*)&h0 | ((uint32_t)*(uint16_t*)&h1 << 16);
    l = (uint32_t)*(uint16_t*)&l0 | ((uint32_t)*(uint16_t*)&l1 << 16);
}
// fp16 hi/lo split (linear GEMM activations)
__device__ __forceinline__ void split2h(float v0, float v1, uint32_t& h, uint32_t& l) {
    __half h0 = __float2half_rn(v0), h1 = __float2half_rn(v1);
    float r0 = v0 - __half2float(h0), r1 = v1 - __half2float(h1);
    __half l0 = __float2half_rn(r0), l1 = __float2half_rn(r1);
    h = (uint32_t)*(uint16_t*)&h0 | ((uint32_t)*(uint16_t*)&h1 << 16);
    l = (uint32_t)*(uint16_t*)&l0 | ((uint32_t)*(uint16_t*)&l1 << 16);
}
__device__ __forceinline__ uint32_t pack2h(float v0, float v1) {
    __half h0 = __float2half_rn(v0), h1 = __float2half_rn(v1);
    return (uint32_t)*(uint16_t*)&h0 | ((uint32_t)*(uint16_t*)&h1 << 16);
}

// ---------------- fp32 -> fp16 (hi only) weight convert ----------------
__global__ void splith_kernel(const float* __restrict__ src, __half* __restrict__ hi, int n)
{
    int i = (blockIdx.x * blockDim.x + threadIdx.x) * 8;
    if (i >= n) return;
    float4 a = *(const float4*)(src + i);
    float4 b = *(const float4*)(src + i + 4);
    uint4 H;
    H.x = pack2h(a.x, a.y); H.y = pack2h(a.z, a.w);
    H.z = pack2h(b.x, b.y); H.w = pack2h(b.z, b.w);
    *(uint4*)(hi + i) = H;
}

// ---------------- HMMA fp16x2 GEMM: A(hi+lo fp16) x W(hi fp16), 3-stage ----------------
#define TSTA 144
#define TSTW 80
#define A_BYTES (128 * TSTA)        // 18432
#define W_BYTES (128 * TSTW)        // 10240
#define STG (A_BYTES + W_BYTES)     // 28672
#define GEMM_SMEM (3 * STG)         // 86016

__device__ __forceinline__ void gemm_load_stage(
    uint32_t smbase, int kt, int NT, int K, int tid,
    const __half* s0, const __half* s1, const __half* s2)
{
    if (kt < NT) {
        uint32_t sb = smbase + (kt % 3) * STG;
        int k0 = kt * 32;
#pragma unroll
        for (int t = 0; t < 6; t++) {
            int idx = tid + 256 * t;            // 0..1535
            if (idx < 1024) {
                int row = idx >> 3, ch = idx & 7;
                uint32_t dst = sb + row * TSTA + ((ch < 4) ? ch * 16 : 64 + (ch - 4) * 16);
                const __half* src = ((ch < 4) ? s0 : s1) + (size_t)row * K + k0 + (ch & 3) * 8;
                CP_ASYNC16(dst, src);
            } else {
                int cc = idx - 1024;
                int row = cc >> 2, ch = cc & 3;
                uint32_t dst = sb + A_BYTES + row * TSTW + ch * 16;
                CP_ASYNC16(dst, s2 + (size_t)row * K + k0 + ch * 8);
            }
        }
    }
    CP_COMMIT();
}

// mode 0: C fp32 (+res); mode 1: relu^2 -> fp16 split OH/OL; mode 2: fused qkv prep
__global__ __launch_bounds__(256, 2) void gemm_fp16x2(
    const __half* __restrict__ Ah, const __half* __restrict__ Al,
    const __half* __restrict__ Wh,
    float* __restrict__ C, const float* __restrict__ res, int N, int K,
    __half* __restrict__ OH, __half* __restrict__ OL, int mode,
    __nv_bfloat16* __restrict__ qh, __nv_bfloat16* __restrict__ ql,
    __nv_bfloat16* __restrict__ kh, __nv_bfloat16* __restrict__ kl,
    __nv_bfloat16* __restrict__ vh, __nv_bfloat16* __restrict__ vl,
    const float* __restrict__ qg, const float* __restrict__ kg)
{
    extern __shared__ char smem[];
    uint32_t smbase = smem_u32(smem);
    int tid = threadIdx.x, wid = tid >> 5, lane = tid & 31;
    int m0 = blockIdx.y * 128, n0 = blockIdx.x * 128;
    int wm = wid >> 1, wn = wid & 1;

    const __half* s0 = Ah + (size_t)m0 * K;
    const __half* s1 = Al + (size_t)m0 * K;
    const __half* s2 = Wh + (size_t)n0 * K;

    float acc[2][8][4];
#pragma unroll
    for (int i = 0; i < 2; i++)
#pragma unroll
        for (int j = 0; j < 8; j++)
#pragma unroll
            for (int r = 0; r < 4; r++) acc[i][j][r] = 0.f;

    int NT = K >> 5;
    gemm_load_stage(smbase, 0, NT, K, tid, s0, s1, s2);
    gemm_load_stage(smbase, 1, NT, K, tid, s0, s1, s2);

    int lt = lane >> 3, lr = lane & 7;
    for (int kt = 0; kt < NT; kt++) {
        CP_WAIT1();
        __syncthreads();
        gemm_load_stage(smbase, kt + 2, NT, K, tid, s0, s1, s2);
        uint32_t sb = smbase + (kt % 3) * STG;
        uint32_t sbW = sb + A_BYTES;
#pragma unroll
        for (int kk = 0; kk < 2; kk++) {
            uint32_t a_hi[2][4], a_lo[2][4];
#pragma unroll
            for (int i = 0; i < 2; i++) {
                int row = wm * 32 + i * 16 + lr + (lt & 1) * 8;
                int kofs = kk * 16 + (lt >> 1) * 8;
                uint32_t addr = sb + row * TSTA + kofs * 2;
                LDSM_X4(a_hi[i], addr);
                LDSM_X4(a_lo[i], addr + 64);
            }
            uint32_t b_hi[4][4];
#pragma unroll
            for (int j = 0; j < 4; j++) {
                int row = wn * 64 + j * 16 + lr + (lt >> 1) * 8;
                int kofs = kk * 16 + (lt & 1) * 8;
                LDSM_X4(b_hi[j], sbW + row * TSTW + kofs * 2);
            }
#pragma unroll
            for (int i = 0; i < 2; i++)
#pragma unroll
                for (int j = 0; j < 8; j++) {
                    uint32_t bh0 = b_hi[j >> 1][(j & 1) * 2], bh1 = b_hi[j >> 1][(j & 1) * 2 + 1];
                    MMA_FP16(acc[i][j], a_hi[i], bh0, bh1);
                    MMA_FP16(acc[i][j], a_lo[i], bh0, bh1);
                }
        }
    }
    CP_WAIT0();

    int rbase = m0 + wm * 32 + (lane >> 2);
    int cbase = n0 + wn * 64 + (lane & 3) * 2;

    if (mode == 2) {
        // fused per-head RMS*gain + RoPE + bf16 split (q,k) / split (v)
        int hd = blockIdx.x * 2 + wn;    // 0-15 q, 16-19 k, 20-23 v
#pragma unroll
        for (int i = 0; i < 2; i++) {
#pragma unroll
            for (int half = 0; half < 2; half++) {
                int m = rbase + i * 16 + half * 8;
                int t = m & 2047, bb = m >> 11;
                float vals[8][2];
#pragma unroll
                for (int j = 0; j < 8; j++) {
                    vals[j][0] = acc[i][j][half * 2 + 0];
                    vals[j][1] = acc[i][j][half * 2 + 1];
                }
                if (hd < 20) {
                    float ss = 0.f;
#pragma unroll
                    for (int j = 0; j < 8; j++) ss += vals[j][0]*vals[j][0] + vals[j][1]*vals[j][1];
                    ss += __shfl_xor_sync(0xffffffffu, ss, 1);
                    ss += __shfl_xor_sync(0xffffffffu, ss, 2);
                    float gain = (hd < 16) ? qg[hd] : kg[hd - 16];
                    float r = rsqrtf(ss * (1.f/64.f) + 1e-6f) * gain;
                    __nv_bfloat16 *dh, *dl;
                    size_t base;
                    if (hd < 16) { dh = qh; dl = ql; base = ((size_t)(bb * 16 + hd) * 2048 + t) * 64; }
                    else         { dh = kh; dl = kl; base = ((size_t)(bb * 4 + hd - 16) * 2048 + t) * 64; }
#pragma unroll
                    for (int j = 0; j < 4; j++) {
                        float o1[2], o2[2];
#pragma unroll
                        for (int s = 0; s < 2; s++) {
                            int p = (lane & 3) * 2 + j * 8 + s;
                            float ang = (float)t * exp2f(-0.41524101186092029f * (float)p);
                            float sn, cs;
                            sincosf(ang, &sn, &cs);
                            float v1 = vals[j][s] * r, v2 = vals[j + 4][s] * r;
                            o1[s] = v1 * cs + v2 * sn;
                            o2[s] = v2 * cs - v1 * sn;
                        }
                        int c0 = (lane & 3) * 2 + j * 8;
                        uint32_t hh, ll;
                        split2(o1[0], o1[1], hh, ll);
                        *(uint32_t*)(dh + base + c0) = hh;
                        *(uint32_t*)(dl + base + c0) = ll;
                        split2(o2[0], o2[1], hh, ll);
                        *(uint32_t*)(dh + base + c0 + 32) = hh;
                        *(uint32_t*)(dl + base + c0 + 32) = ll;
                    }
                } else {
                    size_t base = ((size_t)(bb * 4 + hd - 20) * 2048 + t) * 64;
#pragma unroll
                    for (int j = 0; j < 8; j++) {
                        int c0 = (lane & 3) * 2 + j * 8;
                        uint32_t hh, ll;
                        split2(vals[j][0], vals[j][1], hh, ll);
                        *(uint32_t*)(vh + base + c0) = hh;
                        *(uint32_t*)(vl + base + c0) = ll;
                    }
                }
            }
        }
        return;
    }

#pragma unroll
    for (int i = 0; i < 2; i++) {
#pragma unroll
        for (int half = 0; half < 2; half++) {
            size_t row = (size_t)(rbase + i * 16 + half * 8);
#pragma unroll
            for (int j = 0; j < 8; j++) {
                size_t idx = row * (size_t)N + cbase + j * 8;
                float v0 = acc[i][j][half * 2 + 0];
                float v1 = acc[i][j][half * 2 + 1];
                if (mode == 1) {
                    v0 = fmaxf(v0, 0.f); v0 *= v0;
                    v1 = fmaxf(v1, 0.f); v1 *= v1;
                    uint32_t hh, ll;
                    split2h(v0, v1, hh, ll);
                    *(uint32_t*)(OH + idx) = hh;
                    *(uint32_t*)(OL + idx) = ll;
                } else {
                    if (res) { v0 += res[idx]; v1 += res[idx + 1]; }
                    *(float2*)(C + idx) = make_float2(v0, v1);
                }
            }
        }
    }
}

// ---------------- RMSNorm with fp16 hi/lo split output ----------------
__global__ void rmsnorm_split_kernel(const float* __restrict__ x,
                                     __half* __restrict__ hi, __half* __restrict__ lo)
{
    int n = blockIdx.x;
    int tid = threadIdx.x;
    const float4* xr = (const float4*)(x + (size_t)n * 1024);
    float4 v = xr[tid];
    float s = v.x*v.x + v.y*v.y + v.z*v.z + v.w*v.w;
#pragma unroll
    for (int off = 16; off > 0; off >>= 1) s += __shfl_xor_sync(0xffffffffu, s, off);
    __shared__ float red[8];
    if ((tid & 31) == 0) red[tid >> 5] = s;
    __syncthreads();
    float tot = 0.f;
#pragma unroll
    for (int i = 0; i < 8; i++) tot += red[i];
    float r = rsqrtf(tot * (1.f/1024.f) + 1e-6f);
    uint32_t h0,l0,h1,l1;
    split2h(v.x*r, v.y*r, h0, l0);
    split2h(v.z*r, v.w*r, h1, l1);
    size_t base = (size_t)n * 1024 + tid * 4;
    *(uint2*)(hi + base) = make_uint2(h0, h1);
    *(uint2*)(lo + base) = make_uint2(l0, l1);
}

// ---------------- tensor-core flash attention (bf16x3 in, fp16 split out) ----------------
#define AT_ROWB 144
#define AT_TILE (64 * AT_ROWB)
#define AT_STAGE (4 * AT_TILE)
#define ATTN_SMEM (2 * AT_TILE + 2 * AT_STAGE)

__device__ __forceinline__ void attn_load_kv(
    uint32_t dstbase, int tid,
    const __nv_bfloat16* kh, const __nv_bfloat16* kl,
    const __nv_bfloat16* vh, const __nv_bfloat16* vl,
    size_t kvoff, int kt)
{
    const __nv_bfloat16* srcs[4] = {kh, kl, vh, vl};
#pragma unroll
    for (int t = 0; t < 16; t++) {
        int idx = tid + 128 * t;
        int buf = idx >> 9, cc = idx & 511, row = cc >> 3, ch = cc & 7;
        const __nv_bfloat16* src = srcs[buf] + kvoff + (size_t)(kt * 64 + row) * 64 + ch * 8;
        CP_ASYNC16(dstbase + buf * AT_TILE + row * AT_ROWB + ch * 16, src);
    }
}

__global__ __launch_bounds__(128) void attn_mma_kernel(
    const __nv_bfloat16* __restrict__ qh, const __nv_bfloat16* __restrict__ ql,
    const __nv_bfloat16* __restrict__ kh, const __nv_bfloat16* __restrict__ kl,
    const __nv_bfloat16* __restrict__ vh, const __nv_bfloat16* __restrict__ vl,
    __half* __restrict__ yh, __half* __restrict__ yl)
{
    extern __shared__ char smem[];
    uint32_t sb = smem_u32(smem);
    int qt = gridDim.x - 1 - blockIdx.x;
    int h = blockIdx.y, b = blockIdx.z;
    int tid = threadIdx.x, w = tid >> 5, lane = tid & 31;
    int lr = lane & 7, lt = lane >> 3;
    size_t qoff = ((size_t)(b * 16 + h) * 2048 + qt * 64) * 64;
    size_t kvoff = (size_t)(b * 4 + (h >> 2)) * 2048 * 64;

#pragma unroll
    for (int t = 0; t < 8; t++) {
        int idx = tid + 128 * t;
        int buf = idx >> 9, cc = idx & 511, row = cc >> 3, ch = cc & 7;
        const __nv_bfloat16* src = (buf ? ql : qh) + qoff + row * 64 + ch * 8;
        CP_ASYNC16(sb + buf * AT_TILE + row * AT_ROWB + ch * 16, src);
    }
    CP_COMMIT();
    attn_load_kv(sb + 2 * AT_TILE, tid, kh, kl, vh, vl, kvoff, 0);
    CP_COMMIT();
    CP_WAIT0();
    __syncthreads();

    uint32_t qfh[4][4], qfl[4][4];
#pragma unroll
    for (int kk = 0; kk < 4; kk++) {
        uint32_t addr = sb + (w * 16 + lr + (lt & 1) * 8) * AT_ROWB + (kk * 16 + (lt >> 1) * 8) * 2;
        LDSM_X4(qfh[kk], addr);
        LDSM_X4(qfl[kk], addr + AT_TILE);
    }

    float O[8][4];
#pragma unroll
    for (int j = 0; j < 8; j++)
#pragma unroll
        for (int r = 0; r < 4; r++) O[j][r] = 0.f;
    float m0 = -1e30f, m1 = -1e30f, l0 = 0.f, l1 = 0.f;

    for (int kt = 0; kt <= qt; kt++) {
        if (kt < qt) {
            attn_load_kv(sb + 2 * AT_TILE + ((kt + 1) & 1) * AT_STAGE, tid, kh, kl, vh, vl, kvoff, kt + 1);
            CP_COMMIT();
        }
        uint32_t kb = sb + 2 * AT_TILE + (kt & 1) * AT_STAGE;
        float c[8][4];
#pragma unroll
        for (int j = 0; j < 8; j++)
#pragma unroll
            for (int r = 0; r < 4; r++) c[j][r] = 0.f;
#pragma unroll
        for (int kk = 0; kk < 4; kk++) {
            uint32_t kbh[4][4], kbl[4][4];
#pragma unroll
            for (int j2 = 0; j2 < 4; j2++) {
                uint32_t addr = kb + (j2 * 16 + lr + (lt >> 1) * 8) * AT_ROWB + (kk * 16 + (lt & 1) * 8) * 2;
                LDSM_X4(kbh[j2], addr);
                LDSM_X4(kbl[j2], addr + AT_TILE);
            }
#pragma unroll
            for (int j = 0; j < 8; j++) {
                uint32_t bh0 = kbh[j >> 1][(j & 1) * 2], bh1 = kbh[j >> 1][(j & 1) * 2 + 1];
                uint32_t bl0 = kbl[j >> 1][(j & 1) * 2], bl1 = kbl[j >> 1][(j & 1) * 2 + 1];
                MMA_BF16(c[j], qfh[kk], bh0, bh1);
                MMA_BF16(c[j], qfh[kk], bl0, bl1);
                MMA_BF16(c[j], qfl[kk], bh0, bh1);
            }
        }
        if (kt == qt) {
            int r0 = w * 16 + (lane >> 2), r1 = r0 + 8;
#pragma unroll
            for (int j = 0; j < 8; j++) {
                int col = j * 8 + (lane & 3) * 2;
                if (col     > r0) c[j][0] = -1e30f;
                if (col + 1 > r0) c[j][1] = -1e30f;
                if (col     > r1) c[j][2] = -1e30f;
                if (col + 1 > r1) c[j][3] = -1e30f;
            }
        }
        float mx0 = -1e30f, mx1 = -1e30f;
#pragma unroll
        for (int j = 0; j < 8; j++) {
            mx0 = fmaxf(mx0, fmaxf(c[j][0], c[j][1]));
            mx1 = fmaxf(mx1, fmaxf(c[j][2], c[j][3]));
        }
        mx0 *= 0.125f; mx1 *= 0.125f;
        mx0 = fmaxf(mx0, __shfl_xor_sync(0xffffffffu, mx0, 1));
        mx0 = fmaxf(mx0, __shfl_xor_sync(0xffffffffu, mx0, 2));
        mx1 = fmaxf(mx1, __shfl_xor_sync(0xffffffffu, mx1, 1));
        mx1 = fmaxf(mx1, __shfl_xor_sync(0xffffffffu, mx1, 2));
        float m0n = fmaxf(m0, mx0), m1n = fmaxf(m1, mx1);
        float cr0 = __expf(m0 - m0n), cr1 = __expf(m1 - m1n);
        float s0 = 0.f, s1 = 0.f;
#pragma unroll
        for (int j = 0; j < 8; j++) {
            c[j][0] = __expf(fmaf(c[j][0], 0.125f, -m0n)); s0 += c[j][0];
            c[j][1] = __expf(fmaf(c[j][1], 0.125f, -m0n)); s0 += c[j][1];
            c[j][2] = __expf(fmaf(c[j][2], 0.125f, -m1n)); s1 += c[j][2];
            c[j][3] = __expf(fmaf(c[j][3], 0.125f, -m1n)); s1 += c[j][3];
        }
        s0 += __shfl_xor_sync(0xffffffffu, s0, 1);
        s0 += __shfl_xor_sync(0xffffffffu, s0, 2);
        s1 += __shfl_xor_sync(0xffffffffu, s1, 1);
        s1 += __shfl_xor_sync(0xffffffffu, s1, 2);
        l0 = l0 * cr0 + s0; l1 = l1 * cr1 + s1;
        m0 = m0n; m1 = m1n;
#pragma unroll
        for (int j = 0; j < 8; j++) {
            O[j][0] *= cr0; O[j][1] *= cr0;
            O[j][2] *= cr1; O[j][3] *= cr1;
        }
#pragma unroll
        for (int kt2 = 0; kt2 < 4; kt2++) {
            uint32_t pah[4], pal[4];
            split2(c[2*kt2][0],   c[2*kt2][1],   pah[0], pal[0]);
            split2(c[2*kt2][2],   c[2*kt2][3],   pah[1], pal[1]);
            split2(c[2*kt2+1][0], c[2*kt2+1][1], pah[2], pal[2]);
            split2(c[2*kt2+1][2], c[2*kt2+1][3], pah[3], pal[3]);
#pragma unroll
            for (int jd = 0; jd < 4; jd++) {
                uint32_t vbh[4], vbl[4];
                uint32_t addr = kb + 2 * AT_TILE + (kt2 * 16 + (lt & 1) * 8 + lr) * AT_ROWB + (jd * 16 + (lt >> 1) * 8) * 2;
                LDSM_X4_T(vbh, addr);
                LDSM_X4_T(vbl, addr + AT_TILE);
#pragma unroll
                for (int js = 0; js < 2; js++) {
                    int j = jd * 2 + js;
                    MMA_BF16(O[j], pah, vbh[js*2], vbh[js*2+1]);
                    MMA_BF16(O[j], pah, vbl[js*2], vbl[js*2+1]);
                    MMA_BF16(O[j], pal, vbh[js*2], vbh[js*2+1]);
                }
            }
        }
        if (kt < qt) CP_WAIT0();
        __syncthreads();
    }
    float i0 = 1.f / l0, i1 = 1.f / l1;
    size_t rA = (size_t)(b * 2048 + qt * 64 + w * 16 + (lane >> 2));
    size_t rB = rA + 8;
    int colb = h * 64 + (lane & 3) * 2;
#pragma unroll
    for (int j = 0; j < 8; j++) {
        uint32_t hh, ll;
        int col = colb + j * 8;
        split2h(O[j][0] * i0, O[j][1] * i0, hh, ll);
        *(uint32_t*)(yh + rA * 1024 + col) = hh;
        *(uint32_t*)(yl + rA * 1024 + col) = ll;
        split2h(O[j][2] * i1, O[j][3] * i1, hh, ll);
        *(uint32_t*)(yh + rB * 1024 + col) = hh;
        *(uint32_t*)(yl + rB * 1024 + col) = ll;
    }
}

// ---------------- tile helpers for folding kernels ----------------
#define TP 68
__device__ __forceinline__ void load_tile_s(float* dst, const float* src, size_t stride, int tid) {
#pragma unroll
    for (int r = 0; r < 4; r++) {
        int f = tid + 256 * r;
        int row = f >> 4, c4 = (f & 15) << 2;
        *(float4*)&dst[row*TP + c4] = *(const float4*)(src + (size_t)row * stride + c4);
    }
}
__device__ __forceinline__ void load_tileT_s(float* dst, const float* src, size_t stride, int tid) {
#pragma unroll
    for (int r = 0; r < 4; r++) {
        int f = tid + 256 * r;
        int row = f >> 4, c4 = (f & 15) << 2;
        float4 v = *(const float4*)(src + (size_t)row * stride + c4);
        dst[(c4+0)*TP + row] = v.x; dst[(c4+1)*TP + row] = v.y;
        dst[(c4+2)*TP + row] = v.z; dst[(c4+3)*TP + row] = v.w;
    }
}
__device__ __forceinline__ void mm64(const float* XT, const float* W, float acc[4][4], int tx, int ty) {
#pragma unroll
    for (int c = 0; c < 64; c++) {
        float a[4], bb[4];
        *(float4*)a  = *(const float4*)&XT[c*TP + ty*4];
        *(float4*)bb = *(const float4*)&W [c*TP + tx*4];
#pragma unroll
        for (int i = 0; i < 4; i++)
#pragma unroll
            for (int j = 0; j < 4; j++) acc[i][j] = fmaf(a[i], bb[j], acc[i][j]);
    }
}

// ---------------- P1: fold s2 into mix ----------------
__global__ __launch_bounds__(256) void fold1_kernel(
    const float* __restrict__ Mix, const float* __restrict__ S2,
    float* __restrict__ WM2T, int in_f, int out_f,
    const int* __restrict__ selp)
{
    extern __shared__ float sm[];
    float* MT = sm;
    float* S  = sm + 4352;
    int jb = blockIdx.x, G = blockIdx.y, r = blockIdx.z;
    int sel = selp[r];
    int tid = threadIdx.x;
    load_tile_s(MT, Mix + (size_t)sel * out_f * in_f + (size_t)(G * 64) * in_f + jb * 64, in_f, tid);
    load_tile_s(S,  S2  + (size_t)sel * out_f * 64 + (size_t)G * 4096, 64, tid);
    __syncthreads();
    int tx = tid & 15, ty = tid >> 4;
    float acc[4][4] = {};
    mm64(MT, S, acc, tx, ty);
    float* outp = WM2T + (size_t)r * in_f * out_f;
#pragma unroll
    for (int i = 0; i < 4; i++) {
        size_t row = (size_t)(jb * 64 + ty * 4 + i);
        *(float4*)(outp + row * out_f + G * 64 + tx * 4) =
            make_float4(acc[i][0], acc[i][1], acc[i][2], acc[i][3]);
    }
}

// ---------------- P2: fold s1 + roll-perm, combine experts, fp16 out ----------------
__global__ __launch_bounds__(256) void fold2_kernel(
    const float* __restrict__ WM2T, const float* __restrict__ S1,
    __half* __restrict__ WH,
    int in_f, int out_f, int n_in,
    const int* __restrict__ selp, const float* __restrict__ coefp)
{
    extern __shared__ float sm[];
    float* G0 = sm;
    float* G1 = sm + 4352;
    float* T0 = sm + 8704;
    float* T1 = sm + 13056;
    int g = blockIdx.x, Ob = blockIdx.y, tid = threadIdx.x;
    int s0i = selp[0], s1i = selp[1];
    int gs0 = (g + s0i) % n_in, gs1 = (g + s1i) % n_in;
    const float* W0 = WM2T;
    const float* W1 = WM2T + (size_t)in_f * out_f;
#pragma unroll
    for (int r = 0; r < 4; r++) {
        int f = tid + 256 * r;
        int d = f >> 4, o4 = (f & 15) << 2;
        *(float4*)&G0[d*TP + o4] = *(const float4*)(W0 + (size_t)(d * n_in + gs0) * out_f + Ob * 64 + o4);
        *(float4*)&G1[d*TP + o4] = *(const float4*)(W1 + (size_t)(d * n_in + gs1) * out_f + Ob * 64 + o4);
    }
    load_tileT_s(T0, S1 + (size_t)s0i * in_f * 64 + (size_t)g * 4096, 64, tid);
    load_tileT_s(T1, S1 + (size_t)s1i * in_f * 64 + (size_t)g * 4096, 64, tid);
    __syncthreads();
    int tx = tid & 15, ty = tid >> 4;
    float a0[4][4] = {}, a1[4][4] = {};
    mm64(G0, T0, a0, tx, ty);
    mm64(G1, T1, a1, tx, ty);
    float c0 = coefp[0], c1 = coefp[1];
#pragma unroll
    for (int i = 0; i < 4; i++) {
        size_t base = (size_t)(Ob * 64 + ty * 4 + i) * in_f + g * 64 + tx * 4;
        float v0 = c0 * a0[i][0] + c1 * a1[i][0];
        float v1 = c0 * a0[i][1] + c1 * a1[i][1];
        float v2 = c0 * a0[i][2] + c1 * a1[i][2];
        float v3 = c0 * a0[i][3] + c1 * a1[i][3];
        *(uint32_t*)(WH + base)     = pack2h(v0, v1);
        *(uint32_t*)(WH + base + 2) = pack2h(v2, v3);
    }
}

// ---------------- top-2 router ----------------
__global__ void router_kernel(const float* __restrict__ fcl, const float* __restrict__ pjl,
                              int* __restrict__ sel, float* __restrict__ coef)
{
    if (threadIdx.x == 0 && blockIdx.x == 0) {
#pragma unroll
        for (int s = 0; s < 2; s++) {
            const float* L = s ? pjl : fcl;
            int i1 = 0; float v1 = L[0];
            for (int i = 1; i < 8; i++) if (L[i] > v1) { v1 = L[i]; i1 = i; }
            int i2 = -1; float v2 = -1e30f;
            for (int i = 0; i < 8; i++) if (i != i1 && L[i] > v2) { v2 = L[i]; i2 = i; }
            float e = expf(v2 - v1);
            float z = 1.f + e;
            sel[s*2+0] = i1; sel[s*2+1] = i2;
            coef[s*2+0] = 1.f / z; coef[s*2+1] = e / z;
        }
    }
}

// ---------------- host orchestration ----------------
#define FOLD1_SMEM (8704 * 4)
#define FOLD2_SMEM (17408 * 4)

extern "C" void kernel_launch(void* const* d_in, const int* in_sizes, int n_in_,
                              void* d_out, int out_size)
{
    (void)in_sizes; (void)n_in_; (void)out_size;
    const float* x      = (const float*)d_in[0];
    const float* wq     = (const float*)d_in[1];
    const float* wk     = (const float*)d_in[2];
    const float* wv     = (const float*)d_in[3];
    const float* wo     = (const float*)d_in[4];
    const float* qg     = (const float*)d_in[5];
    const float* kg     = (const float*)d_in[6];
    const float* fc_s1  = (const float*)d_in[7];
    const float* fc_s2  = (const float*)d_in[8];
    const float* fc_mix = (const float*)d_in[9];
    const float* fc_lg  = (const float*)d_in[10];
    const float* pj_s1  = (const float*)d_in[11];
    const float* pj_s2  = (const float*)d_in[12];
    const float* pj_mix = (const float*)d_in[13];
    const float* pj_lg  = (const float*)d_in[14];

    float *x2, *wm0, *wm1, *coef;
    int* sel;
    __half *ah, *al, *gh, *gl, *wh, *wfch, *wpjh, *yh, *yl;
    __nv_bfloat16 *qh, *ql, *kh, *kl, *vh, *vl;
    cudaGetSymbolAddress((void**)&x2,  g_x2);
    cudaGetSymbolAddress((void**)&wm0, g_wm0);
    cudaGetSymbolAddress((void**)&wm1, g_wm1);
    cudaGetSymbolAddress((void**)&sel,  g_sel);
    cudaGetSymbolAddress((void**)&coef, g_coef);
    cudaGetSymbolAddress((void**)&ah, g_ah);
    cudaGetSymbolAddress((void**)&al, g_al);
    cudaGetSymbolAddress((void**)&gh, g_gh);
    cudaGetSymbolAddress((void**)&gl, g_gl);
    cudaGetSymbolAddress((void**)&wh, g_wh);
    cudaGetSymbolAddress((void**)&wfch, g_wfch);
    cudaGetSymbolAddress((void**)&wpjh, g_wpjh);
    cudaGetSymbolAddress((void**)&yh, g_yh);
    cudaGetSymbolAddress((void**)&yl, g_yl);
    cudaGetSymbolAddress((void**)&qh, g_qh);
    cudaGetSymbolAddress((void**)&ql, g_ql);
    cudaGetSymbolAddress((void**)&kh, g_kh);
    cudaGetSymbolAddress((void**)&kl, g_kl);
    cudaGetSymbolAddress((void**)&vh, g_vh);
    cudaGetSymbolAddress((void**)&vl, g_vl);

    cudaFuncSetAttribute(gemm_fp16x2, cudaFuncAttributeMaxDynamicSharedMemorySize, GEMM_SMEM);
    cudaFuncSetAttribute(attn_mma_kernel, cudaFuncAttributeMaxDynamicSharedMemorySize, ATTN_SMEM);
    cudaFuncSetAttribute(fold1_kernel, cudaFuncAttributeMaxDynamicSharedMemorySize, FOLD1_SMEM);
    cudaFuncSetAttribute(fold2_kernel, cudaFuncAttributeMaxDynamicSharedMemorySize, FOLD2_SMEM);

    // routing + weight folding
    router_kernel<<<1, 32>>>(fc_lg, pj_lg, sel, coef);
    fold1_kernel<<<dim3(16, 64, 2), 256, FOLD1_SMEM>>>(fc_mix, fc_s2, wm0, 1024, 4096, sel);
    fold2_kernel<<<dim3(16, 64), 256, FOLD2_SMEM>>>(wm0, fc_s1, wfch, 1024, 4096, 16, sel, coef);
    fold1_kernel<<<dim3(64, 16, 2), 256, FOLD1_SMEM>>>(pj_mix, pj_s2, wm1, 4096, 1024, sel + 2);
    fold2_kernel<<<dim3(64, 16), 256, FOLD2_SMEM>>>(wm1, pj_s1, wpjh, 4096, 1024, 64, sel + 2, coef + 2);

    // x1 = rms_norm(x) -> fp16 split
    rmsnorm_split_kernel<<<4096, 256>>>(x, ah, al);

    // packed QKV weights (fp16 hi only)
    splith_kernel<<<512, 256>>>(wq, wh, 1048576);
    splith_kernel<<<128, 256>>>(wk, wh + 1048576, 262144);
    splith_kernel<<<128, 256>>>(wv, wh + 1310720, 262144);
    // fused QKV projection + per-head rms/rope/split (mode 2)
    gemm_fp16x2<<<dim3(12, 32), 256, GEMM_SMEM>>>(ah, al, wh, nullptr, nullptr, 1536, 1024,
                                                  nullptr, nullptr, 2,
                                                  qh, ql, kh, kl, vh, vl, qg, kg);

    // attention -> y fp16 split
    attn_mma_kernel<<<dim3(32, 16, 2), 128, ATTN_SMEM>>>(qh, ql, kh, kl, vh, vl, yh, yl);

    // x2 = x + y @ wo^T
    splith_kernel<<<512, 256>>>(wo, wh, 1048576);
    gemm_fp16x2<<<dim3(8, 32), 256, GEMM_SMEM>>>(yh, yl, wh, x2, x, 1024, 1024,
                                                 nullptr, nullptr, 0,
                                                 nullptr, nullptr, nullptr, nullptr, nullptr, nullptr, nullptr, nullptr);

    // h = rms_norm(x2) -> fp16 split
    rmsnorm_split_kernel<<<4096, 256>>>(x2, ah, al);

    // fc bank (folded): h = relu(ah@Wfc^T)^2 -> fp16 split
    gemm_fp16x2<<<dim3(32, 32), 256, GEMM_SMEM>>>(ah, al, wfch, nullptr, nullptr, 4096, 1024,
                                                  gh, gl, 1,
                                                  nullptr, nullptr, nullptr, nullptr, nullptr, nullptr, nullptr, nullptr);
    // pj bank (folded): out = x2 + h@Wpj^T
    gemm_fp16x2<<<dim3(8, 32), 256, GEMM_SMEM>>>(gh, gl, wpjh, (float*)d_out, x2, 1024, 4096,
                                                 nullptr, nullptr, 0,
                                                 nullptr, nullptr, nullptr, nullptr, nullptr, nullptr, nullptr, nullptr);
}

// round 9
// speedup vs baseline: 7.1956x; 1.0636x over previous
#include <cuda_runtime.h>
#include <cuda_bf16.h>
#include <cuda_fp16.h>
#include <math.h>
#include <stdint.h>

// ---------------- static device scratch ----------------
static __device__ float g_x2 [4096*1024];
static __device__ float g_wm0[8388608];
static __device__ float g_wm1[8388608];
static __device__ int   g_sel[4];
static __device__ float g_coef[4];
static __device__ __half g_ah[4194304];
static __device__ __half g_al[4194304];
static __device__ __half g_gh[16777216];
static __device__ __half g_gl[16777216];
static __device__ __half g_wh[4194304];
static __device__ __half g_wfch[4194304];
static __device__ __half g_wpjh[4194304];
static __device__ __half g_yh[4194304];
static __device__ __half g_yl[4194304];
static __device__ __half g_qh[4194304];
static __device__ __half g_ql[4194304];
static __device__ __half g_kh[1048576];
static __device__ __half g_vh[1048576];

// ---------------- PTX helpers ----------------
__device__ __forceinline__ uint32_t smem_u32(const void* p) {
    uint32_t a;
    asm("{ .reg .u64 t; cvta.to.shared.u64 t, %1; cvt.u32.u64 %0, t; }" : "=r"(a) : "l"(p));
    return a;
}
#define CP_ASYNC16(dst, src) \
    asm volatile("cp.async.cg.shared.global [%0], [%1], 16;" :: "r"(dst), "l"(src))
#define CP_COMMIT() asm volatile("cp.async.commit_group;" ::: "memory")
#define CP_WAIT1()  asm volatile("cp.async.wait_group 1;" ::: "memory")
#define CP_WAIT0()  asm volatile("cp.async.wait_group 0;" ::: "memory")

#define LDSM_X4(r, addr) \
    asm volatile("ldmatrix.sync.aligned.m8n8.x4.shared.b16 {%0,%1,%2,%3}, [%4];" \
        : "=r"((r)[0]), "=r"((r)[1]), "=r"((r)[2]), "=r"((r)[3]) : "r"(addr))
#define LDSM_X4_T(r, addr) \
    asm volatile("ldmatrix.sync.aligned.m8n8.x4.trans.shared.b16 {%0,%1,%2,%3}, [%4];" \
        : "=r"((r)[0]), "=r"((r)[1]), "=r"((r)[2]), "=r"((r)[3]) : "r"(addr))

#define MMA_FP16(d, a, b0, b1) \
    asm volatile("mma.sync.aligned.m16n8k16.row.col.f32.f16.f16.f32 " \
        "{%0,%1,%2,%3}, {%4,%5,%6,%7}, {%8,%9}, {%0,%1,%2,%3};" \
        : "+f"((d)[0]), "+f"((d)[1]), "+f"((d)[2]), "+f"((d)[3]) \
        : "r"((a)[0]), "r"((a)[1]), "r"((a)[2]), "r"((a)[3]), "r"(b0), "r"(b1))

__device__ __forceinline__ void split2h(float v0, float v1, uint32_t& h, uint32_t& l) {
    __half h0 = __float2half_rn(v0), h1 = __float2half_rn(v1);
    float r0 = v0 - __half2float(h0), r1 = v1 - __half2float(h1);
    __half l0 = __float2half_rn(r0), l1 = __float2half_rn(r1);
    h = (uint32_t)*(uint16_t*)&h0 | ((uint32_t)*(uint16_t*)&h1 << 16);
    l = (uint32_t)*(uint16_t*)&l0 | ((uint32_t)*(uint16_t*)&l1 << 16);
}
__device__ __forceinline__ uint32_t pack2h(float v0, float v1) {
    __half h0 = __float2half_rn(v0), h1 = __float2half_rn(v1);
    return (uint32_t)*(uint16_t*)&h0 | ((uint32_t)*(uint16_t*)&h1 << 16);
}

// ---------------- fp32 -> fp16 weight convert ----------------
__global__ void splith_kernel(const float* __restrict__ src, __half* __restrict__ hi, int n)
{
    int i = (blockIdx.x * blockDim.x + threadIdx.x) * 8;
    if (i >= n) return;
    float4 a = *(const float4*)(src + i);
    float4 b = *(const float4*)(src + i + 4);
    uint4 H;
    H.x = pack2h(a.x, a.y); H.y = pack2h(a.z, a.w);
    H.z = pack2h(b.x, b.y); H.w = pack2h(b.z, b.w);
    *(uint4*)(hi + i) = H;
}

// ---------------- HMMA fp16x2 GEMM ----------------
#define TSTA 144
#define TSTW 80
#define A_BYTES (128 * TSTA)
#define W_BYTES (128 * TSTW)
#define STG (A_BYTES + W_BYTES)
#define GEMM_SMEM (3 * STG)

__device__ __forceinline__ void gemm_load_stage(
    uint32_t smbase, int kt, int NT, int K, int tid,
    const __half* s0, const __half* s1, const __half* s2)
{
    if (kt < NT) {
        uint32_t sb = smbase + (kt % 3) * STG;
        int k0 = kt * 32;
#pragma unroll
        for (int t = 0; t < 6; t++) {
            int idx = tid + 256 * t;
            if (idx < 1024) {
                int row = idx >> 3, ch = idx & 7;
                uint32_t dst = sb + row * TSTA + ((ch < 4) ? ch * 16 : 64 + (ch - 4) * 16);
                const __half* src = ((ch < 4) ? s0 : s1) + (size_t)row * K + k0 + (ch & 3) * 8;
                CP_ASYNC16(dst, src);
            } else {
                int cc = idx - 1024;
                int row = cc >> 2, ch = cc & 3;
                uint32_t dst = sb + A_BYTES + row * TSTW + ch * 16;
                CP_ASYNC16(dst, s2 + (size_t)row * K + k0 + ch * 8);
            }
        }
    }
    CP_COMMIT();
}

// mode 0: C fp32 (+res); mode 1: relu^2 -> fp16 split; mode 2: fused qkv prep
__global__ __launch_bounds__(256, 2) void gemm_fp16x2(
    const __half* __restrict__ Ah, const __half* __restrict__ Al,
    const __half* __restrict__ Wh,
    float* __restrict__ C, const float* __restrict__ res, int N, int K,
    __half* __restrict__ OH, __half* __restrict__ OL, int mode,
    __half* __restrict__ qh, __half* __restrict__ ql,
    __half* __restrict__ kh, __half* __restrict__ vh,
    const float* __restrict__ qg, const float* __restrict__ kg)
{
    extern __shared__ char smem[];
    uint32_t smbase = smem_u32(smem);
    int tid = threadIdx.x, wid = tid >> 5, lane = tid & 31;
    int m0 = blockIdx.y * 128, n0 = blockIdx.x * 128;
    int wm = wid >> 1, wn = wid & 1;

    const __half* s0 = Ah + (size_t)m0 * K;
    const __half* s1 = Al + (size_t)m0 * K;
    const __half* s2 = Wh + (size_t)n0 * K;

    float acc[2][8][4];
#pragma unroll
    for (int i = 0; i < 2; i++)
#pragma unroll
        for (int j = 0; j < 8; j++)
#pragma unroll
            for (int r = 0; r < 4; r++) acc[i][j][r] = 0.f;

    int NT = K >> 5;
    gemm_load_stage(smbase, 0, NT, K, tid, s0, s1, s2);
    gemm_load_stage(smbase, 1, NT, K, tid, s0, s1, s2);

    int lt = lane >> 3, lr = lane & 7;
    for (int kt = 0; kt < NT; kt++) {
        CP_WAIT1();
        __syncthreads();
        gemm_load_stage(smbase, kt + 2, NT, K, tid, s0, s1, s2);
        uint32_t sb = smbase + (kt % 3) * STG;
        uint32_t sbW = sb + A_BYTES;
#pragma unroll
        for (int kk = 0; kk < 2; kk++) {
            uint32_t a_hi[2][4], a_lo[2][4];
#pragma unroll
            for (int i = 0; i < 2; i++) {
                int row = wm * 32 + i * 16 + lr + (lt & 1) * 8;
                int kofs = kk * 16 + (lt >> 1) * 8;
                uint32_t addr = sb + row * TSTA + kofs * 2;
                LDSM_X4(a_hi[i], addr);
                LDSM_X4(a_lo[i], addr + 64);
            }
            uint32_t b_hi[4][4];
#pragma unroll
            for (int j = 0; j < 4; j++) {
                int row = wn * 64 + j * 16 + lr + (lt >> 1) * 8;
                int kofs = kk * 16 + (lt & 1) * 8;
                LDSM_X4(b_hi[j], sbW + row * TSTW + kofs * 2);
            }
#pragma unroll
            for (int i = 0; i < 2; i++)
#pragma unroll
                for (int j = 0; j < 8; j++) {
                    uint32_t bh0 = b_hi[j >> 1][(j & 1) * 2], bh1 = b_hi[j >> 1][(j & 1) * 2 + 1];
                    MMA_FP16(acc[i][j], a_hi[i], bh0, bh1);
                    MMA_FP16(acc[i][j], a_lo[i], bh0, bh1);
                }
        }
    }
    CP_WAIT0();

    int rbase = m0 + wm * 32 + (lane >> 2);
    int cbase = n0 + wn * 64 + (lane & 3) * 2;

    if (mode == 2) {
        int hd = blockIdx.x * 2 + wn;    // 0-15 q, 16-19 k, 20-23 v
#pragma unroll
        for (int i = 0; i < 2; i++) {
#pragma unroll
            for (int half = 0; half < 2; half++) {
                int m = rbase + i * 16 + half * 8;
                int t = m & 2047, bb = m >> 11;
                float vals[8][2];
#pragma unroll
                for (int j = 0; j < 8; j++) {
                    vals[j][0] = acc[i][j][half * 2 + 0];
                    vals[j][1] = acc[i][j][half * 2 + 1];
                }
                if (hd < 20) {
                    float ss = 0.f;
#pragma unroll
                    for (int j = 0; j < 8; j++) ss += vals[j][0]*vals[j][0] + vals[j][1]*vals[j][1];
                    ss += __shfl_xor_sync(0xffffffffu, ss, 1);
                    ss += __shfl_xor_sync(0xffffffffu, ss, 2);
                    float gain = (hd < 16) ? qg[hd] : kg[hd - 16];
                    float r = rsqrtf(ss * (1.f/64.f) + 1e-6f) * gain;
#pragma unroll
                    for (int j = 0; j < 4; j++) {
                        float o1[2], o2[2];
#pragma unroll
                        for (int s = 0; s < 2; s++) {
                            int p = (lane & 3) * 2 + j * 8 + s;
                            float ang = (float)t * exp2f(-0.41524101186092029f * (float)p);
                            float sn, cs;
                            sincosf(ang, &sn, &cs);
                            float v1 = vals[j][s] * r, v2 = vals[j + 4][s] * r;
                            o1[s] = v1 * cs + v2 * sn;
                            o2[s] = v2 * cs - v1 * sn;
                        }
                        int c0 = (lane & 3) * 2 + j * 8;
                        if (hd < 16) {
                            size_t base = ((size_t)(bb * 16 + hd) * 2048 + t) * 64;
                            uint32_t hh, ll;
                            split2h(o1[0], o1[1], hh, ll);
                            *(uint32_t*)(qh + base + c0) = hh;
                            *(uint32_t*)(ql + base + c0) = ll;
                            split2h(o2[0], o2[1], hh, ll);
                            *(uint32_t*)(qh + base + c0 + 32) = hh;
                            *(uint32_t*)(ql + base + c0 + 32) = ll;
                        } else {
                            size_t base = ((size_t)(bb * 4 + hd - 16) * 2048 + t) * 64;
                            *(uint32_t*)(kh + base + c0)      = pack2h(o1[0], o1[1]);
                            *(uint32_t*)(kh + base + c0 + 32) = pack2h(o2[0], o2[1]);
                        }
                    }
                } else {
                    size_t base = ((size_t)(bb * 4 + hd - 20) * 2048 + t) * 64;
#pragma unroll
                    for (int j = 0; j < 8; j++) {
                        int c0 = (lane & 3) * 2 + j * 8;
                        *(uint32_t*)(vh + base + c0) = pack2h(vals[j][0], vals[j][1]);
                    }
                }
            }
        }
        return;
    }

#pragma unroll
    for (int i = 0; i < 2; i++) {
#pragma unroll
        for (int half = 0; half < 2; half++) {
            size_t row = (size_t)(rbase + i * 16 + half * 8);
#pragma unroll
            for (int j = 0; j < 8; j++) {
                size_t idx = row * (size_t)N + cbase + j * 8;
                float v0 = acc[i][j][half * 2 + 0];
                float v1 = acc[i][j][half * 2 + 1];
                if (mode == 1) {
                    v0 = fmaxf(v0, 0.f); v0 *= v0;
                    v1 = fmaxf(v1, 0.f); v1 *= v1;
                    uint32_t hh, ll;
                    split2h(v0, v1, hh, ll);
                    *(uint32_t*)(OH + idx) = hh;
                    *(uint32_t*)(OL + idx) = ll;
                } else {
                    if (res) { v0 += res[idx]; v1 += res[idx + 1]; }
                    *(float2*)(C + idx) = make_float2(v0, v1);
                }
            }
        }
    }
}

// ---------------- RMSNorm with fp16 hi/lo split output ----------------
__global__ void rmsnorm_split_kernel(const float* __restrict__ x,
                                     __half* __restrict__ hi, __half* __restrict__ lo)
{
    int n = blockIdx.x;
    int tid = threadIdx.x;
    const float4* xr = (const float4*)(x + (size_t)n * 1024);
    float4 v = xr[tid];
    float s = v.x*v.x + v.y*v.y + v.z*v.z + v.w*v.w;
#pragma unroll
    for (int off = 16; off > 0; off >>= 1) s += __shfl_xor_sync(0xffffffffu, s, off);
    __shared__ float red[8];
    if ((tid & 31) == 0) red[tid >> 5] = s;
    __syncthreads();
    float tot = 0.f;
#pragma unroll
    for (int i = 0; i < 8; i++) tot += red[i];
    float r = rsqrtf(tot * (1.f/1024.f) + 1e-6f);
    uint32_t h0,l0,h1,l1;
    split2h(v.x*r, v.y*r, h0, l0);
    split2h(v.z*r, v.w*r, h1, l1);
    size_t base = (size_t)n * 1024 + tid * 4;
    *(uint2*)(hi + base) = make_uint2(h0, h1);
    *(uint2*)(lo + base) = make_uint2(l0, l1);
}

// ---------------- tensor-core flash attention (fp16x2) ----------------
// Q: fp16 hi+lo; K,V: fp16 hi only. QK = 2 MMA, PV = 2 MMA.
#define AT_ROWB 144
#define AT_TILE (64 * AT_ROWB)
#define AT_STAGE (2 * AT_TILE)
#define ATTN_SMEM (2 * AT_TILE + 2 * AT_STAGE)   // 55296

__device__ __forceinline__ void attn_load_kv(
    uint32_t dstbase, int tid,
    const __half* kh, const __half* vh, size_t kvoff, int kt)
{
#pragma unroll
    for (int t = 0; t < 8; t++) {
        int idx = tid + 128 * t;                 // 0..1023
        int buf = idx >> 9, cc = idx & 511, row = cc >> 3, ch = cc & 7;
        const __half* src = (buf ? vh : kh) + kvoff + (size_t)(kt * 64 + row) * 64 + ch * 8;
        CP_ASYNC16(dstbase + buf * AT_TILE + row * AT_ROWB + ch * 16, src);
    }
}

__global__ __launch_bounds__(128) void attn_mma_kernel(
    const __half* __restrict__ qh, const __half* __restrict__ ql,
    const __half* __restrict__ kh, const __half* __restrict__ vh,
    __half* __restrict__ yh, __half* __restrict__ yl)
{
    extern __shared__ char smem[];
    uint32_t sb = smem_u32(smem);
    int qt = gridDim.x - 1 - blockIdx.x;
    int h = blockIdx.y, b = blockIdx.z;
    int tid = threadIdx.x, w = tid >> 5, lane = tid & 31;
    int lr = lane & 7, lt = lane >> 3;
    size_t qoff = ((size_t)(b * 16 + h) * 2048 + qt * 64) * 64;
    size_t kvoff = (size_t)(b * 4 + (h >> 2)) * 2048 * 64;

#pragma unroll
    for (int t = 0; t < 8; t++) {
        int idx = tid + 128 * t;
        int buf = idx >> 9, cc = idx & 511, row = cc >> 3, ch = cc & 7;
        const __half* src = (buf ? ql : qh) + qoff + row * 64 + ch * 8;
        CP_ASYNC16(sb + buf * AT_TILE + row * AT_ROWB + ch * 16, src);
    }
    CP_COMMIT();
    attn_load_kv(sb + 2 * AT_TILE, tid, kh, vh, kvoff, 0);
    CP_COMMIT();
    CP_WAIT0();
    __syncthreads();

    uint32_t qfh[4][4], qfl[4][4];
#pragma unroll
    for (int kk = 0; kk < 4; kk++) {
        uint32_t addr = sb + (w * 16 + lr + (lt & 1) * 8) * AT_ROWB + (kk * 16 + (lt >> 1) * 8) * 2;
        LDSM_X4(qfh[kk], addr);
        LDSM_X4(qfl[kk], addr + AT_TILE);
    }

    float O[8][4];
#pragma unroll
    for (int j = 0; j < 8; j++)
#pragma unroll
        for (int r = 0; r < 4; r++) O[j][r] = 0.f;
    float m0 = -1e30f, m1 = -1e30f, l0 = 0.f, l1 = 0.f;

    for (int kt = 0; kt <= qt; kt++) {
        if (kt < qt) {
            attn_load_kv(sb + 2 * AT_TILE + ((kt + 1) & 1) * AT_STAGE, tid, kh, vh, kvoff, kt + 1);
            CP_COMMIT();
        }
        uint32_t kb = sb + 2 * AT_TILE + (kt & 1) * AT_STAGE;
        float c[8][4];
#pragma unroll
        for (int j = 0; j < 8; j++)
#pragma unroll
            for (int r = 0; r < 4; r++) c[j][r] = 0.f;
#pragma unroll
        for (int kk = 0; kk < 4; kk++) {
            uint32_t kbh[4][4];
#pragma unroll
            for (int j2 = 0; j2 < 4; j2++) {
                uint32_t addr = kb + (j2 * 16 + lr + (lt >> 1) * 8) * AT_ROWB + (kk * 16 + (lt & 1) * 8) * 2;
                LDSM_X4(kbh[j2], addr);
            }
#pragma unroll
            for (int j = 0; j < 8; j++) {
                uint32_t bh0 = kbh[j >> 1][(j & 1) * 2], bh1 = kbh[j >> 1][(j & 1) * 2 + 1];
                MMA_FP16(c[j], qfh[kk], bh0, bh1);
                MMA_FP16(c[j], qfl[kk], bh0, bh1);
            }
        }
        if (kt == qt) {
            int r0 = w * 16 + (lane >> 2), r1 = r0 + 8;
#pragma unroll
            for (int j = 0; j < 8; j++) {
                int col = j * 8 + (lane & 3) * 2;
                if (col     > r0) c[j][0] = -1e30f;
                if (col + 1 > r0) c[j][1] = -1e30f;
                if (col     > r1) c[j][2] = -1e30f;
                if (col + 1 > r1) c[j][3] = -1e30f;
            }
        }
        float mx0 = -1e30f, mx1 = -1e30f;
#pragma unroll
        for (int j = 0; j < 8; j++) {
            mx0 = fmaxf(mx0, fmaxf(c[j][0], c[j][1]));
            mx1 = fmaxf(mx1, fmaxf(c[j][2], c[j][3]));
        }
        mx0 *= 0.125f; mx1 *= 0.125f;
        mx0 = fmaxf(mx0, __shfl_xor_sync(0xffffffffu, mx0, 1));
        mx0 = fmaxf(mx0, __shfl_xor_sync(0xffffffffu, mx0, 2));
        mx1 = fmaxf(mx1, __shfl_xor_sync(0xffffffffu, mx1, 1));
        mx1 = fmaxf(mx1, __shfl_xor_sync(0xffffffffu, mx1, 2));
        float m0n = fmaxf(m0, mx0), m1n = fmaxf(m1, mx1);
        float cr0 = __expf(m0 - m0n), cr1 = __expf(m1 - m1n);
        float s0 = 0.f, s1 = 0.f;
#pragma unroll
        for (int j = 0; j < 8; j++) {
            c[j][0] = __expf(fmaf(c[j][0], 0.125f, -m0n)); s0 += c[j][0];
            c[j][1] = __expf(fmaf(c[j][1], 0.125f, -m0n)); s0 += c[j][1];
            c[j][2] = __expf(fmaf(c[j][2], 0.125f, -m1n)); s1 += c[j][2];
            c[j][3] = __expf(fmaf(c[j][3], 0.125f, -m1n)); s1 += c[j][3];
        }
        s0 += __shfl_xor_sync(0xffffffffu, s0, 1);
        s0 += __shfl_xor_sync(0xffffffffu, s0, 2);
        s1 += __shfl_xor_sync(0xffffffffu, s1, 1);
        s1 += __shfl_xor_sync(0xffffffffu, s1, 2);
        l0 = l0 * cr0 + s0; l1 = l1 * cr1 + s1;
        m0 = m0n; m1 = m1n;
#pragma unroll
        for (int j = 0; j < 8; j++) {
            O[j][0] *= cr0; O[j][1] *= cr0;
            O[j][2] *= cr1; O[j][3] *= cr1;
        }
#pragma unroll
        for (int kt2 = 0; kt2 < 4; kt2++) {
            uint32_t pah[4], pal[4];
            split2h(c[2*kt2][0],   c[2*kt2][1],   pah[0], pal[0]);
            split2h(c[2*kt2][2],   c[2*kt2][3],   pah[1], pal[1]);
            split2h(c[2*kt2+1][0], c[2*kt2+1][1], pah[2], pal[2]);
            split2h(c[2*kt2+1][2], c[2*kt2+1][3], pah[3], pal[3]);
#pragma unroll
            for (int jd = 0; jd < 4; jd++) {
                uint32_t vbh[4];
                uint32_t addr = kb + AT_TILE + (kt2 * 16 + (lt & 1) * 8 + lr) * AT_ROWB + (jd * 16 + (lt >> 1) * 8) * 2;
                LDSM_X4_T(vbh, addr);
#pragma unroll
                for (int js = 0; js < 2; js++) {
                    int j = jd * 2 + js;
                    MMA_FP16(O[j], pah, vbh[js*2], vbh[js*2+1]);
                    MMA_FP16(O[j], pal, vbh[js*2], vbh[js*2+1]);
                }
            }
        }
        if (kt < qt) CP_WAIT0();
        __syncthreads();
    }
    float i0 = 1.f / l0, i1 = 1.f / l1;
    size_t rA = (size_t)(b * 2048 + qt * 64 + w * 16 + (lane >> 2));
    size_t rB = rA + 8;
    int colb = h * 64 + (lane & 3) * 2;
#pragma unroll
    for (int j = 0; j < 8; j++) {
        uint32_t hh, ll;
        int col = colb + j * 8;
        split2h(O[j][0] * i0, O[j][1] * i0, hh, ll);
        *(uint32_t*)(yh + rA * 1024 + col) = hh;
        *(uint32_t*)(yl + rA * 1024 + col) = ll;
        split2h(O[j][2] * i1, O[j][3] * i1, hh, ll);
        *(uint32_t*)(yh + rB * 1024 + col) = hh;
        *(uint32_t*)(yl + rB * 1024 + col) = ll;
    }
}

// ---------------- tile helpers for folding kernels ----------------
#define TP 68
__device__ __forceinline__ void load_tile_s(float* dst, const float* src, size_t stride, int tid) {
#pragma unroll
    for (int r = 0; r < 4; r++) {
        int f = tid + 256 * r;
        int row = f >> 4, c4 = (f & 15) << 2;
        *(float4*)&dst[row*TP + c4] = *(const float4*)(src + (size_t)row * stride + c4);
    }
}
__device__ __forceinline__ void load_tileT_s(float* dst, const float* src, size_t stride, int tid) {
#pragma unroll
    for (int r = 0; r < 4; r++) {
        int f = tid + 256 * r;
        int row = f >> 4, c4 = (f & 15) << 2;
        float4 v = *(const float4*)(src + (size_t)row * stride + c4);
        dst[(c4+0)*TP + row] = v.x; dst[(c4+1)*TP + row] = v.y;
        dst[(c4+2)*TP + row] = v.z; dst[(c4+3)*TP + row] = v.w;
    }
}
__device__ __forceinline__ void mm64(const float* XT, const float* W, float acc[4][4], int tx, int ty) {
#pragma unroll
    for (int c = 0; c < 64; c++) {
        float a[4], bb[4];
        *(float4*)a  = *(const float4*)&XT[c*TP + ty*4];
        *(float4*)bb = *(const float4*)&W [c*TP + tx*4];
#pragma unroll
        for (int i = 0; i < 4; i++)
#pragma unroll
            for (int j = 0; j < 4; j++) acc[i][j] = fmaf(a[i], bb[j], acc[i][j]);
    }
}

// ---------------- P1: fold s2 into mix ----------------
__global__ __launch_bounds__(256) void fold1_kernel(
    const float* __restrict__ Mix, const float* __restrict__ S2,
    float* __restrict__ WM2T, int in_f, int out_f,
    const int* __restrict__ selp)
{
    extern __shared__ float sm[];
    float* MT = sm;
    float* S  = sm + 4352;
    int jb = blockIdx.x, G = blockIdx.y, r = blockIdx.z;
    int sel = selp[r];
    int tid = threadIdx.x;
    load_tile_s(MT, Mix + (size_t)sel * out_f * in_f + (size_t)(G * 64) * in_f + jb * 64, in_f, tid);
    load_tile_s(S,  S2  + (size_t)sel * out_f * 64 + (size_t)G * 4096, 64, tid);
    __syncthreads();
    int tx = tid & 15, ty = tid >> 4;
    float acc[4][4] = {};
    mm64(MT, S, acc, tx, ty);
    float* outp = WM2T + (size_t)r * in_f * out_f;
#pragma unroll
    for (int i = 0; i < 4; i++) {
        size_t row = (size_t)(jb * 64 + ty * 4 + i);
        *(float4*)(outp + row * out_f + G * 64 + tx * 4) =
            make_float4(acc[i][0], acc[i][1], acc[i][2], acc[i][3]);
    }
}

// ---------------- P2: fold s1 + roll-perm, combine experts, fp16 out ----------------
__global__ __launch_bounds__(256) void fold2_kernel(
    const float* __restrict__ WM2T, const float* __restrict__ S1,
    __half* __restrict__ WH,
    int in_f, int out_f, int n_in,
    const int* __restrict__ selp, const float* __restrict__ coefp)
{
    extern __shared__ float sm[];
    float* G0 = sm;
    float* G1 = sm + 4352;
    float* T0 = sm + 8704;
    float* T1 = sm + 13056;
    int g = blockIdx.x, Ob = blockIdx.y, tid = threadIdx.x;
    int s0i = selp[0], s1i = selp[1];
    int gs0 = (g + s0i) % n_in, gs1 = (g + s1i) % n_in;
    const float* W0 = WM2T;
    const float* W1 = WM2T + (size_t)in_f * out_f;
#pragma unroll
    for (int r = 0; r < 4; r++) {
        int f = tid + 256 * r;
        int d = f >> 4, o4 = (f & 15) << 2;
        *(float4*)&G0[d*TP + o4] = *(const float4*)(W0 + (size_t)(d * n_in + gs0) * out_f + Ob * 64 + o4);
        *(float4*)&G1[d*TP + o4] = *(const float4*)(W1 + (size_t)(d * n_in + gs1) * out_f + Ob * 64 + o4);
    }
    load_tileT_s(T0, S1 + (size_t)s0i * in_f * 64 + (size_t)g * 4096, 64, tid);
    load_tileT_s(T1, S1 + (size_t)s1i * in_f * 64 + (size_t)g * 4096, 64, tid);
    __syncthreads();
    int tx = tid & 15, ty = tid >> 4;
    float a0[4][4] = {}, a1[4][4] = {};
    mm64(G0, T0, a0, tx, ty);
    mm64(G1, T1, a1, tx, ty);
    float c0 = coefp[0], c1 = coefp[1];
#pragma unroll
    for (int i = 0; i < 4; i++) {
        size_t base = (size_t)(Ob * 64 + ty * 4 + i) * in_f + g * 64 + tx * 4;
        float v0 = c0 * a0[i][0] + c1 * a1[i][0];
        float v1 = c0 * a0[i][1] + c1 * a1[i][1];
        float v2 = c0 * a0[i][2] + c1 * a1[i][2];
        float v3 = c0 * a0[i][3] + c1 * a1[i][3];
        *(uint32_t*)(WH + base)     = pack2h(v0, v1);
        *(uint32_t*)(WH + base + 2) = pack2h(v2, v3);
    }
}

// ---------------- top-2 router ----------------
__global__ void router_kernel(const float* __restrict__ fcl, const float* __restrict__ pjl,
                              int* __restrict__ sel, float* __restrict__ coef)
{
    if (threadIdx.x == 0 && blockIdx.x == 0) {
#pragma unroll
        for (int s = 0; s < 2; s++) {
            const float* L = s ? pjl : fcl;
            int i1 = 0; float v1 = L[0];
            for (int i = 1; i < 8; i++) if (L[i] > v1) { v1 = L[i]; i1 = i; }
            int i2 = -1; float v2 = -1e30f;
            for (int i = 0; i < 8; i++) if (i != i1 && L[i] > v2) { v2 = L[i]; i2 = i; }
            float e = expf(v2 - v1);
            float z = 1.f + e;
            sel[s*2+0] = i1; sel[s*2+1] = i2;
            coef[s*2+0] = 1.f / z; coef[s*2+1] = e / z;
        }
    }
}

// ---------------- host orchestration ----------------
#define FOLD1_SMEM (8704 * 4)
#define FOLD2_SMEM (17408 * 4)

extern "C" void kernel_launch(void* const* d_in, const int* in_sizes, int n_in_,
                              void* d_out, int out_size)
{
    (void)in_sizes; (void)n_in_; (void)out_size;
    const float* x      = (const float*)d_in[0];
    const float* wq     = (const float*)d_in[1];
    const float* wk     = (const float*)d_in[2];
    const float* wv     = (const float*)d_in[3];
    const float* wo     = (const float*)d_in[4];
    const float* qg     = (const float*)d_in[5];
    const float* kg     = (const float*)d_in[6];
    const float* fc_s1  = (const float*)d_in[7];
    const float* fc_s2  = (const float*)d_in[8];
    const float* fc_mix = (const float*)d_in[9];
    const float* fc_lg  = (const float*)d_in[10];
    const float* pj_s1  = (const float*)d_in[11];
    const float* pj_s2  = (const float*)d_in[12];
    const float* pj_mix = (const float*)d_in[13];
    const float* pj_lg  = (const float*)d_in[14];

    float *x2, *wm0, *wm1, *coef;
    int* sel;
    __half *ah, *al, *gh, *gl, *wh, *wfch, *wpjh, *yh, *yl, *qh, *ql, *kh, *vh;
    cudaGetSymbolAddress((void**)&x2,  g_x2);
    cudaGetSymbolAddress((void**)&wm0, g_wm0);
    cudaGetSymbolAddress((void**)&wm1, g_wm1);
    cudaGetSymbolAddress((void**)&sel,  g_sel);
    cudaGetSymbolAddress((void**)&coef, g_coef);
    cudaGetSymbolAddress((void**)&ah, g_ah);
    cudaGetSymbolAddress((void**)&al, g_al);
    cudaGetSymbolAddress((void**)&gh, g_gh);
    cudaGetSymbolAddress((void**)&gl, g_gl);
    cudaGetSymbolAddress((void**)&wh, g_wh);
    cudaGetSymbolAddress((void**)&wfch, g_wfch);
    cudaGetSymbolAddress((void**)&wpjh, g_wpjh);
    cudaGetSymbolAddress((void**)&yh, g_yh);
    cudaGetSymbolAddress((void**)&yl, g_yl);
    cudaGetSymbolAddress((void**)&qh, g_qh);
    cudaGetSymbolAddress((void**)&ql, g_ql);
    cudaGetSymbolAddress((void**)&kh, g_kh);
    cudaGetSymbolAddress((void**)&vh, g_vh);

    cudaFuncSetAttribute(gemm_fp16x2, cudaFuncAttributeMaxDynamicSharedMemorySize, GEMM_SMEM);
    cudaFuncSetAttribute(attn_mma_kernel, cudaFuncAttributeMaxDynamicSharedMemorySize, ATTN_SMEM);
    cudaFuncSetAttribute(fold1_kernel, cudaFuncAttributeMaxDynamicSharedMemorySize, FOLD1_SMEM);
    cudaFuncSetAttribute(fold2_kernel, cudaFuncAttributeMaxDynamicSharedMemorySize, FOLD2_SMEM);

    // routing + weight folding
    router_kernel<<<1, 32>>>(fc_lg, pj_lg, sel, coef);
    fold1_kernel<<<dim3(16, 64, 2), 256, FOLD1_SMEM>>>(fc_mix, fc_s2, wm0, 1024, 4096, sel);
    fold2_kernel<<<dim3(16, 64), 256, FOLD2_SMEM>>>(wm0, fc_s1, wfch, 1024, 4096, 16, sel, coef);
    fold1_kernel<<<dim3(64, 16, 2), 256, FOLD1_SMEM>>>(pj_mix, pj_s2, wm1, 4096, 1024, sel + 2);
    fold2_kernel<<<dim3(64, 16), 256, FOLD2_SMEM>>>(wm1, pj_s1, wpjh, 4096, 1024, 64, sel + 2, coef + 2);

    // x1 = rms_norm(x) -> fp16 split
    rmsnorm_split_kernel<<<4096, 256>>>(x, ah, al);

    // packed QKV weights (fp16)
    splith_kernel<<<512, 256>>>(wq, wh, 1048576);
    splith_kernel<<<128, 256>>>(wk, wh + 1048576, 262144);
    splith_kernel<<<128, 256>>>(wv, wh + 1310720, 262144);
    // fused QKV projection + per-head rms/rope/split (mode 2)
    gemm_fp16x2<<<dim3(12, 32), 256, GEMM_SMEM>>>(ah, al, wh, nullptr, nullptr, 1536, 1024,
                                                  nullptr, nullptr, 2,
                                                  qh, ql, kh, vh, qg, kg);

    // attention -> y fp16 split
    attn_mma_kernel<<<dim3(32, 16, 2), 128, ATTN_SMEM>>>(qh, ql, kh, vh, yh, yl);

    // x2 = x + y @ wo^T
    splith_kernel<<<512, 256>>>(wo, wh, 1048576);
    gemm_fp16x2<<<dim3(8, 32), 256, GEMM_SMEM>>>(yh, yl, wh, x2, x, 1024, 1024,
                                                 nullptr, nullptr, 0,
                                                 nullptr, nullptr, nullptr, nullptr, nullptr, nullptr);

    // h = rms_norm(x2) -> fp16 split
    rmsnorm_split_kernel<<<4096, 256>>>(x2, ah, al);

    // fc bank (folded): h = relu(ah@Wfc^T)^2 -> fp16 split
    gemm_fp16x2<<<dim3(32, 32), 256, GEMM_SMEM>>>(ah, al, wfch, nullptr, nullptr, 4096, 1024,
                                                  gh, gl, 1,
                                                  nullptr, nullptr, nullptr, nullptr, nullptr, nullptr);
    // pj bank (folded): out = x2 + h@Wpj^T
    gemm_fp16x2<<<dim3(8, 32), 256, GEMM_SMEM>>>(gh, gl, wpjh, (float*)d_out, x2, 1024, 4096,
                                                 nullptr, nullptr, 0,
                                                 nullptr, nullptr, nullptr, nullptr, nullptr, nullptr);
}

// round 10
// speedup vs baseline: 7.5563x; 1.0501x over previous
#include <cuda_runtime.h>
#include <cuda_bf16.h>
#include <cuda_fp16.h>
#include <math.h>
#include <stdint.h>

// ---------------- static device scratch ----------------
static __device__ float g_x2 [4096*1024];
static __device__ float g_wm0[8388608];
static __device__ float g_wm1[8388608];
static __device__ int   g_sel[4];
static __device__ float g_coef[4];
static __device__ __half g_ah[4194304];
static __device__ __half g_al[4194304];
static __device__ __half g_gh[16777216];
static __device__ __half g_gl[16777216];
static __device__ __half g_wh[4194304];      // qkv weights fp16
static __device__ __half g_who[1048576];     // wo weights fp16 (separate: split runs on side stream)
static __device__ __half g_wfch[4194304];
static __device__ __half g_wpjh[4194304];
static __device__ __half g_yh[4194304];
static __device__ __half g_yl[4194304];
static __device__ __half g_qh[4194304];
static __device__ __half g_ql[4194304];
static __device__ __half g_kh[1048576];
static __device__ __half g_vh[1048576];

// ---------------- PTX helpers ----------------
__device__ __forceinline__ uint32_t smem_u32(const void* p) {
    uint32_t a;
    asm("{ .reg .u64 t; cvta.to.shared.u64 t, %1; cvt.u32.u64 %0, t; }" : "=r"(a) : "l"(p));
    return a;
}
#define CP_ASYNC16(dst, src) \
    asm volatile("cp.async.cg.shared.global [%0], [%1], 16;" :: "r"(dst), "l"(src))
#define CP_COMMIT() asm volatile("cp.async.commit_group;" ::: "memory")
#define CP_WAIT1()  asm volatile("cp.async.wait_group 1;" ::: "memory")
#define CP_WAIT0()  asm volatile("cp.async.wait_group 0;" ::: "memory")

#define LDSM_X4(r, addr) \
    asm volatile("ldmatrix.sync.aligned.m8n8.x4.shared.b16 {%0,%1,%2,%3}, [%4];" \
        : "=r"((r)[0]), "=r"((r)[1]), "=r"((r)[2]), "=r"((r)[3]) : "r"(addr))
#define LDSM_X4_T(r, addr) \
    asm volatile("ldmatrix.sync.aligned.m8n8.x4.trans.shared.b16 {%0,%1,%2,%3}, [%4];" \
        : "=r"((r)[0]), "=r"((r)[1]), "=r"((r)[2]), "=r"((r)[3]) : "r"(addr))

#define MMA_FP16(d, a, b0, b1) \
    asm volatile("mma.sync.aligned.m16n8k16.row.col.f32.f16.f16.f32 " \
        "{%0,%1,%2,%3}, {%4,%5,%6,%7}, {%8,%9}, {%0,%1,%2,%3};" \
        : "+f"((d)[0]), "+f"((d)[1]), "+f"((d)[2]), "+f"((d)[3]) \
        : "r"((a)[0]), "r"((a)[1]), "r"((a)[2]), "r"((a)[3]), "r"(b0), "r"(b1))

__device__ __forceinline__ void split2h(float v0, float v1, uint32_t& h, uint32_t& l) {
    __half h0 = __float2half_rn(v0), h1 = __float2half_rn(v1);
    float r0 = v0 - __half2float(h0), r1 = v1 - __half2float(h1);
    __half l0 = __float2half_rn(r0), l1 = __float2half_rn(r1);
    h = (uint32_t)*(uint16_t*)&h0 | ((uint32_t)*(uint16_t*)&h1 << 16);
    l = (uint32_t)*(uint16_t*)&l0 | ((uint32_t)*(uint16_t*)&l1 << 16);
}
__device__ __forceinline__ uint32_t pack2h(float v0, float v1) {
    __half h0 = __float2half_rn(v0), h1 = __float2half_rn(v1);
    return (uint32_t)*(uint16_t*)&h0 | ((uint32_t)*(uint16_t*)&h1 << 16);
}

// ---------------- fp32 -> fp16 weight convert ----------------
__global__ void splith_kernel(const float* __restrict__ src, __half* __restrict__ hi, int n)
{
    int i = (blockIdx.x * blockDim.x + threadIdx.x) * 8;
    if (i >= n) return;
    float4 a = *(const float4*)(src + i);
    float4 b = *(const float4*)(src + i + 4);
    uint4 H;
    H.x = pack2h(a.x, a.y); H.y = pack2h(a.z, a.w);
    H.z = pack2h(b.x, b.y); H.w = pack2h(b.z, b.w);
    *(uint4*)(hi + i) = H;
}

// ---------------- HMMA fp16x2 GEMM ----------------
#define TSTA 144
#define TSTW 80
#define A_BYTES (128 * TSTA)
#define W_BYTES (128 * TSTW)
#define STG (A_BYTES + W_BYTES)
#define GEMM_SMEM (3 * STG)

__device__ __forceinline__ void gemm_load_stage(
    uint32_t smbase, int kt, int NT, int K, int tid,
    const __half* s0, const __half* s1, const __half* s2)
{
    if (kt < NT) {
        uint32_t sb = smbase + (kt % 3) * STG;
        int k0 = kt * 32;
#pragma unroll
        for (int t = 0; t < 6; t++) {
            int idx = tid + 256 * t;
            if (idx < 1024) {
                int row = idx >> 3, ch = idx & 7;
                uint32_t dst = sb + row * TSTA + ((ch < 4) ? ch * 16 : 64 + (ch - 4) * 16);
                const __half* src = ((ch < 4) ? s0 : s1) + (size_t)row * K + k0 + (ch & 3) * 8;
                CP_ASYNC16(dst, src);
            } else {
                int cc = idx - 1024;
                int row = cc >> 2, ch = cc & 3;
                uint32_t dst = sb + A_BYTES + row * TSTW + ch * 16;
                CP_ASYNC16(dst, s2 + (size_t)row * K + k0 + ch * 8);
            }
        }
    }
    CP_COMMIT();
}

// mode 0: C fp32 (+res); mode 1: relu^2 -> fp16 split; mode 2: fused qkv prep
__global__ __launch_bounds__(256, 2) void gemm_fp16x2(
    const __half* __restrict__ Ah, const __half* __restrict__ Al,
    const __half* __restrict__ Wh,
    float* __restrict__ C, const float* __restrict__ res, int N, int K,
    __half* __restrict__ OH, __half* __restrict__ OL, int mode,
    __half* __restrict__ qh, __half* __restrict__ ql,
    __half* __restrict__ kh, __half* __restrict__ vh,
    const float* __restrict__ qg, const float* __restrict__ kg)
{
    extern __shared__ char smem[];
    uint32_t smbase = smem_u32(smem);
    int tid = threadIdx.x, wid = tid >> 5, lane = tid & 31;
    int m0 = blockIdx.y * 128, n0 = blockIdx.x * 128;
    int wm = wid >> 1, wn = wid & 1;

    const __half* s0 = Ah + (size_t)m0 * K;
    const __half* s1 = Al + (size_t)m0 * K;
    const __half* s2 = Wh + (size_t)n0 * K;

    float acc[2][8][4];
#pragma unroll
    for (int i = 0; i < 2; i++)
#pragma unroll
        for (int j = 0; j < 8; j++)
#pragma unroll
            for (int r = 0; r < 4; r++) acc[i][j][r] = 0.f;

    int NT = K >> 5;
    gemm_load_stage(smbase, 0, NT, K, tid, s0, s1, s2);
    gemm_load_stage(smbase, 1, NT, K, tid, s0, s1, s2);

    int lt = lane >> 3, lr = lane & 7;
    for (int kt = 0; kt < NT; kt++) {
        CP_WAIT1();
        __syncthreads();
        gemm_load_stage(smbase, kt + 2, NT, K, tid, s0, s1, s2);
        uint32_t sb = smbase + (kt % 3) * STG;
        uint32_t sbW = sb + A_BYTES;
#pragma unroll
        for (int kk = 0; kk < 2; kk++) {
            uint32_t a_hi[2][4], a_lo[2][4];
#pragma unroll
            for (int i = 0; i < 2; i++) {
                int row = wm * 32 + i * 16 + lr + (lt & 1) * 8;
                int kofs = kk * 16 + (lt >> 1) * 8;
                uint32_t addr = sb + row * TSTA + kofs * 2;
                LDSM_X4(a_hi[i], addr);
                LDSM_X4(a_lo[i], addr + 64);
            }
            uint32_t b_hi[4][4];
#pragma unroll
            for (int j = 0; j < 4; j++) {
                int row = wn * 64 + j * 16 + lr + (lt >> 1) * 8;
                int kofs = kk * 16 + (lt & 1) * 8;
                LDSM_X4(b_hi[j], sbW + row * TSTW + kofs * 2);
            }
#pragma unroll
            for (int i = 0; i < 2; i++)
#pragma unroll
                for (int j = 0; j < 8; j++) {
                    uint32_t bh0 = b_hi[j >> 1][(j & 1) * 2], bh1 = b_hi[j >> 1][(j & 1) * 2 + 1];
                    MMA_FP16(acc[i][j], a_hi[i], bh0, bh1);
                    MMA_FP16(acc[i][j], a_lo[i], bh0, bh1);
                }
        }
    }
    CP_WAIT0();

    int rbase = m0 + wm * 32 + (lane >> 2);
    int cbase = n0 + wn * 64 + (lane & 3) * 2;

    if (mode == 2) {
        int hd = blockIdx.x * 2 + wn;    // 0-15 q, 16-19 k, 20-23 v
#pragma unroll
        for (int i = 0; i < 2; i++) {
#pragma unroll
            for (int half = 0; half < 2; half++) {
                int m = rbase + i * 16 + half * 8;
                int t = m & 2047, bb = m >> 11;
                float vals[8][2];
#pragma unroll
                for (int j = 0; j < 8; j++) {
                    vals[j][0] = acc[i][j][half * 2 + 0];
                    vals[j][1] = acc[i][j][half * 2 + 1];
                }
                if (hd < 20) {
                    float ss = 0.f;
#pragma unroll
                    for (int j = 0; j < 8; j++) ss += vals[j][0]*vals[j][0] + vals[j][1]*vals[j][1];
                    ss += __shfl_xor_sync(0xffffffffu, ss, 1);
                    ss += __shfl_xor_sync(0xffffffffu, ss, 2);
                    float gain = (hd < 16) ? qg[hd] : kg[hd - 16];
                    float r = rsqrtf(ss * (1.f/64.f) + 1e-6f) * gain;
#pragma unroll
                    for (int j = 0; j < 4; j++) {
                        float o1[2], o2[2];
#pragma unroll
                        for (int s = 0; s < 2; s++) {
                            int p = (lane & 3) * 2 + j * 8 + s;
                            float ang = (float)t * exp2f(-0.41524101186092029f * (float)p);
                            float sn, cs;
                            sincosf(ang, &sn, &cs);
                            float v1 = vals[j][s] * r, v2 = vals[j + 4][s] * r;
                            o1[s] = v1 * cs + v2 * sn;
                            o2[s] = v2 * cs - v1 * sn;
                        }
                        int c0 = (lane & 3) * 2 + j * 8;
                        if (hd < 16) {
                            size_t base = ((size_t)(bb * 16 + hd) * 2048 + t) * 64;
                            uint32_t hh, ll;
                            split2h(o1[0], o1[1], hh, ll);
                            *(uint32_t*)(qh + base + c0) = hh;
                            *(uint32_t*)(ql + base + c0) = ll;
                            split2h(o2[0], o2[1], hh, ll);
                            *(uint32_t*)(qh + base + c0 + 32) = hh;
                            *(uint32_t*)(ql + base + c0 + 32) = ll;
                        } else {
                            size_t base = ((size_t)(bb * 4 + hd - 16) * 2048 + t) * 64;
                            *(uint32_t*)(kh + base + c0)      = pack2h(o1[0], o1[1]);
                            *(uint32_t*)(kh + base + c0 + 32) = pack2h(o2[0], o2[1]);
                        }
                    }
                } else {
                    size_t base = ((size_t)(bb * 4 + hd - 20) * 2048 + t) * 64;
#pragma unroll
                    for (int j = 0; j < 8; j++) {
                        int c0 = (lane & 3) * 2 + j * 8;
                        *(uint32_t*)(vh + base + c0) = pack2h(vals[j][0], vals[j][1]);
                    }
                }
            }
        }
        return;
    }

#pragma unroll
    for (int i = 0; i < 2; i++) {
#pragma unroll
        for (int half = 0; half < 2; half++) {
            size_t row = (size_t)(rbase + i * 16 + half * 8);
#pragma unroll
            for (int j = 0; j < 8; j++) {
                size_t idx = row * (size_t)N + cbase + j * 8;
                float v0 = acc[i][j][half * 2 + 0];
                float v1 = acc[i][j][half * 2 + 1];
                if (mode == 1) {
                    v0 = fmaxf(v0, 0.f); v0 *= v0;
                    v1 = fmaxf(v1, 0.f); v1 *= v1;
                    uint32_t hh, ll;
                    split2h(v0, v1, hh, ll);
                    *(uint32_t*)(OH + idx) = hh;
                    *(uint32_t*)(OL + idx) = ll;
                } else {
                    if (res) { v0 += res[idx]; v1 += res[idx + 1]; }
                    *(float2*)(C + idx) = make_float2(v0, v1);
                }
            }
        }
    }
}

// ---------------- RMSNorm with fp16 hi/lo split output ----------------
__global__ void rmsnorm_split_kernel(const float* __restrict__ x,
                                     __half* __restrict__ hi, __half* __restrict__ lo)
{
    int n = blockIdx.x;
    int tid = threadIdx.x;
    const float4* xr = (const float4*)(x + (size_t)n * 1024);
    float4 v = xr[tid];
    float s = v.x*v.x + v.y*v.y + v.z*v.z + v.w*v.w;
#pragma unroll
    for (int off = 16; off > 0; off >>= 1) s += __shfl_xor_sync(0xffffffffu, s, off);
    __shared__ float red[8];
    if ((tid & 31) == 0) red[tid >> 5] = s;
    __syncthreads();
    float tot = 0.f;
#pragma unroll
    for (int i = 0; i < 8; i++) tot += red[i];
    float r = rsqrtf(tot * (1.f/1024.f) + 1e-6f);
    uint32_t h0,l0,h1,l1;
    split2h(v.x*r, v.y*r, h0, l0);
    split2h(v.z*r, v.w*r, h1, l1);
    size_t base = (size_t)n * 1024 + tid * 4;
    *(uint2*)(hi + base) = make_uint2(h0, h1);
    *(uint2*)(lo + base) = make_uint2(l0, l1);
}

// ---------------- tensor-core flash attention (fp16x2) ----------------
#define AT_ROWB 144
#define AT_TILE (64 * AT_ROWB)
#define AT_STAGE (2 * AT_TILE)
#define ATTN_SMEM (2 * AT_TILE + 2 * AT_STAGE)

__device__ __forceinline__ void attn_load_kv(
    uint32_t dstbase, int tid,
    const __half* kh, const __half* vh, size_t kvoff, int kt)
{
#pragma unroll
    for (int t = 0; t < 8; t++) {
        int idx = tid + 128 * t;
        int buf = idx >> 9, cc = idx & 511, row = cc >> 3, ch = cc & 7;
        const __half* src = (buf ? vh : kh) + kvoff + (size_t)(kt * 64 + row) * 64 + ch * 8;
        CP_ASYNC16(dstbase + buf * AT_TILE + row * AT_ROWB + ch * 16, src);
    }
}

__global__ __launch_bounds__(128) void attn_mma_kernel(
    const __half* __restrict__ qh, const __half* __restrict__ ql,
    const __half* __restrict__ kh, const __half* __restrict__ vh,
    __half* __restrict__ yh, __half* __restrict__ yl)
{
    extern __shared__ char smem[];
    uint32_t sb = smem_u32(smem);
    int qt = gridDim.x - 1 - blockIdx.x;
    int h = blockIdx.y, b = blockIdx.z;
    int tid = threadIdx.x, w = tid >> 5, lane = tid & 31;
    int lr = lane & 7, lt = lane >> 3;
    size_t qoff = ((size_t)(b * 16 + h) * 2048 + qt * 64) * 64;
    size_t kvoff = (size_t)(b * 4 + (h >> 2)) * 2048 * 64;

#pragma unroll
    for (int t = 0; t < 8; t++) {
        int idx = tid + 128 * t;
        int buf = idx >> 9, cc = idx & 511, row = cc >> 3, ch = cc & 7;
        const __half* src = (buf ? ql : qh) + qoff + row * 64 + ch * 8;
        CP_ASYNC16(sb + buf * AT_TILE + row * AT_ROWB + ch * 16, src);
    }
    CP_COMMIT();
    attn_load_kv(sb + 2 * AT_TILE, tid, kh, vh, kvoff, 0);
    CP_COMMIT();
    CP_WAIT0();
    __syncthreads();

    uint32_t qfh[4][4], qfl[4][4];
#pragma unroll
    for (int kk = 0; kk < 4; kk++) {
        uint32_t addr = sb + (w * 16 + lr + (lt & 1) * 8) * AT_ROWB + (kk * 16 + (lt >> 1) * 8) * 2;
        LDSM_X4(qfh[kk], addr);
        LDSM_X4(qfl[kk], addr + AT_TILE);
    }

    float O[8][4];
#pragma unroll
    for (int j = 0; j < 8; j++)
#pragma unroll
        for (int r = 0; r < 4; r++) O[j][r] = 0.f;
    float m0 = -1e30f, m1 = -1e30f, l0 = 0.f, l1 = 0.f;

    for (int kt = 0; kt <= qt; kt++) {
        if (kt < qt) {
            attn_load_kv(sb + 2 * AT_TILE + ((kt + 1) & 1) * AT_STAGE, tid, kh, vh, kvoff, kt + 1);
            CP_COMMIT();
        }
        uint32_t kb = sb + 2 * AT_TILE + (kt & 1) * AT_STAGE;
        float c[8][4];
#pragma unroll
        for (int j = 0; j < 8; j++)
#pragma unroll
            for (int r = 0; r < 4; r++) c[j][r] = 0.f;
#pragma unroll
        for (int kk = 0; kk < 4; kk++) {
            uint32_t kbh[4][4];
#pragma unroll
            for (int j2 = 0; j2 < 4; j2++) {
                uint32_t addr = kb + (j2 * 16 + lr + (lt >> 1) * 8) * AT_ROWB + (kk * 16 + (lt & 1) * 8) * 2;
                LDSM_X4(kbh[j2], addr);
            }
#pragma unroll
            for (int j = 0; j < 8; j++) {
                uint32_t bh0 = kbh[j >> 1][(j & 1) * 2], bh1 = kbh[j >> 1][(j & 1) * 2 + 1];
                MMA_FP16(c[j], qfh[kk], bh0, bh1);
                MMA_FP16(c[j], qfl[kk], bh0, bh1);
            }
        }
        if (kt == qt) {
            int r0 = w * 16 + (lane >> 2), r1 = r0 + 8;
#pragma unroll
            for (int j = 0; j < 8; j++) {
                int col = j * 8 + (lane & 3) * 2;
                if (col     > r0) c[j][0] = -1e30f;
                if (col + 1 > r0) c[j][1] = -1e30f;
                if (col     > r1) c[j][2] = -1e30f;
                if (col + 1 > r1) c[j][3] = -1e30f;
            }
        }
        float mx0 = -1e30f, mx1 = -1e30f;
#pragma unroll
        for (int j = 0; j < 8; j++) {
            mx0 = fmaxf(mx0, fmaxf(c[j][0], c[j][1]));
            mx1 = fmaxf(mx1, fmaxf(c[j][2], c[j][3]));
        }
        mx0 *= 0.125f; mx1 *= 0.125f;
        mx0 = fmaxf(mx0, __shfl_xor_sync(0xffffffffu, mx0, 1));
        mx0 = fmaxf(mx0, __shfl_xor_sync(0xffffffffu, mx0, 2));
        mx1 = fmaxf(mx1, __shfl_xor_sync(0xffffffffu, mx1, 1));
        mx1 = fmaxf(mx1, __shfl_xor_sync(0xffffffffu, mx1, 2));
        float m0n = fmaxf(m0, mx0), m1n = fmaxf(m1, mx1);
        float cr0 = __expf(m0 - m0n), cr1 = __expf(m1 - m1n);
        float s0 = 0.f, s1 = 0.f;
#pragma unroll
        for (int j = 0; j < 8; j++) {
            c[j][0] = __expf(fmaf(c[j][0], 0.125f, -m0n)); s0 += c[j][0];
            c[j][1] = __expf(fmaf(c[j][1], 0.125f, -m0n)); s0 += c[j][1];
            c[j][2] = __expf(fmaf(c[j][2], 0.125f, -m1n)); s1 += c[j][2];
            c[j][3] = __expf(fmaf(c[j][3], 0.125f, -m1n)); s1 += c[j][3];
        }
        s0 += __shfl_xor_sync(0xffffffffu, s0, 1);
        s0 += __shfl_xor_sync(0xffffffffu, s0, 2);
        s1 += __shfl_xor_sync(0xffffffffu, s1, 1);
        s1 += __shfl_xor_sync(0xffffffffu, s1, 2);
        l0 = l0 * cr0 + s0; l1 = l1 * cr1 + s1;
        m0 = m0n; m1 = m1n;
#pragma unroll
        for (int j = 0; j < 8; j++) {
            O[j][0] *= cr0; O[j][1] *= cr0;
            O[j][2] *= cr1; O[j][3] *= cr1;
        }
#pragma unroll
        for (int kt2 = 0; kt2 < 4; kt2++) {
            uint32_t pah[4], pal[4];
            split2h(c[2*kt2][0],   c[2*kt2][1],   pah[0], pal[0]);
            split2h(c[2*kt2][2],   c[2*kt2][3],   pah[1], pal[1]);
            split2h(c[2*kt2+1][0], c[2*kt2+1][1], pah[2], pal[2]);
            split2h(c[2*kt2+1][2], c[2*kt2+1][3], pah[3], pal[3]);
#pragma unroll
            for (int jd = 0; jd < 4; jd++) {
                uint32_t vbh[4];
                uint32_t addr = kb + AT_TILE + (kt2 * 16 + (lt & 1) * 8 + lr) * AT_ROWB + (jd * 16 + (lt >> 1) * 8) * 2;
                LDSM_X4_T(vbh, addr);
#pragma unroll
                for (int js = 0; js < 2; js++) {
                    int j = jd * 2 + js;
                    MMA_FP16(O[j], pah, vbh[js*2], vbh[js*2+1]);
                    MMA_FP16(O[j], pal, vbh[js*2], vbh[js*2+1]);
                }
            }
        }
        if (kt < qt) CP_WAIT0();
        __syncthreads();
    }
    float i0 = 1.f / l0, i1 = 1.f / l1;
    size_t rA = (size_t)(b * 2048 + qt * 64 + w * 16 + (lane >> 2));
    size_t rB = rA + 8;
    int colb = h * 64 + (lane & 3) * 2;
#pragma unroll
    for (int j = 0; j < 8; j++) {
        uint32_t hh, ll;
        int col = colb + j * 8;
        split2h(O[j][0] * i0, O[j][1] * i0, hh, ll);
        *(uint32_t*)(yh + rA * 1024 + col) = hh;
        *(uint32_t*)(yl + rA * 1024 + col) = ll;
        split2h(O[j][2] * i1, O[j][3] * i1, hh, ll);
        *(uint32_t*)(yh + rB * 1024 + col) = hh;
        *(uint32_t*)(yl + rB * 1024 + col) = ll;
    }
}

// ---------------- tile helpers for folding kernels ----------------
#define TP 68
__device__ __forceinline__ void load_tile_s(float* dst, const float* src, size_t stride, int tid) {
#pragma unroll
    for (int r = 0; r < 4; r++) {
        int f = tid + 256 * r;
        int row = f >> 4, c4 = (f & 15) << 2;
        *(float4*)&dst[row*TP + c4] = *(const float4*)(src + (size_t)row * stride + c4);
    }
}
__device__ __forceinline__ void load_tileT_s(float* dst, const float* src, size_t stride, int tid) {
#pragma unroll
    for (int r = 0; r < 4; r++) {
        int f = tid + 256 * r;
        int row = f >> 4, c4 = (f & 15) << 2;
        float4 v = *(const float4*)(src + (size_t)row * stride + c4);
        dst[(c4+0)*TP + row] = v.x; dst[(c4+1)*TP + row] = v.y;
        dst[(c4+2)*TP + row] = v.z; dst[(c4+3)*TP + row] = v.w;
    }
}
__device__ __forceinline__ void mm64(const float* XT, const float* W, float acc[4][4], int tx, int ty) {
#pragma unroll
    for (int c = 0; c < 64; c++) {
        float a[4], bb[4];
        *(float4*)a  = *(const float4*)&XT[c*TP + ty*4];
        *(float4*)bb = *(const float4*)&W [c*TP + tx*4];
#pragma unroll
        for (int i = 0; i < 4; i++)
#pragma unroll
            for (int j = 0; j < 4; j++) acc[i][j] = fmaf(a[i], bb[j], acc[i][j]);
    }
}

// ---------------- P1: fold s2 into mix ----------------
__global__ __launch_bounds__(256) void fold1_kernel(
    const float* __restrict__ Mix, const float* __restrict__ S2,
    float* __restrict__ WM2T, int in_f, int out_f,
    const int* __restrict__ selp)
{
    extern __shared__ float sm[];
    float* MT = sm;
    float* S  = sm + 4352;
    int jb = blockIdx.x, G = blockIdx.y, r = blockIdx.z;
    int sel = selp[r];
    int tid = threadIdx.x;
    load_tile_s(MT, Mix + (size_t)sel * out_f * in_f + (size_t)(G * 64) * in_f + jb * 64, in_f, tid);
    load_tile_s(S,  S2  + (size_t)sel * out_f * 64 + (size_t)G * 4096, 64, tid);
    __syncthreads();
    int tx = tid & 15, ty = tid >> 4;
    float acc[4][4] = {};
    mm64(MT, S, acc, tx, ty);
    float* outp = WM2T + (size_t)r * in_f * out_f;
#pragma unroll
    for (int i = 0; i < 4; i++) {
        size_t row = (size_t)(jb * 64 + ty * 4 + i);
        *(float4*)(outp + row * out_f + G * 64 + tx * 4) =
            make_float4(acc[i][0], acc[i][1], acc[i][2], acc[i][3]);
    }
}

// ---------------- P2: fold s1 + roll-perm, combine experts, fp16 out ----------------
__global__ __launch_bounds__(256) void fold2_kernel(
    const float* __restrict__ WM2T, const float* __restrict__ S1,
    __half* __restrict__ WH,
    int in_f, int out_f, int n_in,
    const int* __restrict__ selp, const float* __restrict__ coefp)
{
    extern __shared__ float sm[];
    float* G0 = sm;
    float* G1 = sm + 4352;
    float* T0 = sm + 8704;
    float* T1 = sm + 13056;
    int g = blockIdx.x, Ob = blockIdx.y, tid = threadIdx.x;
    int s0i = selp[0], s1i = selp[1];
    int gs0 = (g + s0i) % n_in, gs1 = (g + s1i) % n_in;
    const float* W0 = WM2T;
    const float* W1 = WM2T + (size_t)in_f * out_f;
#pragma unroll
    for (int r = 0; r < 4; r++) {
        int f = tid + 256 * r;
        int d = f >> 4, o4 = (f & 15) << 2;
        *(float4*)&G0[d*TP + o4] = *(const float4*)(W0 + (size_t)(d * n_in + gs0) * out_f + Ob * 64 + o4);
        *(float4*)&G1[d*TP + o4] = *(const float4*)(W1 + (size_t)(d * n_in + gs1) * out_f + Ob * 64 + o4);
    }
    load_tileT_s(T0, S1 + (size_t)s0i * in_f * 64 + (size_t)g * 4096, 64, tid);
    load_tileT_s(T1, S1 + (size_t)s1i * in_f * 64 + (size_t)g * 4096, 64, tid);
    __syncthreads();
    int tx = tid & 15, ty = tid >> 4;
    float a0[4][4] = {}, a1[4][4] = {};
    mm64(G0, T0, a0, tx, ty);
    mm64(G1, T1, a1, tx, ty);
    float c0 = coefp[0], c1 = coefp[1];
#pragma unroll
    for (int i = 0; i < 4; i++) {
        size_t base = (size_t)(Ob * 64 + ty * 4 + i) * in_f + g * 64 + tx * 4;
        float v0 = c0 * a0[i][0] + c1 * a1[i][0];
        float v1 = c0 * a0[i][1] + c1 * a1[i][1];
        float v2 = c0 * a0[i][2] + c1 * a1[i][2];
        float v3 = c0 * a0[i][3] + c1 * a1[i][3];
        *(uint32_t*)(WH + base)     = pack2h(v0, v1);
        *(uint32_t*)(WH + base + 2) = pack2h(v2, v3);
    }
}

// ---------------- top-2 router ----------------
__global__ void router_kernel(const float* __restrict__ fcl, const float* __restrict__ pjl,
                              int* __restrict__ sel, float* __restrict__ coef)
{
    if (threadIdx.x == 0 && blockIdx.x == 0) {
#pragma unroll
        for (int s = 0; s < 2; s++) {
            const float* L = s ? pjl : fcl;
            int i1 = 0; float v1 = L[0];
            for (int i = 1; i < 8; i++) if (L[i] > v1) { v1 = L[i]; i1 = i; }
            int i2 = -1; float v2 = -1e30f;
            for (int i = 0; i < 8; i++) if (i != i1 && L[i] > v2) { v2 = L[i]; i2 = i; }
            float e = expf(v2 - v1);
            float z = 1.f + e;
            sel[s*2+0] = i1; sel[s*2+1] = i2;
            coef[s*2+0] = 1.f / z; coef[s*2+1] = e / z;
        }
    }
}

// ---------------- host orchestration ----------------
#define FOLD1_SMEM (8704 * 4)
#define FOLD2_SMEM (17408 * 4)

extern "C" void kernel_launch(void* const* d_in, const int* in_sizes, int n_in_,
                              void* d_out, int out_size)
{
    (void)in_sizes; (void)n_in_; (void)out_size;
    const float* x      = (const float*)d_in[0];
    const float* wq     = (const float*)d_in[1];
    const float* wk     = (const float*)d_in[2];
    const float* wv     = (const float*)d_in[3];
    const float* wo     = (const float*)d_in[4];
    const float* qg     = (const float*)d_in[5];
    const float* kg     = (const float*)d_in[6];
    const float* fc_s1  = (const float*)d_in[7];
    const float* fc_s2  = (const float*)d_in[8];
    const float* fc_mix = (const float*)d_in[9];
    const float* fc_lg  = (const float*)d_in[10];
    const float* pj_s1  = (const float*)d_in[11];
    const float* pj_s2  = (const float*)d_in[12];
    const float* pj_mix = (const float*)d_in[13];
    const float* pj_lg  = (const float*)d_in[14];

    float *x2, *wm0, *wm1, *coef;
    int* sel;
    __half *ah, *al, *gh, *gl, *wh, *who, *wfch, *wpjh, *yh, *yl, *qh, *ql, *kh, *vh;
    cudaGetSymbolAddress((void**)&x2,  g_x2);
    cudaGetSymbolAddress((void**)&wm0, g_wm0);
    cudaGetSymbolAddress((void**)&wm1, g_wm1);
    cudaGetSymbolAddress((void**)&sel,  g_sel);
    cudaGetSymbolAddress((void**)&coef, g_coef);
    cudaGetSymbolAddress((void**)&ah, g_ah);
    cudaGetSymbolAddress((void**)&al, g_al);
    cudaGetSymbolAddress((void**)&gh, g_gh);
    cudaGetSymbolAddress((void**)&gl, g_gl);
    cudaGetSymbolAddress((void**)&wh, g_wh);
    cudaGetSymbolAddress((void**)&who, g_who);
    cudaGetSymbolAddress((void**)&wfch, g_wfch);
    cudaGetSymbolAddress((void**)&wpjh, g_wpjh);
    cudaGetSymbolAddress((void**)&yh, g_yh);
    cudaGetSymbolAddress((void**)&yl, g_yl);
    cudaGetSymbolAddress((void**)&qh, g_qh);
    cudaGetSymbolAddress((void**)&ql, g_ql);
    cudaGetSymbolAddress((void**)&kh, g_kh);
    cudaGetSymbolAddress((void**)&vh, g_vh);

    cudaFuncSetAttribute(gemm_fp16x2, cudaFuncAttributeMaxDynamicSharedMemorySize, GEMM_SMEM);
    cudaFuncSetAttribute(attn_mma_kernel, cudaFuncAttributeMaxDynamicSharedMemorySize, ATTN_SMEM);
    cudaFuncSetAttribute(fold1_kernel, cudaFuncAttributeMaxDynamicSharedMemorySize, FOLD1_SMEM);
    cudaFuncSetAttribute(fold2_kernel, cudaFuncAttributeMaxDynamicSharedMemorySize, FOLD2_SMEM);

    // side stream + fork/join events (created once, outside any capture)
    static cudaStream_t s2 = nullptr;
    static cudaEvent_t ev_fork = nullptr, ev_wo = nullptr, ev_fold = nullptr;
    if (!s2) {
        cudaStreamCreateWithFlags(&s2, cudaStreamNonBlocking);
        cudaEventCreateWithFlags(&ev_fork, cudaEventDisableTiming);
        cudaEventCreateWithFlags(&ev_wo,   cudaEventDisableTiming);
        cudaEventCreateWithFlags(&ev_fold, cudaEventDisableTiming);
    }

    // ---- fork: side stream does wo-split + routing + weight folding ----
    cudaEventRecord(ev_fork, 0);
    cudaStreamWaitEvent(s2, ev_fork, 0);

    splith_kernel<<<512, 256, 0, s2>>>(wo, who, 1048576);
    cudaEventRecord(ev_wo, s2);
    router_kernel<<<1, 32, 0, s2>>>(fc_lg, pj_lg, sel, coef);
    fold1_kernel<<<dim3(16, 64, 2), 256, FOLD1_SMEM, s2>>>(fc_mix, fc_s2, wm0, 1024, 4096, sel);
    fold2_kernel<<<dim3(16, 64), 256, FOLD2_SMEM, s2>>>(wm0, fc_s1, wfch, 1024, 4096, 16, sel, coef);
    fold1_kernel<<<dim3(64, 16, 2), 256, FOLD1_SMEM, s2>>>(pj_mix, pj_s2, wm1, 4096, 1024, sel + 2);
    fold2_kernel<<<dim3(64, 16), 256, FOLD2_SMEM, s2>>>(wm1, pj_s1, wpjh, 4096, 1024, 64, sel + 2, coef + 2);
    cudaEventRecord(ev_fold, s2);

    // ---- main stream: attention path ----
    rmsnorm_split_kernel<<<4096, 256>>>(x, ah, al);
    splith_kernel<<<512, 256>>>(wq, wh, 1048576);
    splith_kernel<<<128, 256>>>(wk, wh + 1048576, 262144);
    splith_kernel<<<128, 256>>>(wv, wh + 1310720, 262144);
    gemm_fp16x2<<<dim3(12, 32), 256, GEMM_SMEM>>>(ah, al, wh, nullptr, nullptr, 1536, 1024,
                                                  nullptr, nullptr, 2,
                                                  qh, ql, kh, vh, qg, kg);
    attn_mma_kernel<<<dim3(32, 16, 2), 128, ATTN_SMEM>>>(qh, ql, kh, vh, yh, yl);

    // join 1: wo weights ready
    cudaStreamWaitEvent(0, ev_wo, 0);
    gemm_fp16x2<<<dim3(8, 32), 256, GEMM_SMEM>>>(yh, yl, who, x2, x, 1024, 1024,
                                                 nullptr, nullptr, 0,
                                                 nullptr, nullptr, nullptr, nullptr, nullptr, nullptr);

    rmsnorm_split_kernel<<<4096, 256>>>(x2, ah, al);

    // join 2: folded weights ready
    cudaStreamWaitEvent(0, ev_fold, 0);
    gemm_fp16x2<<<dim3(32, 32), 256, GEMM_SMEM>>>(ah, al, wfch, nullptr, nullptr, 4096, 1024,
                                                  gh, gl, 1,
                                                  nullptr, nullptr, nullptr, nullptr, nullptr, nullptr);
    gemm_fp16x2<<<dim3(8, 32), 256, GEMM_SMEM>>>(gh, gl, wpjh, (float*)d_out, x2, 1024, 4096,
                                                 nullptr, nullptr, 0,
                                                 nullptr, nullptr, nullptr, nullptr, nullptr, nullptr);
}

// round 11
// speedup vs baseline: 8.2084x; 1.0863x over previous
#include <cuda_runtime.h>
#include <cuda_bf16.h>
#include <cuda_fp16.h>
#include <math.h>
#include <stdint.h>

// ---------------- static device scratch ----------------
static __device__ float g_x2 [4096*1024];
static __device__ float g_wm0[8388608];
static __device__ float g_wm1[8388608];
static __device__ int   g_sel[4];
static __device__ float g_coef[4];
static __device__ __half g_ah[4194304];
static __device__ __half g_al[4194304];
static __device__ __half g_gh[16777216];
static __device__ __half g_wh[4194304];      // qkv weights fp16
static __device__ __half g_who[1048576];     // wo weights fp16
static __device__ __half g_wfch[4194304];
static __device__ __half g_wpjh[4194304];
static __device__ __half g_yh[4194304];
static __device__ __half g_yl[4194304];
static __device__ __half g_qh[4194304];
static __device__ __half g_kh[1048576];
static __device__ __half g_vh[1048576];

// ---------------- PTX helpers ----------------
__device__ __forceinline__ uint32_t smem_u32(const void* p) {
    uint32_t a;
    asm("{ .reg .u64 t; cvta.to.shared.u64 t, %1; cvt.u32.u64 %0, t; }" : "=r"(a) : "l"(p));
    return a;
}
#define CP_ASYNC16(dst, src) \
    asm volatile("cp.async.cg.shared.global [%0], [%1], 16;" :: "r"(dst), "l"(src))
#define CP_COMMIT() asm volatile("cp.async.commit_group;" ::: "memory")
#define CP_WAIT1()  asm volatile("cp.async.wait_group 1;" ::: "memory")
#define CP_WAIT0()  asm volatile("cp.async.wait_group 0;" ::: "memory")

#define LDSM_X4(r, addr) \
    asm volatile("ldmatrix.sync.aligned.m8n8.x4.shared.b16 {%0,%1,%2,%3}, [%4];" \
        : "=r"((r)[0]), "=r"((r)[1]), "=r"((r)[2]), "=r"((r)[3]) : "r"(addr))
#define LDSM_X4_T(r, addr) \
    asm volatile("ldmatrix.sync.aligned.m8n8.x4.trans.shared.b16 {%0,%1,%2,%3}, [%4];" \
        : "=r"((r)[0]), "=r"((r)[1]), "=r"((r)[2]), "=r"((r)[3]) : "r"(addr))

#define MMA_FP16(d, a, b0, b1) \
    asm volatile("mma.sync.aligned.m16n8k16.row.col.f32.f16.f16.f32 " \
        "{%0,%1,%2,%3}, {%4,%5,%6,%7}, {%8,%9}, {%0,%1,%2,%3};" \
        : "+f"((d)[0]), "+f"((d)[1]), "+f"((d)[2]), "+f"((d)[3]) \
        : "r"((a)[0]), "r"((a)[1]), "r"((a)[2]), "r"((a)[3]), "r"(b0), "r"(b1))

__device__ __forceinline__ void split2h(float v0, float v1, uint32_t& h, uint32_t& l) {
    __half h0 = __float2half_rn(v0), h1 = __float2half_rn(v1);
    float r0 = v0 - __half2float(h0), r1 = v1 - __half2float(h1);
    __half l0 = __float2half_rn(r0), l1 = __float2half_rn(r1);
    h = (uint32_t)*(uint16_t*)&h0 | ((uint32_t)*(uint16_t*)&h1 << 16);
    l = (uint32_t)*(uint16_t*)&l0 | ((uint32_t)*(uint16_t*)&l1 << 16);
}
__device__ __forceinline__ uint32_t pack2h(float v0, float v1) {
    __half h0 = __float2half_rn(v0), h1 = __float2half_rn(v1);
    return (uint32_t)*(uint16_t*)&h0 | ((uint32_t)*(uint16_t*)&h1 << 16);
}

// ---------------- fp32 -> fp16 weight convert ----------------
__global__ void splith_kernel(const float* __restrict__ src, __half* __restrict__ hi, int n)
{
    int i = (blockIdx.x * blockDim.x + threadIdx.x) * 8;
    if (i >= n) return;
    float4 a = *(const float4*)(src + i);
    float4 b = *(const float4*)(src + i + 4);
    uint4 H;
    H.x = pack2h(a.x, a.y); H.y = pack2h(a.z, a.w);
    H.z = pack2h(b.x, b.y); H.w = pack2h(b.z, b.w);
    *(uint4*)(hi + i) = H;
}

// ---------------- HMMA fp16 GEMM (A hi + optional lo, W fp16) ----------------
#define TSTA 144
#define TSTW 80
#define A_BYTES (128 * TSTA)
#define W_BYTES (128 * TSTW)
#define STG (A_BYTES + W_BYTES)
#define GEMM_SMEM (3 * STG)

__device__ __forceinline__ void gemm_load_stage(
    uint32_t smbase, int kt, int NT, int K, int tid,
    const __half* s0, const __half* s1, const __half* s2)
{
    if (kt < NT) {
        uint32_t sb = smbase + (kt % 3) * STG;
        int k0 = kt * 32;
#pragma unroll
        for (int t = 0; t < 6; t++) {
            int idx = tid + 256 * t;
            if (idx < 1024) {
                int row = idx >> 3, ch = idx & 7;
                if (ch < 4) {
                    CP_ASYNC16(sb + row * TSTA + ch * 16,
                               s0 + (size_t)row * K + k0 + ch * 8);
                } else if (s1) {
                    CP_ASYNC16(sb + row * TSTA + 64 + (ch - 4) * 16,
                               s1 + (size_t)row * K + k0 + (ch - 4) * 8);
                }
            } else {
                int cc = idx - 1024;
                int row = cc >> 2, ch = cc & 3;
                CP_ASYNC16(sb + A_BYTES + row * TSTW + ch * 16,
                           s2 + (size_t)row * K + k0 + ch * 8);
            }
        }
    }
    CP_COMMIT();
}

// mode 0: C fp32 (+res); mode 1: relu^2 -> fp16 (OH, single); mode 2: fused qkv prep
__global__ __launch_bounds__(256, 2) void gemm_fp16x2(
    const __half* __restrict__ Ah, const __half* __restrict__ Al,
    const __half* __restrict__ Wh,
    float* __restrict__ C, const float* __restrict__ res, int N, int K,
    __half* __restrict__ OH, int mode,
    __half* __restrict__ qh, __half* __restrict__ kh, __half* __restrict__ vh,
    const float* __restrict__ qg, const float* __restrict__ kg)
{
    extern __shared__ char smem[];
    uint32_t smbase = smem_u32(smem);
    int tid = threadIdx.x, wid = tid >> 5, lane = tid & 31;
    int m0 = blockIdx.y * 128, n0 = blockIdx.x * 128;
    int wm = wid >> 1, wn = wid & 1;

    const __half* s0 = Ah + (size_t)m0 * K;
    const __half* s1 = Al ? Al + (size_t)m0 * K : nullptr;
    const __half* s2 = Wh + (size_t)n0 * K;

    float acc[2][8][4];
#pragma unroll
    for (int i = 0; i < 2; i++)
#pragma unroll
        for (int j = 0; j < 8; j++)
#pragma unroll
            for (int r = 0; r < 4; r++) acc[i][j][r] = 0.f;

    int NT = K >> 5;
    gemm_load_stage(smbase, 0, NT, K, tid, s0, s1, s2);
    gemm_load_stage(smbase, 1, NT, K, tid, s0, s1, s2);

    int lt = lane >> 3, lr = lane & 7;
    for (int kt = 0; kt < NT; kt++) {
        CP_WAIT1();
        __syncthreads();
        gemm_load_stage(smbase, kt + 2, NT, K, tid, s0, s1, s2);
        uint32_t sb = smbase + (kt % 3) * STG;
        uint32_t sbW = sb + A_BYTES;
#pragma unroll
        for (int kk = 0; kk < 2; kk++) {
            uint32_t a_hi[2][4], a_lo[2][4];
#pragma unroll
            for (int i = 0; i < 2; i++) {
                int row = wm * 32 + i * 16 + lr + (lt & 1) * 8;
                int kofs = kk * 16 + (lt >> 1) * 8;
                uint32_t addr = sb + row * TSTA + kofs * 2;
                LDSM_X4(a_hi[i], addr);
                if (Al) LDSM_X4(a_lo[i], addr + 64);
            }
            uint32_t b_hi[4][4];
#pragma unroll
            for (int j = 0; j < 4; j++) {
                int row = wn * 64 + j * 16 + lr + (lt >> 1) * 8;
                int kofs = kk * 16 + (lt & 1) * 8;
                LDSM_X4(b_hi[j], sbW + row * TSTW + kofs * 2);
            }
#pragma unroll
            for (int i = 0; i < 2; i++)
#pragma unroll
                for (int j = 0; j < 8; j++) {
                    uint32_t bh0 = b_hi[j >> 1][(j & 1) * 2], bh1 = b_hi[j >> 1][(j & 1) * 2 + 1];
                    MMA_FP16(acc[i][j], a_hi[i], bh0, bh1);
                    if (Al) MMA_FP16(acc[i][j], a_lo[i], bh0, bh1);
                }
        }
    }
    CP_WAIT0();

    int rbase = m0 + wm * 32 + (lane >> 2);
    int cbase = n0 + wn * 64 + (lane & 3) * 2;

    if (mode == 2) {
        int hd = blockIdx.x * 2 + wn;    // 0-15 q, 16-19 k, 20-23 v
#pragma unroll
        for (int i = 0; i < 2; i++) {
#pragma unroll
            for (int half = 0; half < 2; half++) {
                int m = rbase + i * 16 + half * 8;
                int t = m & 2047, bb = m >> 11;
                float vals[8][2];
#pragma unroll
                for (int j = 0; j < 8; j++) {
                    vals[j][0] = acc[i][j][half * 2 + 0];
                    vals[j][1] = acc[i][j][half * 2 + 1];
                }
                if (hd < 20) {
                    float ss = 0.f;
#pragma unroll
                    for (int j = 0; j < 8; j++) ss += vals[j][0]*vals[j][0] + vals[j][1]*vals[j][1];
                    ss += __shfl_xor_sync(0xffffffffu, ss, 1);
                    ss += __shfl_xor_sync(0xffffffffu, ss, 2);
                    float gain = (hd < 16) ? qg[hd] : kg[hd - 16];
                    float r = rsqrtf(ss * (1.f/64.f) + 1e-6f) * gain;
#pragma unroll
                    for (int j = 0; j < 4; j++) {
                        float o1[2], o2[2];
#pragma unroll
                        for (int s = 0; s < 2; s++) {
                            int p = (lane & 3) * 2 + j * 8 + s;
                            float ang = (float)t * exp2f(-0.41524101186092029f * (float)p);
                            float sn, cs;
                            sincosf(ang, &sn, &cs);
                            float v1 = vals[j][s] * r, v2 = vals[j + 4][s] * r;
                            o1[s] = v1 * cs + v2 * sn;
                            o2[s] = v2 * cs - v1 * sn;
                        }
                        int c0 = (lane & 3) * 2 + j * 8;
                        if (hd < 16) {
                            size_t base = ((size_t)(bb * 16 + hd) * 2048 + t) * 64;
                            *(uint32_t*)(qh + base + c0)      = pack2h(o1[0], o1[1]);
                            *(uint32_t*)(qh + base + c0 + 32) = pack2h(o2[0], o2[1]);
                        } else {
                            size_t base = ((size_t)(bb * 4 + hd - 16) * 2048 + t) * 64;
                            *(uint32_t*)(kh + base + c0)      = pack2h(o1[0], o1[1]);
                            *(uint32_t*)(kh + base + c0 + 32) = pack2h(o2[0], o2[1]);
                        }
                    }
                } else {
                    size_t base = ((size_t)(bb * 4 + hd - 20) * 2048 + t) * 64;
#pragma unroll
                    for (int j = 0; j < 8; j++) {
                        int c0 = (lane & 3) * 2 + j * 8;
                        *(uint32_t*)(vh + base + c0) = pack2h(vals[j][0], vals[j][1]);
                    }
                }
            }
        }
        return;
    }

#pragma unroll
    for (int i = 0; i < 2; i++) {
#pragma unroll
        for (int half = 0; half < 2; half++) {
            size_t row = (size_t)(rbase + i * 16 + half * 8);
#pragma unroll
            for (int j = 0; j < 8; j++) {
                size_t idx = row * (size_t)N + cbase + j * 8;
                float v0 = acc[i][j][half * 2 + 0];
                float v1 = acc[i][j][half * 2 + 1];
                if (mode == 1) {
                    v0 = fmaxf(v0, 0.f); v0 *= v0;
                    v1 = fmaxf(v1, 0.f); v1 *= v1;
                    *(uint32_t*)(OH + idx) = pack2h(v0, v1);
                } else {
                    if (res) { v0 += res[idx]; v1 += res[idx + 1]; }
                    *(float2*)(C + idx) = make_float2(v0, v1);
                }
            }
        }
    }
}

// ---------------- RMSNorm with fp16 hi/lo split output ----------------
__global__ void rmsnorm_split_kernel(const float* __restrict__ x,
                                     __half* __restrict__ hi, __half* __restrict__ lo)
{
    int n = blockIdx.x;
    int tid = threadIdx.x;
    const float4* xr = (const float4*)(x + (size_t)n * 1024);
    float4 v = xr[tid];
    float s = v.x*v.x + v.y*v.y + v.z*v.z + v.w*v.w;
#pragma unroll
    for (int off = 16; off > 0; off >>= 1) s += __shfl_xor_sync(0xffffffffu, s, off);
    __shared__ float red[8];
    if ((tid & 31) == 0) red[tid >> 5] = s;
    __syncthreads();
    float tot = 0.f;
#pragma unroll
    for (int i = 0; i < 8; i++) tot += red[i];
    float r = rsqrtf(tot * (1.f/1024.f) + 1e-6f);
    uint32_t h0,l0,h1,l1;
    split2h(v.x*r, v.y*r, h0, l0);
    split2h(v.z*r, v.w*r, h1, l1);
    size_t base = (size_t)n * 1024 + tid * 4;
    *(uint2*)(hi + base) = make_uint2(h0, h1);
    *(uint2*)(lo + base) = make_uint2(l0, l1);
}

// ---------------- tensor-core flash attention (single fp16) ----------------
#define AT_ROWB 144
#define AT_TILE (64 * AT_ROWB)
#define AT_STAGE (2 * AT_TILE)
#define ATTN_SMEM (AT_TILE + 2 * AT_STAGE)    // 46080

__device__ __forceinline__ void attn_load_kv(
    uint32_t dstbase, int tid,
    const __half* kh, const __half* vh, size_t kvoff, int kt)
{
#pragma unroll
    for (int t = 0; t < 8; t++) {
        int idx = tid + 128 * t;
        int buf = idx >> 9, cc = idx & 511, row = cc >> 3, ch = cc & 7;
        const __half* src = (buf ? vh : kh) + kvoff + (size_t)(kt * 64 + row) * 64 + ch * 8;
        CP_ASYNC16(dstbase + buf * AT_TILE + row * AT_ROWB + ch * 16, src);
    }
}

__global__ __launch_bounds__(128) void attn_mma_kernel(
    const __half* __restrict__ qh,
    const __half* __restrict__ kh, const __half* __restrict__ vh,
    __half* __restrict__ yh, __half* __restrict__ yl)
{
    extern __shared__ char smem[];
    uint32_t sb = smem_u32(smem);
    int qt = gridDim.x - 1 - blockIdx.x;
    int h = blockIdx.y, b = blockIdx.z;
    int tid = threadIdx.x, w = tid >> 5, lane = tid & 31;
    int lr = lane & 7, lt = lane >> 3;
    size_t qoff = ((size_t)(b * 16 + h) * 2048 + qt * 64) * 64;
    size_t kvoff = (size_t)(b * 4 + (h >> 2)) * 2048 * 64;

#pragma unroll
    for (int t = 0; t < 4; t++) {
        int idx = tid + 128 * t;                 // 0..511
        int row = idx >> 3, ch = idx & 7;
        CP_ASYNC16(sb + row * AT_ROWB + ch * 16, qh + qoff + row * 64 + ch * 8);
    }
    CP_COMMIT();
    attn_load_kv(sb + AT_TILE, tid, kh, vh, kvoff, 0);
    CP_COMMIT();
    CP_WAIT0();
    __syncthreads();

    uint32_t qfh[4][4];
#pragma unroll
    for (int kk = 0; kk < 4; kk++) {
        uint32_t addr = sb + (w * 16 + lr + (lt & 1) * 8) * AT_ROWB + (kk * 16 + (lt >> 1) * 8) * 2;
        LDSM_X4(qfh[kk], addr);
    }

    float O[8][4];
#pragma unroll
    for (int j = 0; j < 8; j++)
#pragma unroll
        for (int r = 0; r < 4; r++) O[j][r] = 0.f;
    float m0 = -1e30f, m1 = -1e30f, l0 = 0.f, l1 = 0.f;

    for (int kt = 0; kt <= qt; kt++) {
        if (kt < qt) {
            attn_load_kv(sb + AT_TILE + ((kt + 1) & 1) * AT_STAGE, tid, kh, vh, kvoff, kt + 1);
            CP_COMMIT();
        }
        uint32_t kb = sb + AT_TILE + (kt & 1) * AT_STAGE;
        float c[8][4];
#pragma unroll
        for (int j = 0; j < 8; j++)
#pragma unroll
            for (int r = 0; r < 4; r++) c[j][r] = 0.f;
#pragma unroll
        for (int kk = 0; kk < 4; kk++) {
            uint32_t kbh[4][4];
#pragma unroll
            for (int j2 = 0; j2 < 4; j2++) {
                uint32_t addr = kb + (j2 * 16 + lr + (lt >> 1) * 8) * AT_ROWB + (kk * 16 + (lt & 1) * 8) * 2;
                LDSM_X4(kbh[j2], addr);
            }
#pragma unroll
            for (int j = 0; j < 8; j++) {
                MMA_FP16(c[j], qfh[kk], kbh[j >> 1][(j & 1) * 2], kbh[j >> 1][(j & 1) * 2 + 1]);
            }
        }
        if (kt == qt) {
            int r0 = w * 16 + (lane >> 2), r1 = r0 + 8;
#pragma unroll
            for (int j = 0; j < 8; j++) {
                int col = j * 8 + (lane & 3) * 2;
                if (col     > r0) c[j][0] = -1e30f;
                if (col + 1 > r0) c[j][1] = -1e30f;
                if (col     > r1) c[j][2] = -1e30f;
                if (col + 1 > r1) c[j][3] = -1e30f;
            }
        }
        float mx0 = -1e30f, mx1 = -1e30f;
#pragma unroll
        for (int j = 0; j < 8; j++) {
            mx0 = fmaxf(mx0, fmaxf(c[j][0], c[j][1]));
            mx1 = fmaxf(mx1, fmaxf(c[j][2], c[j][3]));
        }
        mx0 *= 0.125f; mx1 *= 0.125f;
        mx0 = fmaxf(mx0, __shfl_xor_sync(0xffffffffu, mx0, 1));
        mx0 = fmaxf(mx0, __shfl_xor_sync(0xffffffffu, mx0, 2));
        mx1 = fmaxf(mx1, __shfl_xor_sync(0xffffffffu, mx1, 1));
        mx1 = fmaxf(mx1, __shfl_xor_sync(0xffffffffu, mx1, 2));
        float m0n = fmaxf(m0, mx0), m1n = fmaxf(m1, mx1);
        float cr0 = __expf(m0 - m0n), cr1 = __expf(m1 - m1n);
        float s0 = 0.f, s1 = 0.f;
#pragma unroll
        for (int j = 0; j < 8; j++) {
            c[j][0] = __expf(fmaf(c[j][0], 0.125f, -m0n)); s0 += c[j][0];
            c[j][1] = __expf(fmaf(c[j][1], 0.125f, -m0n)); s0 += c[j][1];
            c[j][2] = __expf(fmaf(c[j][2], 0.125f, -m1n)); s1 += c[j][2];
            c[j][3] = __expf(fmaf(c[j][3], 0.125f, -m1n)); s1 += c[j][3];
        }
        s0 += __shfl_xor_sync(0xffffffffu, s0, 1);
        s0 += __shfl_xor_sync(0xffffffffu, s0, 2);
        s1 += __shfl_xor_sync(0xffffffffu, s1, 1);
        s1 += __shfl_xor_sync(0xffffffffu, s1, 2);
        l0 = l0 * cr0 + s0; l1 = l1 * cr1 + s1;
        m0 = m0n; m1 = m1n;
#pragma unroll
        for (int j = 0; j < 8; j++) {
            O[j][0] *= cr0; O[j][1] *= cr0;
            O[j][2] *= cr1; O[j][3] *= cr1;
        }
#pragma unroll
        for (int kt2 = 0; kt2 < 4; kt2++) {
            uint32_t pah[4];
            pah[0] = pack2h(c[2*kt2][0],   c[2*kt2][1]);
            pah[1] = pack2h(c[2*kt2][2],   c[2*kt2][3]);
            pah[2] = pack2h(c[2*kt2+1][0], c[2*kt2+1][1]);
            pah[3] = pack2h(c[2*kt2+1][2], c[2*kt2+1][3]);
#pragma unroll
            for (int jd = 0; jd < 4; jd++) {
                uint32_t vbh[4];
                uint32_t addr = kb + AT_TILE + (kt2 * 16 + (lt & 1) * 8 + lr) * AT_ROWB + (jd * 16 + (lt >> 1) * 8) * 2;
                LDSM_X4_T(vbh, addr);
#pragma unroll
                for (int js = 0; js < 2; js++) {
                    MMA_FP16(O[jd * 2 + js], pah, vbh[js*2], vbh[js*2+1]);
                }
            }
        }
        if (kt < qt) CP_WAIT0();
        __syncthreads();
    }
    float i0 = 1.f / l0, i1 = 1.f / l1;
    size_t rA = (size_t)(b * 2048 + qt * 64 + w * 16 + (lane >> 2));
    size_t rB = rA + 8;
    int colb = h * 64 + (lane & 3) * 2;
#pragma unroll
    for (int j = 0; j < 8; j++) {
        uint32_t hh, ll;
        int col = colb + j * 8;
        split2h(O[j][0] * i0, O[j][1] * i0, hh, ll);
        *(uint32_t*)(yh + rA * 1024 + col) = hh;
        *(uint32_t*)(yl + rA * 1024 + col) = ll;
        split2h(O[j][2] * i1, O[j][3] * i1, hh, ll);
        *(uint32_t*)(yh + rB * 1024 + col) = hh;
        *(uint32_t*)(yl + rB * 1024 + col) = ll;
    }
}

// ---------------- tile helpers for folding kernels ----------------
#define TP 68
__device__ __forceinline__ void load_tile_s(float* dst, const float* src, size_t stride, int tid) {
#pragma unroll
    for (int r = 0; r < 4; r++) {
        int f = tid + 256 * r;
        int row = f >> 4, c4 = (f & 15) << 2;
        *(float4*)&dst[row*TP + c4] = *(const float4*)(src + (size_t)row * stride + c4);
    }
}
__device__ __forceinline__ void load_tileT_s(float* dst, const float* src, size_t stride, int tid) {
#pragma unroll
    for (int r = 0; r < 4; r++) {
        int f = tid + 256 * r;
        int row = f >> 4, c4 = (f & 15) << 2;
        float4 v = *(const float4*)(src + (size_t)row * stride + c4);
        dst[(c4+0)*TP + row] = v.x; dst[(c4+1)*TP + row] = v.y;
        dst[(c4+2)*TP + row] = v.z; dst[(c4+3)*TP + row] = v.w;
    }
}
__device__ __forceinline__ void mm64(const float* XT, const float* W, float acc[4][4], int tx, int ty) {
#pragma unroll
    for (int c = 0; c < 64; c++) {
        float a[4], bb[4];
        *(float4*)a  = *(const float4*)&XT[c*TP + ty*4];
        *(float4*)bb = *(const float4*)&W [c*TP + tx*4];
#pragma unroll
        for (int i = 0; i < 4; i++)
#pragma unroll
            for (int j = 0; j < 4; j++) acc[i][j] = fmaf(a[i], bb[j], acc[i][j]);
    }
}

// ---------------- P1: fold s2 into mix ----------------
__global__ __launch_bounds__(256) void fold1_kernel(
    const float* __restrict__ Mix, const float* __restrict__ S2,
    float* __restrict__ WM2T, int in_f, int out_f,
    const int* __restrict__ selp)
{
    extern __shared__ float sm[];
    float* MT = sm;
    float* S  = sm + 4352;
    int jb = blockIdx.x, G = blockIdx.y, r = blockIdx.z;
    int sel = selp[r];
    int tid = threadIdx.x;
    load_tile_s(MT, Mix + (size_t)sel * out_f * in_f + (size_t)(G * 64) * in_f + jb * 64, in_f, tid);
    load_tile_s(S,  S2  + (size_t)sel * out_f * 64 + (size_t)G * 4096, 64, tid);
    __syncthreads();
    int tx = tid & 15, ty = tid >> 4;
    float acc[4][4] = {};
    mm64(MT, S, acc, tx, ty);
    float* outp = WM2T + (size_t)r * in_f * out_f;
#pragma unroll
    for (int i = 0; i < 4; i++) {
        size_t row = (size_t)(jb * 64 + ty * 4 + i);
        *(float4*)(outp + row * out_f + G * 64 + tx * 4) =
            make_float4(acc[i][0], acc[i][1], acc[i][2], acc[i][3]);
    }
}

// ---------------- P2: fold s1 + roll-perm, combine experts, fp16 out ----------------
__global__ __launch_bounds__(256) void fold2_kernel(
    const float* __restrict__ WM2T, const float* __restrict__ S1,
    __half* __restrict__ WH,
    int in_f, int out_f, int n_in,
    const int* __restrict__ selp, const float* __restrict__ coefp)
{
    extern __shared__ float sm[];
    float* G0 = sm;
    float* G1 = sm + 4352;
    float* T0 = sm + 8704;
    float* T1 = sm + 13056;
    int g = blockIdx.x, Ob = blockIdx.y, tid = threadIdx.x;
    int s0i = selp[0], s1i = selp[1];
    int gs0 = (g + s0i) % n_in, gs1 = (g + s1i) % n_in;
    const float* W0 = WM2T;
    const float* W1 = WM2T + (size_t)in_f * out_f;
#pragma unroll
    for (int r = 0; r < 4; r++) {
        int f = tid + 256 * r;
        int d = f >> 4, o4 = (f & 15) << 2;
        *(float4*)&G0[d*TP + o4] = *(const float4*)(W0 + (size_t)(d * n_in + gs0) * out_f + Ob * 64 + o4);
        *(float4*)&G1[d*TP + o4] = *(const float4*)(W1 + (size_t)(d * n_in + gs1) * out_f + Ob * 64 + o4);
    }
    load_tileT_s(T0, S1 + (size_t)s0i * in_f * 64 + (size_t)g * 4096, 64, tid);
    load_tileT_s(T1, S1 + (size_t)s1i * in_f * 64 + (size_t)g * 4096, 64, tid);
    __syncthreads();
    int tx = tid & 15, ty = tid >> 4;
    float a0[4][4] = {}, a1[4][4] = {};
    mm64(G0, T0, a0, tx, ty);
    mm64(G1, T1, a1, tx, ty);
    float c0 = coefp[0], c1 = coefp[1];
#pragma unroll
    for (int i = 0; i < 4; i++) {
        size_t base = (size_t)(Ob * 64 + ty * 4 + i) * in_f + g * 64 + tx * 4;
        float v0 = c0 * a0[i][0] + c1 * a1[i][0];
        float v1 = c0 * a0[i][1] + c1 * a1[i][1];
        float v2 = c0 * a0[i][2] + c1 * a1[i][2];
        float v3 = c0 * a0[i][3] + c1 * a1[i][3];
        *(uint32_t*)(WH + base)     = pack2h(v0, v1);
        *(uint32_t*)(WH + base + 2) = pack2h(v2, v3);
    }
}

// ---------------- top-2 router ----------------
__global__ void router_kernel(const float* __restrict__ fcl, const float* __restrict__ pjl,
                              int* __restrict__ sel, float* __restrict__ coef)
{
    if (threadIdx.x == 0 && blockIdx.x == 0) {
#pragma unroll
        for (int s = 0; s < 2; s++) {
            const float* L = s ? pjl : fcl;
            int i1 = 0; float v1 = L[0];
            for (int i = 1; i < 8; i++) if (L[i] > v1) { v1 = L[i]; i1 = i; }
            int i2 = -1; float v2 = -1e30f;
            for (int i = 0; i < 8; i++) if (i != i1 && L[i] > v2) { v2 = L[i]; i2 = i; }
            float e = expf(v2 - v1);
            float z = 1.f + e;
            sel[s*2+0] = i1; sel[s*2+1] = i2;
            coef[s*2+0] = 1.f / z; coef[s*2+1] = e / z;
        }
    }
}

// ---------------- host orchestration ----------------
#define FOLD1_SMEM (8704 * 4)
#define FOLD2_SMEM (17408 * 4)

extern "C" void kernel_launch(void* const* d_in, const int* in_sizes, int n_in_,
                              void* d_out, int out_size)
{
    (void)in_sizes; (void)n_in_; (void)out_size;
    const float* x      = (const float*)d_in[0];
    const float* wq     = (const float*)d_in[1];
    const float* wk     = (const float*)d_in[2];
    const float* wv     = (const float*)d_in[3];
    const float* wo     = (const float*)d_in[4];
    const float* qg     = (const float*)d_in[5];
    const float* kg     = (const float*)d_in[6];
    const float* fc_s1  = (const float*)d_in[7];
    const float* fc_s2  = (const float*)d_in[8];
    const float* fc_mix = (const float*)d_in[9];
    const float* fc_lg  = (const float*)d_in[10];
    const float* pj_s1  = (const float*)d_in[11];
    const float* pj_s2  = (const float*)d_in[12];
    const float* pj_mix = (const float*)d_in[13];
    const float* pj_lg  = (const float*)d_in[14];

    float *x2, *wm0, *wm1, *coef;
    int* sel;
    __half *ah, *al, *gh, *wh, *who, *wfch, *wpjh, *yh, *yl, *qh, *kh, *vh;
    cudaGetSymbolAddress((void**)&x2,  g_x2);
    cudaGetSymbolAddress((void**)&wm0, g_wm0);
    cudaGetSymbolAddress((void**)&wm1, g_wm1);
    cudaGetSymbolAddress((void**)&sel,  g_sel);
    cudaGetSymbolAddress((void**)&coef, g_coef);
    cudaGetSymbolAddress((void**)&ah, g_ah);
    cudaGetSymbolAddress((void**)&al, g_al);
    cudaGetSymbolAddress((void**)&gh, g_gh);
    cudaGetSymbolAddress((void**)&wh, g_wh);
    cudaGetSymbolAddress((void**)&who, g_who);
    cudaGetSymbolAddress((void**)&wfch, g_wfch);
    cudaGetSymbolAddress((void**)&wpjh, g_wpjh);
    cudaGetSymbolAddress((void**)&yh, g_yh);
    cudaGetSymbolAddress((void**)&yl, g_yl);
    cudaGetSymbolAddress((void**)&qh, g_qh);
    cudaGetSymbolAddress((void**)&kh, g_kh);
    cudaGetSymbolAddress((void**)&vh, g_vh);

    cudaFuncSetAttribute(gemm_fp16x2, cudaFuncAttributeMaxDynamicSharedMemorySize, GEMM_SMEM);
    cudaFuncSetAttribute(attn_mma_kernel, cudaFuncAttributeMaxDynamicSharedMemorySize, ATTN_SMEM);
    cudaFuncSetAttribute(fold1_kernel, cudaFuncAttributeMaxDynamicSharedMemorySize, FOLD1_SMEM);
    cudaFuncSetAttribute(fold2_kernel, cudaFuncAttributeMaxDynamicSharedMemorySize, FOLD2_SMEM);

    // side stream + fork/join events (created once, outside any capture)
    static cudaStream_t s2 = nullptr;
    static cudaEvent_t ev_fork = nullptr, ev_wqkv = nullptr, ev_wo = nullptr, ev_fold = nullptr;
    if (!s2) {
        cudaStreamCreateWithFlags(&s2, cudaStreamNonBlocking);
        cudaEventCreateWithFlags(&ev_fork, cudaEventDisableTiming);
        cudaEventCreateWithFlags(&ev_wqkv, cudaEventDisableTiming);
        cudaEventCreateWithFlags(&ev_wo,   cudaEventDisableTiming);
        cudaEventCreateWithFlags(&ev_fold, cudaEventDisableTiming);
    }

    // ---- fork: side stream does weight converts + routing + folding ----
    cudaEventRecord(ev_fork, 0);
    cudaStreamWaitEvent(s2, ev_fork, 0);

    splith_kernel<<<512, 256, 0, s2>>>(wq, wh, 1048576);
    splith_kernel<<<128, 256, 0, s2>>>(wk, wh + 1048576, 262144);
    splith_kernel<<<128, 256, 0, s2>>>(wv, wh + 1310720, 262144);
    cudaEventRecord(ev_wqkv, s2);
    splith_kernel<<<512, 256, 0, s2>>>(wo, who, 1048576);
    cudaEventRecord(ev_wo, s2);
    router_kernel<<<1, 32, 0, s2>>>(fc_lg, pj_lg, sel, coef);
    fold1_kernel<<<dim3(16, 64, 2), 256, FOLD1_SMEM, s2>>>(fc_mix, fc_s2, wm0, 1024, 4096, sel);
    fold2_kernel<<<dim3(16, 64), 256, FOLD2_SMEM, s2>>>(wm0, fc_s1, wfch, 1024, 4096, 16, sel, coef);
    fold1_kernel<<<dim3(64, 16, 2), 256, FOLD1_SMEM, s2>>>(pj_mix, pj_s2, wm1, 4096, 1024, sel + 2);
    fold2_kernel<<<dim3(64, 16), 256, FOLD2_SMEM, s2>>>(wm1, pj_s1, wpjh, 4096, 1024, 64, sel + 2, coef + 2);
    cudaEventRecord(ev_fold, s2);

    // ---- main stream: attention path ----
    rmsnorm_split_kernel<<<4096, 256>>>(x, ah, al);
    cudaStreamWaitEvent(0, ev_wqkv, 0);
    gemm_fp16x2<<<dim3(12, 32), 256, GEMM_SMEM>>>(ah, al, wh, nullptr, nullptr, 1536, 1024,
                                                  nullptr, 2, qh, kh, vh, qg, kg);
    attn_mma_kernel<<<dim3(32, 16, 2), 128, ATTN_SMEM>>>(qh, kh, vh, yh, yl);

    cudaStreamWaitEvent(0, ev_wo, 0);
    gemm_fp16x2<<<dim3(8, 32), 256, GEMM_SMEM>>>(yh, yl, who, x2, x, 1024, 1024,
                                                 nullptr, 0, nullptr, nullptr, nullptr, nullptr, nullptr);

    rmsnorm_split_kernel<<<4096, 256>>>(x2, ah, al);

    cudaStreamWaitEvent(0, ev_fold, 0);
    gemm_fp16x2<<<dim3(32, 32), 256, GEMM_SMEM>>>(ah, al, wfch, nullptr, nullptr, 4096, 1024,
                                                  gh, 1, nullptr, nullptr, nullptr, nullptr, nullptr);
    gemm_fp16x2<<<dim3(8, 32), 256, GEMM_SMEM>>>(gh, nullptr, wpjh, (float*)d_out, x2, 1024, 4096,
                                                 nullptr, 0, nullptr, nullptr, nullptr, nullptr, nullptr);
}

// round 12
// speedup vs baseline: 12.4358x; 1.5150x over previous
#include <cuda_runtime.h>
#include <cuda_bf16.h>
#include <cuda_fp16.h>
#include <math.h>
#include <stdint.h>

// ---------------- static device scratch ----------------
static __device__ float g_x2 [4096*1024];
static __device__ float g_wm0[8388608];
static __device__ float g_wm1[8388608];
static __device__ int   g_sel[4];
static __device__ float g_coef[4];
static __device__ __half g_ah[4194304];
static __device__ __half g_gh[16777216];
static __device__ __half g_wh[4194304];      // qkv weights fp16
static __device__ __half g_who[1048576];     // wo weights fp16
static __device__ __half g_wfch[4194304];
static __device__ __half g_wpjh[4194304];
static __device__ __half g_yh[4194304];
static __device__ __half g_qh[4194304];
static __device__ __half g_kh[1048576];
static __device__ __half g_vh[1048576];

// ---------------- PTX helpers ----------------
__device__ __forceinline__ uint32_t smem_u32(const void* p) {
    uint32_t a;
    asm("{ .reg .u64 t; cvta.to.shared.u64 t, %1; cvt.u32.u64 %0, t; }" : "=r"(a) : "l"(p));
    return a;
}
#define CP_ASYNC16(dst, src) \
    asm volatile("cp.async.cg.shared.global [%0], [%1], 16;" :: "r"(dst), "l"(src))
#define CP_COMMIT() asm volatile("cp.async.commit_group;" ::: "memory")
#define CP_WAIT1()  asm volatile("cp.async.wait_group 1;" ::: "memory")
#define CP_WAIT0()  asm volatile("cp.async.wait_group 0;" ::: "memory")

#define LDSM_X4(r, addr) \
    asm volatile("ldmatrix.sync.aligned.m8n8.x4.shared.b16 {%0,%1,%2,%3}, [%4];" \
        : "=r"((r)[0]), "=r"((r)[1]), "=r"((r)[2]), "=r"((r)[3]) : "r"(addr))
#define LDSM_X4_T(r, addr) \
    asm volatile("ldmatrix.sync.aligned.m8n8.x4.trans.shared.b16 {%0,%1,%2,%3}, [%4];" \
        : "=r"((r)[0]), "=r"((r)[1]), "=r"((r)[2]), "=r"((r)[3]) : "r"(addr))

#define MMA_FP16(d, a, b0, b1) \
    asm volatile("mma.sync.aligned.m16n8k16.row.col.f32.f16.f16.f32 " \
        "{%0,%1,%2,%3}, {%4,%5,%6,%7}, {%8,%9}, {%0,%1,%2,%3};" \
        : "+f"((d)[0]), "+f"((d)[1]), "+f"((d)[2]), "+f"((d)[3]) \
        : "r"((a)[0]), "r"((a)[1]), "r"((a)[2]), "r"((a)[3]), "r"(b0), "r"(b1))

__device__ __forceinline__ uint32_t pack2h(float v0, float v1) {
    __half h0 = __float2half_rn(v0), h1 = __float2half_rn(v1);
    return (uint32_t)*(uint16_t*)&h0 | ((uint32_t)*(uint16_t*)&h1 << 16);
}

// ---------------- fp32 -> fp16 convert ----------------
__global__ void splith_kernel(const float* __restrict__ src, __half* __restrict__ hi, int n)
{
    int i = (blockIdx.x * blockDim.x + threadIdx.x) * 8;
    if (i >= n) return;
    float4 a = *(const float4*)(src + i);
    float4 b = *(const float4*)(src + i + 4);
    uint4 H;
    H.x = pack2h(a.x, a.y); H.y = pack2h(a.z, a.w);
    H.z = pack2h(b.x, b.y); H.w = pack2h(b.z, b.w);
    *(uint4*)(hi + i) = H;
}

// ---------------- HMMA fp16 GEMM (single-precision operands, 1 MMA/tile) ----------------
#define TST 80
#define REG_BYTES (128 * TST)       // 10240
#define STG (2 * REG_BYTES)         // 20480
#define GEMM_SMEM (3 * STG)         // 61440

__device__ __forceinline__ void gemm_load_stage(
    uint32_t smbase, int kt, int NT, int K, int tid,
    const __half* s0, const __half* s2)
{
    if (kt < NT) {
        uint32_t sb = smbase + (kt % 3) * STG;
        int k0 = kt * 32;
#pragma unroll
        for (int t = 0; t < 4; t++) {
            int idx = tid + 256 * t;            // 0..1023
            int region = idx >> 9;
            int cc = idx & 511;
            int row = cc >> 2, ch = cc & 3;
            uint32_t dst = sb + region * REG_BYTES + row * TST + ch * 16;
            const __half* src = (region ? s2 : s0) + (size_t)row * K + k0 + ch * 8;
            CP_ASYNC16(dst, src);
        }
    }
    CP_COMMIT();
}

// mode 0: C fp32 (+res); mode 1: relu^2 -> fp16; mode 2: fused qkv prep
__global__ __launch_bounds__(256, 2) void gemm_fp16(
    const __half* __restrict__ Ah, const __half* __restrict__ Wh,
    float* __restrict__ C, const float* __restrict__ res, int N, int K,
    __half* __restrict__ OH, int mode,
    __half* __restrict__ qh, __half* __restrict__ kh, __half* __restrict__ vh,
    const float* __restrict__ qg, const float* __restrict__ kg)
{
    extern __shared__ char smem[];
    uint32_t smbase = smem_u32(smem);
    int tid = threadIdx.x, wid = tid >> 5, lane = tid & 31;
    int m0 = blockIdx.y * 128, n0 = blockIdx.x * 128;
    int wm = wid >> 1, wn = wid & 1;

    const __half* s0 = Ah + (size_t)m0 * K;
    const __half* s2 = Wh + (size_t)n0 * K;

    float acc[2][8][4];
#pragma unroll
    for (int i = 0; i < 2; i++)
#pragma unroll
        for (int j = 0; j < 8; j++)
#pragma unroll
            for (int r = 0; r < 4; r++) acc[i][j][r] = 0.f;

    int NT = K >> 5;
    gemm_load_stage(smbase, 0, NT, K, tid, s0, s2);
    gemm_load_stage(smbase, 1, NT, K, tid, s0, s2);

    int lt = lane >> 3, lr = lane & 7;
    for (int kt = 0; kt < NT; kt++) {
        CP_WAIT1();
        __syncthreads();
        gemm_load_stage(smbase, kt + 2, NT, K, tid, s0, s2);
        uint32_t sb = smbase + (kt % 3) * STG;
        uint32_t sbW = sb + REG_BYTES;
#pragma unroll
        for (int kk = 0; kk < 2; kk++) {
            uint32_t a_hi[2][4];
#pragma unroll
            for (int i = 0; i < 2; i++) {
                int row = wm * 32 + i * 16 + lr + (lt & 1) * 8;
                int kofs = kk * 16 + (lt >> 1) * 8;
                LDSM_X4(a_hi[i], sb + row * TST + kofs * 2);
            }
            uint32_t b_hi[4][4];
#pragma unroll
            for (int j = 0; j < 4; j++) {
                int row = wn * 64 + j * 16 + lr + (lt >> 1) * 8;
                int kofs = kk * 16 + (lt & 1) * 8;
                LDSM_X4(b_hi[j], sbW + row * TST + kofs * 2);
            }
#pragma unroll
            for (int i = 0; i < 2; i++)
#pragma unroll
                for (int j = 0; j < 8; j++) {
                    MMA_FP16(acc[i][j], a_hi[i],
                             b_hi[j >> 1][(j & 1) * 2], b_hi[j >> 1][(j & 1) * 2 + 1]);
                }
        }
    }
    CP_WAIT0();

    int rbase = m0 + wm * 32 + (lane >> 2);
    int cbase = n0 + wn * 64 + (lane & 3) * 2;

    if (mode == 2) {
        int hd = blockIdx.x * 2 + wn;    // 0-15 q, 16-19 k, 20-23 v
#pragma unroll
        for (int i = 0; i < 2; i++) {
#pragma unroll
            for (int half = 0; half < 2; half++) {
                int m = rbase + i * 16 + half * 8;
                int t = m & 2047, bb = m >> 11;
                float vals[8][2];
#pragma unroll
                for (int j = 0; j < 8; j++) {
                    vals[j][0] = acc[i][j][half * 2 + 0];
                    vals[j][1] = acc[i][j][half * 2 + 1];
                }
                if (hd < 20) {
                    float ss = 0.f;
#pragma unroll
                    for (int j = 0; j < 8; j++) ss += vals[j][0]*vals[j][0] + vals[j][1]*vals[j][1];
                    ss += __shfl_xor_sync(0xffffffffu, ss, 1);
                    ss += __shfl_xor_sync(0xffffffffu, ss, 2);
                    float gain = (hd < 16) ? qg[hd] : kg[hd - 16];
                    float r = rsqrtf(ss * (1.f/64.f) + 1e-6f) * gain;
#pragma unroll
                    for (int j = 0; j < 4; j++) {
                        float o1[2], o2[2];
#pragma unroll
                        for (int s = 0; s < 2; s++) {
                            int p = (lane & 3) * 2 + j * 8 + s;
                            float ang = (float)t * exp2f(-0.41524101186092029f * (float)p);
                            float sn, cs;
                            sincosf(ang, &sn, &cs);
                            float v1 = vals[j][s] * r, v2 = vals[j + 4][s] * r;
                            o1[s] = v1 * cs + v2 * sn;
                            o2[s] = v2 * cs - v1 * sn;
                        }
                        int c0 = (lane & 3) * 2 + j * 8;
                        if (hd < 16) {
                            size_t base = ((size_t)(bb * 16 + hd) * 2048 + t) * 64;
                            *(uint32_t*)(qh + base + c0)      = pack2h(o1[0], o1[1]);
                            *(uint32_t*)(qh + base + c0 + 32) = pack2h(o2[0], o2[1]);
                        } else {
                            size_t base = ((size_t)(bb * 4 + hd - 16) * 2048 + t) * 64;
                            *(uint32_t*)(kh + base + c0)      = pack2h(o1[0], o1[1]);
                            *(uint32_t*)(kh + base + c0 + 32) = pack2h(o2[0], o2[1]);
                        }
                    }
                } else {
                    size_t base = ((size_t)(bb * 4 + hd - 20) * 2048 + t) * 64;
#pragma unroll
                    for (int j = 0; j < 8; j++) {
                        int c0 = (lane & 3) * 2 + j * 8;
                        *(uint32_t*)(vh + base + c0) = pack2h(vals[j][0], vals[j][1]);
                    }
                }
            }
        }
        return;
    }

#pragma unroll
    for (int i = 0; i < 2; i++) {
#pragma unroll
        for (int half = 0; half < 2; half++) {
            size_t row = (size_t)(rbase + i * 16 + half * 8);
#pragma unroll
            for (int j = 0; j < 8; j++) {
                size_t idx = row * (size_t)N + cbase + j * 8;
                float v0 = acc[i][j][half * 2 + 0];
                float v1 = acc[i][j][half * 2 + 1];
                if (mode == 1) {
                    v0 = fmaxf(v0, 0.f); v0 *= v0;
                    v1 = fmaxf(v1, 0.f); v1 *= v1;
                    *(uint32_t*)(OH + idx) = pack2h(v0, v1);
                } else {
                    if (res) { v0 += res[idx]; v1 += res[idx + 1]; }
                    *(float2*)(C + idx) = make_float2(v0, v1);
                }
            }
        }
    }
}

// ---------------- RMSNorm with fp16 output ----------------
__global__ void rmsnorm_h_kernel(const float* __restrict__ x, __half* __restrict__ hi)
{
    int n = blockIdx.x;
    int tid = threadIdx.x;
    const float4* xr = (const float4*)(x + (size_t)n * 1024);
    float4 v = xr[tid];
    float s = v.x*v.x + v.y*v.y + v.z*v.z + v.w*v.w;
#pragma unroll
    for (int off = 16; off > 0; off >>= 1) s += __shfl_xor_sync(0xffffffffu, s, off);
    __shared__ float red[8];
    if ((tid & 31) == 0) red[tid >> 5] = s;
    __syncthreads();
    float tot = 0.f;
#pragma unroll
    for (int i = 0; i < 8; i++) tot += red[i];
    float r = rsqrtf(tot * (1.f/1024.f) + 1e-6f);
    size_t base = (size_t)n * 1024 + tid * 4;
    *(uint2*)(hi + base) = make_uint2(pack2h(v.x*r, v.y*r), pack2h(v.z*r, v.w*r));
}

// ---------------- tensor-core flash attention (single fp16) ----------------
#define AT_ROWB 144
#define AT_TILE (64 * AT_ROWB)
#define AT_STAGE (2 * AT_TILE)
#define ATTN_SMEM (AT_TILE + 2 * AT_STAGE)

__device__ __forceinline__ void attn_load_kv(
    uint32_t dstbase, int tid,
    const __half* kh, const __half* vh, size_t kvoff, int kt)
{
#pragma unroll
    for (int t = 0; t < 8; t++) {
        int idx = tid + 128 * t;
        int buf = idx >> 9, cc = idx & 511, row = cc >> 3, ch = cc & 7;
        const __half* src = (buf ? vh : kh) + kvoff + (size_t)(kt * 64 + row) * 64 + ch * 8;
        CP_ASYNC16(dstbase + buf * AT_TILE + row * AT_ROWB + ch * 16, src);
    }
}

__global__ __launch_bounds__(128) void attn_mma_kernel(
    const __half* __restrict__ qh,
    const __half* __restrict__ kh, const __half* __restrict__ vh,
    __half* __restrict__ yh)
{
    extern __shared__ char smem[];
    uint32_t sb = smem_u32(smem);
    int qt = gridDim.x - 1 - blockIdx.x;
    int h = blockIdx.y, b = blockIdx.z;
    int tid = threadIdx.x, w = tid >> 5, lane = tid & 31;
    int lr = lane & 7, lt = lane >> 3;
    size_t qoff = ((size_t)(b * 16 + h) * 2048 + qt * 64) * 64;
    size_t kvoff = (size_t)(b * 4 + (h >> 2)) * 2048 * 64;

#pragma unroll
    for (int t = 0; t < 4; t++) {
        int idx = tid + 128 * t;
        int row = idx >> 3, ch = idx & 7;
        CP_ASYNC16(sb + row * AT_ROWB + ch * 16, qh + qoff + row * 64 + ch * 8);
    }
    CP_COMMIT();
    attn_load_kv(sb + AT_TILE, tid, kh, vh, kvoff, 0);
    CP_COMMIT();
    CP_WAIT0();
    __syncthreads();

    uint32_t qfh[4][4];
#pragma unroll
    for (int kk = 0; kk < 4; kk++) {
        uint32_t addr = sb + (w * 16 + lr + (lt & 1) * 8) * AT_ROWB + (kk * 16 + (lt >> 1) * 8) * 2;
        LDSM_X4(qfh[kk], addr);
    }

    float O[8][4];
#pragma unroll
    for (int j = 0; j < 8; j++)
#pragma unroll
        for (int r = 0; r < 4; r++) O[j][r] = 0.f;
    float m0 = -1e30f, m1 = -1e30f, l0 = 0.f, l1 = 0.f;

    for (int kt = 0; kt <= qt; kt++) {
        if (kt < qt) {
            attn_load_kv(sb + AT_TILE + ((kt + 1) & 1) * AT_STAGE, tid, kh, vh, kvoff, kt + 1);
            CP_COMMIT();
        }
        uint32_t kb = sb + AT_TILE + (kt & 1) * AT_STAGE;
        float c[8][4];
#pragma unroll
        for (int j = 0; j < 8; j++)
#pragma unroll
            for (int r = 0; r < 4; r++) c[j][r] = 0.f;
#pragma unroll
        for (int kk = 0; kk < 4; kk++) {
            uint32_t kbh[4][4];
#pragma unroll
            for (int j2 = 0; j2 < 4; j2++) {
                uint32_t addr = kb + (j2 * 16 + lr + (lt >> 1) * 8) * AT_ROWB + (kk * 16 + (lt & 1) * 8) * 2;
                LDSM_X4(kbh[j2], addr);
            }
#pragma unroll
            for (int j = 0; j < 8; j++) {
                MMA_FP16(c[j], qfh[kk], kbh[j >> 1][(j & 1) * 2], kbh[j >> 1][(j & 1) * 2 + 1]);
            }
        }
        if (kt == qt) {
            int r0 = w * 16 + (lane >> 2), r1 = r0 + 8;
#pragma unroll
            for (int j = 0; j < 8; j++) {
                int col = j * 8 + (lane & 3) * 2;
                if (col     > r0) c[j][0] = -1e30f;
                if (col + 1 > r0) c[j][1] = -1e30f;
                if (col     > r1) c[j][2] = -1e30f;
                if (col + 1 > r1) c[j][3] = -1e30f;
            }
        }
        float mx0 = -1e30f, mx1 = -1e30f;
#pragma unroll
        for (int j = 0; j < 8; j++) {
            mx0 = fmaxf(mx0, fmaxf(c[j][0], c[j][1]));
            mx1 = fmaxf(mx1, fmaxf(c[j][2], c[j][3]));
        }
        mx0 *= 0.125f; mx1 *= 0.125f;
        mx0 = fmaxf(mx0, __shfl_xor_sync(0xffffffffu, mx0, 1));
        mx0 = fmaxf(mx0, __shfl_xor_sync(0xffffffffu, mx0, 2));
        mx1 = fmaxf(mx1, __shfl_xor_sync(0xffffffffu, mx1, 1));
        mx1 = fmaxf(mx1, __shfl_xor_sync(0xffffffffu, mx1, 2));
        float m0n = fmaxf(m0, mx0), m1n = fmaxf(m1, mx1);
        float cr0 = __expf(m0 - m0n), cr1 = __expf(m1 - m1n);
        float s0 = 0.f, s1 = 0.f;
#pragma unroll
        for (int j = 0; j < 8; j++) {
            c[j][0] = __expf(fmaf(c[j][0], 0.125f, -m0n)); s0 += c[j][0];
            c[j][1] = __expf(fmaf(c[j][1], 0.125f, -m0n)); s0 += c[j][1];
            c[j][2] = __expf(fmaf(c[j][2], 0.125f, -m1n)); s1 += c[j][2];
            c[j][3] = __expf(fmaf(c[j][3], 0.125f, -m1n)); s1 += c[j][3];
        }
        s0 += __shfl_xor_sync(0xffffffffu, s0, 1);
        s0 += __shfl_xor_sync(0xffffffffu, s0, 2);
        s1 += __shfl_xor_sync(0xffffffffu, s1, 1);
        s1 += __shfl_xor_sync(0xffffffffu, s1, 2);
        l0 = l0 * cr0 + s0; l1 = l1 * cr1 + s1;
        m0 = m0n; m1 = m1n;
#pragma unroll
        for (int j = 0; j < 8; j++) {
            O[j][0] *= cr0; O[j][1] *= cr0;
            O[j][2] *= cr1; O[j][3] *= cr1;
        }
#pragma unroll
        for (int kt2 = 0; kt2 < 4; kt2++) {
            uint32_t pah[4];
            pah[0] = pack2h(c[2*kt2][0],   c[2*kt2][1]);
            pah[1] = pack2h(c[2*kt2][2],   c[2*kt2][3]);
            pah[2] = pack2h(c[2*kt2+1][0], c[2*kt2+1][1]);
            pah[3] = pack2h(c[2*kt2+1][2], c[2*kt2+1][3]);
#pragma unroll
            for (int jd = 0; jd < 4; jd++) {
                uint32_t vbh[4];
                uint32_t addr = kb + AT_TILE + (kt2 * 16 + (lt & 1) * 8 + lr) * AT_ROWB + (jd * 16 + (lt >> 1) * 8) * 2;
                LDSM_X4_T(vbh, addr);
#pragma unroll
                for (int js = 0; js < 2; js++) {
                    MMA_FP16(O[jd * 2 + js], pah, vbh[js*2], vbh[js*2+1]);
                }
            }
        }
        if (kt < qt) CP_WAIT0();
        __syncthreads();
    }
    float i0 = 1.f / l0, i1 = 1.f / l1;
    size_t rA = (size_t)(b * 2048 + qt * 64 + w * 16 + (lane >> 2));
    size_t rB = rA + 8;
    int colb = h * 64 + (lane & 3) * 2;
#pragma unroll
    for (int j = 0; j < 8; j++) {
        int col = colb + j * 8;
        *(uint32_t*)(yh + rA * 1024 + col) = pack2h(O[j][0] * i0, O[j][1] * i0);
        *(uint32_t*)(yh + rB * 1024 + col) = pack2h(O[j][2] * i1, O[j][3] * i1);
    }
}

// ---------------- tile helpers for folding kernels ----------------
#define TP 68
__device__ __forceinline__ void load_tile_s(float* dst, const float* src, size_t stride, int tid) {
#pragma unroll
    for (int r = 0; r < 4; r++) {
        int f = tid + 256 * r;
        int row = f >> 4, c4 = (f & 15) << 2;
        *(float4*)&dst[row*TP + c4] = *(const float4*)(src + (size_t)row * stride + c4);
    }
}
__device__ __forceinline__ void load_tileT_s(float* dst, const float* src, size_t stride, int tid) {
#pragma unroll
    for (int r = 0; r < 4; r++) {
        int f = tid + 256 * r;
        int row = f >> 4, c4 = (f & 15) << 2;
        float4 v = *(const float4*)(src + (size_t)row * stride + c4);
        dst[(c4+0)*TP + row] = v.x; dst[(c4+1)*TP + row] = v.y;
        dst[(c4+2)*TP + row] = v.z; dst[(c4+3)*TP + row] = v.w;
    }
}
__device__ __forceinline__ void mm64(const float* XT, const float* W, float acc[4][4], int tx, int ty) {
#pragma unroll
    for (int c = 0; c < 64; c++) {
        float a[4], bb[4];
        *(float4*)a  = *(const float4*)&XT[c*TP + ty*4];
        *(float4*)bb = *(const float4*)&W [c*TP + tx*4];
#pragma unroll
        for (int i = 0; i < 4; i++)
#pragma unroll
            for (int j = 0; j < 4; j++) acc[i][j] = fmaf(a[i], bb[j], acc[i][j]);
    }
}

// ---------------- P1: fold s2 into mix ----------------
__global__ __launch_bounds__(256) void fold1_kernel(
    const float* __restrict__ Mix, const float* __restrict__ S2,
    float* __restrict__ WM2T, int in_f, int out_f,
    const int* __restrict__ selp)
{
    extern __shared__ float sm[];
    float* MT = sm;
    float* S  = sm + 4352;
    int jb = blockIdx.x, G = blockIdx.y, r = blockIdx.z;
    int sel = selp[r];
    int tid = threadIdx.x;
    load_tile_s(MT, Mix + (size_t)sel * out_f * in_f + (size_t)(G * 64) * in_f + jb * 64, in_f, tid);
    load_tile_s(S,  S2  + (size_t)sel * out_f * 64 + (size_t)G * 4096, 64, tid);
    __syncthreads();
    int tx = tid & 15, ty = tid >> 4;
    float acc[4][4] = {};
    mm64(MT, S, acc, tx, ty);
    float* outp = WM2T + (size_t)r * in_f * out_f;
#pragma unroll
    for (int i = 0; i < 4; i++) {
        size_t row = (size_t)(jb * 64 + ty * 4 + i);
        *(float4*)(outp + row * out_f + G * 64 + tx * 4) =
            make_float4(acc[i][0], acc[i][1], acc[i][2], acc[i][3]);
    }
}

// ---------------- P2: fold s1 + roll-perm, combine experts, fp16 out ----------------
__global__ __launch_bounds__(256) void fold2_kernel(
    const float* __restrict__ WM2T, const float* __restrict__ S1,
    __half* __restrict__ WH,
    int in_f, int out_f, int n_in,
    const int* __restrict__ selp, const float* __restrict__ coefp)
{
    extern __shared__ float sm[];
    float* G0 = sm;
    float* G1 = sm + 4352;
    float* T0 = sm + 8704;
    float* T1 = sm + 13056;
    int g = blockIdx.x, Ob = blockIdx.y, tid = threadIdx.x;
    int s0i = selp[0], s1i = selp[1];
    int gs0 = (g + s0i) % n_in, gs1 = (g + s1i) % n_in;
    const float* W0 = WM2T;
    const float* W1 = WM2T + (size_t)in_f * out_f;
#pragma unroll
    for (int r = 0; r < 4; r++) {
        int f = tid + 256 * r;
        int d = f >> 4, o4 = (f & 15) << 2;
        *(float4*)&G0[d*TP + o4] = *(const float4*)(W0 + (size_t)(d * n_in + gs0) * out_f + Ob * 64 + o4);
        *(float4*)&G1[d*TP + o4] = *(const float4*)(W1 + (size_t)(d * n_in + gs1) * out_f + Ob * 64 + o4);
    }
    load_tileT_s(T0, S1 + (size_t)s0i * in_f * 64 + (size_t)g * 4096, 64, tid);
    load_tileT_s(T1, S1 + (size_t)s1i * in_f * 64 + (size_t)g * 4096, 64, tid);
    __syncthreads();
    int tx = tid & 15, ty = tid >> 4;
    float a0[4][4] = {}, a1[4][4] = {};
    mm64(G0, T0, a0, tx, ty);
    mm64(G1, T1, a1, tx, ty);
    float c0 = coefp[0], c1 = coefp[1];
#pragma unroll
    for (int i = 0; i < 4; i++) {
        size_t base = (size_t)(Ob * 64 + ty * 4 + i) * in_f + g * 64 + tx * 4;
        float v0 = c0 * a0[i][0] + c1 * a1[i][0];
        float v1 = c0 * a0[i][1] + c1 * a1[i][1];
        float v2 = c0 * a0[i][2] + c1 * a1[i][2];
        float v3 = c0 * a0[i][3] + c1 * a1[i][3];
        *(uint32_t*)(WH + base)     = pack2h(v0, v1);
        *(uint32_t*)(WH + base + 2) = pack2h(v2, v3);
    }
}

// ---------------- top-2 router ----------------
__global__ void router_kernel(const float* __restrict__ fcl, const float* __restrict__ pjl,
                              int* __restrict__ sel, float* __restrict__ coef)
{
    if (threadIdx.x == 0 && blockIdx.x == 0) {
#pragma unroll
        for (int s = 0; s < 2; s++) {
            const float* L = s ? pjl : fcl;
            int i1 = 0; float v1 = L[0];
            for (int i = 1; i < 8; i++) if (L[i] > v1) { v1 = L[i]; i1 = i; }
            int i2 = -1; float v2 = -1e30f;
            for (int i = 0; i < 8; i++) if (i != i1 && L[i] > v2) { v2 = L[i]; i2 = i; }
            float e = expf(v2 - v1);
            float z = 1.f + e;
            sel[s*2+0] = i1; sel[s*2+1] = i2;
            coef[s*2+0] = 1.f / z; coef[s*2+1] = e / z;
        }
    }
}

// ---------------- host orchestration ----------------
#define FOLD1_SMEM (8704 * 4)
#define FOLD2_SMEM (17408 * 4)

extern "C" void kernel_launch(void* const* d_in, const int* in_sizes, int n_in_,
                              void* d_out, int out_size)
{
    (void)in_sizes; (void)n_in_; (void)out_size;
    const float* x      = (const float*)d_in[0];
    const float* wq     = (const float*)d_in[1];
    const float* wk     = (const float*)d_in[2];
    const float* wv     = (const float*)d_in[3];
    const float* wo     = (const float*)d_in[4];
    const float* qg     = (const float*)d_in[5];
    const float* kg     = (const float*)d_in[6];
    const float* fc_s1  = (const float*)d_in[7];
    const float* fc_s2  = (const float*)d_in[8];
    const float* fc_mix = (const float*)d_in[9];
    const float* fc_lg  = (const float*)d_in[10];
    const float* pj_s1  = (const float*)d_in[11];
    const float* pj_s2  = (const float*)d_in[12];
    const float* pj_mix = (const float*)d_in[13];
    const float* pj_lg  = (const float*)d_in[14];

    float *x2, *wm0, *wm1, *coef;
    int* sel;
    __half *ah, *gh, *wh, *who, *wfch, *wpjh, *yh, *qh, *kh, *vh;
    cudaGetSymbolAddress((void**)&x2,  g_x2);
    cudaGetSymbolAddress((void**)&wm0, g_wm0);
    cudaGetSymbolAddress((void**)&wm1, g_wm1);
    cudaGetSymbolAddress((void**)&sel,  g_sel);
    cudaGetSymbolAddress((void**)&coef, g_coef);
    cudaGetSymbolAddress((void**)&ah, g_ah);
    cudaGetSymbolAddress((void**)&gh, g_gh);
    cudaGetSymbolAddress((void**)&wh, g_wh);
    cudaGetSymbolAddress((void**)&who, g_who);
    cudaGetSymbolAddress((void**)&wfch, g_wfch);
    cudaGetSymbolAddress((void**)&wpjh, g_wpjh);
    cudaGetSymbolAddress((void**)&yh, g_yh);
    cudaGetSymbolAddress((void**)&qh, g_qh);
    cudaGetSymbolAddress((void**)&kh, g_kh);
    cudaGetSymbolAddress((void**)&vh, g_vh);

    cudaFuncSetAttribute(gemm_fp16, cudaFuncAttributeMaxDynamicSharedMemorySize, GEMM_SMEM);
    cudaFuncSetAttribute(attn_mma_kernel, cudaFuncAttributeMaxDynamicSharedMemorySize, ATTN_SMEM);
    cudaFuncSetAttribute(fold1_kernel, cudaFuncAttributeMaxDynamicSharedMemorySize, FOLD1_SMEM);
    cudaFuncSetAttribute(fold2_kernel, cudaFuncAttributeMaxDynamicSharedMemorySize, FOLD2_SMEM);

    static cudaStream_t s2 = nullptr;
    static cudaEvent_t ev_fork = nullptr, ev_wqkv = nullptr, ev_wo = nullptr, ev_fold = nullptr;
    if (!s2) {
        cudaStreamCreateWithFlags(&s2, cudaStreamNonBlocking);
        cudaEventCreateWithFlags(&ev_fork, cudaEventDisableTiming);
        cudaEventCreateWithFlags(&ev_wqkv, cudaEventDisableTiming);
        cudaEventCreateWithFlags(&ev_wo,   cudaEventDisableTiming);
        cudaEventCreateWithFlags(&ev_fold, cudaEventDisableTiming);
    }

    // ---- fork: side stream does weight converts + routing + folding ----
    cudaEventRecord(ev_fork, 0);
    cudaStreamWaitEvent(s2, ev_fork, 0);

    splith_kernel<<<512, 256, 0, s2>>>(wq, wh, 1048576);
    splith_kernel<<<128, 256, 0, s2>>>(wk, wh + 1048576, 262144);
    splith_kernel<<<128, 256, 0, s2>>>(wv, wh + 1310720, 262144);
    cudaEventRecord(ev_wqkv, s2);
    splith_kernel<<<512, 256, 0, s2>>>(wo, who, 1048576);
    cudaEventRecord(ev_wo, s2);
    router_kernel<<<1, 32, 0, s2>>>(fc_lg, pj_lg, sel, coef);
    fold1_kernel<<<dim3(16, 64, 2), 256, FOLD1_SMEM, s2>>>(fc_mix, fc_s2, wm0, 1024, 4096, sel);
    fold2_kernel<<<dim3(16, 64), 256, FOLD2_SMEM, s2>>>(wm0, fc_s1, wfch, 1024, 4096, 16, sel, coef);
    fold1_kernel<<<dim3(64, 16, 2), 256, FOLD1_SMEM, s2>>>(pj_mix, pj_s2, wm1, 4096, 1024, sel + 2);
    fold2_kernel<<<dim3(64, 16), 256, FOLD2_SMEM, s2>>>(wm1, pj_s1, wpjh, 4096, 1024, 64, sel + 2, coef + 2);
    cudaEventRecord(ev_fold, s2);

    // ---- main stream: attention path ----
    rmsnorm_h_kernel<<<4096, 256>>>(x, ah);
    cudaStreamWaitEvent(0, ev_wqkv, 0);
    gemm_fp16<<<dim3(12, 32), 256, GEMM_SMEM>>>(ah, wh, nullptr, nullptr, 1536, 1024,
                                                nullptr, 2, qh, kh, vh, qg, kg);
    attn_mma_kernel<<<dim3(32, 16, 2), 128, ATTN_SMEM>>>(qh, kh, vh, yh);

    cudaStreamWaitEvent(0, ev_wo, 0);
    gemm_fp16<<<dim3(8, 32), 256, GEMM_SMEM>>>(yh, who, x2, x, 1024, 1024,
                                               nullptr, 0, nullptr, nullptr, nullptr, nullptr, nullptr);

    rmsnorm_h_kernel<<<4096, 256>>>(x2, ah);

    cudaStreamWaitEvent(0, ev_fold, 0);
    gemm_fp16<<<dim3(32, 32), 256, GEMM_SMEM>>>(ah, wfch, nullptr, nullptr, 4096, 1024,
                                                gh, 1, nullptr, nullptr, nullptr, nullptr, nullptr);
    gemm_fp16<<<dim3(8, 32), 256, GEMM_SMEM>>>(gh, wpjh, (float*)d_out, x2, 1024, 4096,
                                               nullptr, 0, nullptr, nullptr, nullptr, nullptr, nullptr);
}